// round 2
// baseline (speedup 1.0000x reference)
#include <cuda_runtime.h>
#include <math.h>

#define NB 8
#define NC 256
#define NHW 128
#define NTOK 16384
#define NHEADS 8
#define DK 32

// ------------------------- device scratch -------------------------
__device__ float g_T[NHW * 128];              // sine table (same for y and x; h==w)
__device__ float g_WkT[NC * NC];              // Wk transposed [ci][co]
__device__ float g_WvT[NC * NC];
__device__ float g_RK[NHW * NC];              // pos-y contribution to K proj
__device__ float g_PK[NHW * NC];              // pos-x contribution to K proj
__device__ float g_spart[(size_t)NB * NHW * NHEADS * DK * DK];  // per-row score partials (32MB)
__device__ float g_S[NB * NHEADS * DK * DK];  // reduced scores / n
__device__ float g_M[NB * NC * NC];           // fused Wq^T @ blockdiag(S) per batch
__device__ float g_biasq[NB * NC];
__device__ float g_RQ[NB * NHW * NC];
__device__ float g_PQ[NB * NHW * NC];

// ------------------------- prep0: transposes + sine table -------------------------
__global__ void prep0_kernel(const float* __restrict__ Wk, const float* __restrict__ Wv) {
    int idx = blockIdx.x * 256 + threadIdx.x;   // 65536 threads
    int co = idx >> 8, ci = idx & 255;
    g_WkT[ci * NC + co] = Wk[idx];
    g_WvT[ci * NC + co] = Wv[idx];
    if (idx < NHW * 128) {
        int p = idx >> 7;          // position 0..127
        int c = idx & 127;         // channel 0..127
        int j = c >> 1;
        float dimt = powf(10000.0f, (float)j * (1.0f / 64.0f));
        float base = (float)(p + 1) * (6.283185307179586f / (128.0f + 1e-6f));
        float t = base / dimt;
        g_T[idx] = (c & 1) ? cosf(t) : sinf(t);
    }
}

// ------------------------- prep1: RK/PK tables from WkT -------------------------
__global__ void prep1_kernel() {
    int table = blockIdx.x >> 3, chunk = blockIdx.x & 7;  // 16 blocks
    int n = chunk * 32 + (threadIdx.x & 31);
    int yg = threadIdx.x >> 5;                            // 8 groups of 16 positions
    float acc[16];
#pragma unroll
    for (int i = 0; i < 16; i++) acc[i] = 0.f;
    const float* W = g_WkT + (table ? 128 * NC : 0);
#pragma unroll 4
    for (int c = 0; c < 128; c++) {
        float w = W[c * NC + n];
#pragma unroll
        for (int yy = 0; yy < 16; yy++)
            acc[yy] += g_T[(yg * 16 + yy) * 128 + c] * w;
    }
    float* dst = table ? g_PK : g_RK;
#pragma unroll
    for (int yy = 0; yy < 16; yy++) dst[(yg * 16 + yy) * NC + n] = acc[yy];
}

// ------------------------- K1: fused K/V proj + per-head LN + scores -------------------------
// grid (128 image rows, 8 batch), 256 threads, dyn smem 103936B
__global__ void __launch_bounds__(256, 2) k1_kvscores(
    const float* __restrict__ x,
    const float* __restrict__ bk, const float* __restrict__ bv,
    const float* __restrict__ gK, const float* __restrict__ bKp,
    const float* __restrict__ gV, const float* __restrict__ bVp)
{
    extern __shared__ float sm[];
    float* As  = sm;                 // [32][132]
    float* Wks = As + 32 * 132;      // [32][68]
    float* Wvs = Wks + 32 * 68;      // [32][68]
    float* Ksm = Wvs + 32 * 68;      // [128][68]
    float* Vsm = Ksm + 128 * 68;     // [128][68]

    const int tid = threadIdx.x;
    const int rb = blockIdx.x;       // image row (y)
    const int b  = blockIdx.y;
    const int ty = tid >> 4;         // token group (8 tokens)
    const int tx = tid & 15;         // co group (4 co)
    const float* xb = x + ((size_t)b * NC) * NTOK + rb * 128;

#pragma unroll 1
    for (int nc = 0; nc < 4; nc++) {             // 64-co chunk = heads 2nc, 2nc+1
        float accK[8][4], accV[8][4];
#pragma unroll
        for (int i = 0; i < 8; i++)
#pragma unroll
            for (int j = 0; j < 4; j++) { accK[i][j] = 0.f; accV[i][j] = 0.f; }

#pragma unroll 1
        for (int cc = 0; cc < 8; cc++) {
            __syncthreads();
#pragma unroll
            for (int p = 0; p < 16; p++) {
                int idx = tid + p * 256; int ci = idx >> 7, tok = idx & 127;
                As[ci * 132 + tok] = xb[(size_t)(cc * 32 + ci) * NTOK + tok];
            }
#pragma unroll
            for (int p = 0; p < 8; p++) {
                int idx = tid + p * 256; int ci = idx >> 6, j = idx & 63;
                Wks[ci * 68 + j] = g_WkT[(cc * 32 + ci) * NC + nc * 64 + j];
                Wvs[ci * 68 + j] = g_WvT[(cc * 32 + ci) * NC + nc * 64 + j];
            }
            __syncthreads();
#pragma unroll 8
            for (int k = 0; k < 32; k++) {
                float4 a0 = *(const float4*)&As[k * 132 + ty * 8];
                float4 a1 = *(const float4*)&As[k * 132 + ty * 8 + 4];
                float4 wk = *(const float4*)&Wks[k * 68 + tx * 4];
                float4 wv = *(const float4*)&Wvs[k * 68 + tx * 4];
                float a[8] = {a0.x, a0.y, a0.z, a0.w, a1.x, a1.y, a1.z, a1.w};
                float kr[4] = {wk.x, wk.y, wk.z, wk.w};
                float vr[4] = {wv.x, wv.y, wv.z, wv.w};
#pragma unroll
                for (int i = 0; i < 8; i++)
#pragma unroll
                    for (int j = 0; j < 4; j++) {
                        accK[i][j] += a[i] * kr[j];
                        accV[i][j] += a[i] * vr[j];
                    }
            }
        }
        __syncthreads();

        // epilogue: add pos tables + bias, stage to smem
        {
            int coB = nc * 64 + tx * 4;
            float4 rk  = *(const float4*)&g_RK[rb * NC + coB];
            float4 bk4 = *(const float4*)&bk[coB];
            float4 bv4 = *(const float4*)&bv[coB];
#pragma unroll
            for (int i = 0; i < 8; i++) {
                int tok = ty * 8 + i;
                float4 pk = *(const float4*)&g_PK[tok * NC + coB];
                float4 ko, vo;
                ko.x = accK[i][0] + rk.x + pk.x + bk4.x;
                ko.y = accK[i][1] + rk.y + pk.y + bk4.y;
                ko.z = accK[i][2] + rk.z + pk.z + bk4.z;
                ko.w = accK[i][3] + rk.w + pk.w + bk4.w;
                vo.x = accV[i][0] + bv4.x;
                vo.y = accV[i][1] + bv4.y;
                vo.z = accV[i][2] + bv4.z;
                vo.w = accV[i][3] + bv4.w;
                *(float4*)&Ksm[tok * 68 + tx * 4] = ko;
                *(float4*)&Vsm[tok * 68 + tx * 4] = vo;
            }
        }
        __syncthreads();

        // per-head LayerNorm in place (token, head-half per thread)
        {
            int tok = tid & 127, hl = tid >> 7;
            int head = nc * 2 + hl;
            float* kp = &Ksm[tok * 68 + hl * 32];
            float* vp = &Vsm[tok * 68 + hl * 32];
            const float4* gk4 = (const float4*)(gK + head * 32);
            const float4* bk4 = (const float4*)(bKp + head * 32);
            const float4* gv4 = (const float4*)(gV + head * 32);
            const float4* bv4 = (const float4*)(bVp + head * 32);

            float4 r[8]; float s = 0.f, s2 = 0.f;
#pragma unroll
            for (int jj = 0; jj < 8; jj++) {
                r[jj] = ((const float4*)kp)[jj];
                s  += r[jj].x + r[jj].y + r[jj].z + r[jj].w;
                s2 += r[jj].x * r[jj].x + r[jj].y * r[jj].y + r[jj].z * r[jj].z + r[jj].w * r[jj].w;
            }
            float mu = s * (1.f / 32.f);
            float rstd = rsqrtf(s2 * (1.f / 32.f) - mu * mu + 1e-5f);
#pragma unroll
            for (int jj = 0; jj < 8; jj++) {
                float4 g = gk4[jj], be = bk4[jj], o;
                o.x = (r[jj].x - mu) * rstd * g.x + be.x;
                o.y = (r[jj].y - mu) * rstd * g.y + be.y;
                o.z = (r[jj].z - mu) * rstd * g.z + be.z;
                o.w = (r[jj].w - mu) * rstd * g.w + be.w;
                ((float4*)kp)[jj] = o;
            }
            s = 0.f; s2 = 0.f;
#pragma unroll
            for (int jj = 0; jj < 8; jj++) {
                r[jj] = ((const float4*)vp)[jj];
                s  += r[jj].x + r[jj].y + r[jj].z + r[jj].w;
                s2 += r[jj].x * r[jj].x + r[jj].y * r[jj].y + r[jj].z * r[jj].z + r[jj].w * r[jj].w;
            }
            mu = s * (1.f / 32.f);
            rstd = rsqrtf(s2 * (1.f / 32.f) - mu * mu + 1e-5f);
#pragma unroll
            for (int jj = 0; jj < 8; jj++) {
                float4 g = gv4[jj], be = bv4[jj], o;
                o.x = (r[jj].x - mu) * rstd * g.x + be.x;
                o.y = (r[jj].y - mu) * rstd * g.y + be.y;
                o.z = (r[jj].z - mu) * rstd * g.z + be.z;
                o.w = (r[jj].w - mu) * rstd * g.w + be.w;
                ((float4*)vp)[jj] = o;
            }
        }
        __syncthreads();

        // score outer-product accumulation: S[head][d][e] over 128 tokens
        {
            int hl = tid >> 7, d = (tid >> 2) & 31, eg = tid & 3;
            float sacc[8];
#pragma unroll
            for (int j = 0; j < 8; j++) sacc[j] = 0.f;
#pragma unroll 4
            for (int tok = 0; tok < 128; tok++) {
                float kd = Ksm[tok * 68 + hl * 32 + d];
                float4 v0 = *(const float4*)&Vsm[tok * 68 + hl * 32 + eg * 8];
                float4 v1 = *(const float4*)&Vsm[tok * 68 + hl * 32 + eg * 8 + 4];
                sacc[0] += kd * v0.x; sacc[1] += kd * v0.y;
                sacc[2] += kd * v0.z; sacc[3] += kd * v0.w;
                sacc[4] += kd * v1.x; sacc[5] += kd * v1.y;
                sacc[6] += kd * v1.z; sacc[7] += kd * v1.w;
            }
            float* dst = g_spart + ((size_t)(b * 128 + rb)) * 8192
                         + (size_t)(nc * 2 + hl) * 1024 + d * 32 + eg * 8;
#pragma unroll
            for (int j = 0; j < 8; j++) dst[j] = sacc[j];
        }
    }
}

// ------------------------- K2a: reduce partials -> S / n -------------------------
__global__ void k2_reduce() {
    int b = blockIdx.x >> 3, seg = blockIdx.x & 7;   // 64 blocks
    int base = seg * 1024 + threadIdx.x;
    float s[4] = {0.f, 0.f, 0.f, 0.f};
    for (int rb = 0; rb < 128; rb++) {
        const float* p = g_spart + ((size_t)(b * 128 + rb)) * 8192 + base;
#pragma unroll
        for (int q = 0; q < 4; q++) s[q] += p[q * 256];
    }
#pragma unroll
    for (int q = 0; q < 4; q++)
        g_S[b * 8192 + base + q * 256] = s[q] * (1.0f / 16384.0f);
}

// ------------------------- K2b: M_b = Wq^T @ blockdiag(S_b), biasq -------------------------
__global__ void k2b_buildM(const float* __restrict__ Wq, const float* __restrict__ bq) {
    __shared__ float Wqs[256 * 33];
    int chunk = blockIdx.x, b = blockIdx.y;
    int co = threadIdx.x, h = co >> 5, e = co & 31;
    for (int idx = threadIdx.x; idx < 8192; idx += 256) {
        int row = idx >> 5, cil = idx & 31;
        Wqs[row * 33 + cil] = Wq[row * NC + chunk * 32 + cil];
    }
    float Scol[32];
#pragma unroll
    for (int d = 0; d < 32; d++) Scol[d] = g_S[b * 8192 + h * 1024 + d * 32 + e];
    __syncthreads();
    for (int cil = 0; cil < 32; cil++) {
        float m = 0.f;
#pragma unroll
        for (int d = 0; d < 32; d++) m += Wqs[(h * 32 + d) * 33 + cil] * Scol[d];
        g_M[(size_t)b * 65536 + (chunk * 32 + cil) * NC + co] = m;
    }
    if (chunk == 0) {
        float bb = 0.f;
#pragma unroll
        for (int d = 0; d < 32; d++) bb += bq[h * 32 + d] * Scol[d];
        g_biasq[b * NC + co] = bb;
    }
}

// ------------------------- K2c: RQ/PQ tables from M -------------------------
__global__ void k2c_rqpq() {
    int p = blockIdx.x, b = blockIdx.y;
    int co = threadIdx.x;
    float accR = 0.f, accP = 0.f;
#pragma unroll 4
    for (int c = 0; c < 128; c++) {
        float tv = g_T[p * 128 + c];
        accR += tv * g_M[(size_t)b * 65536 + c * NC + co];
        accP += tv * g_M[(size_t)b * 65536 + (128 + c) * NC + co];
    }
    g_RQ[(b * 128 + p) * NC + co] = accR;
    g_PQ[(b * 128 + p) * NC + co] = accP;
}

// ------------------------- K3: out GEMM + x2 + final LN + transposed store -------------------------
// grid (256 tiles of 64 tokens, 8 batch), 256 threads, dyn smem 67072B
__global__ void __launch_bounds__(256, 2) k3_out(
    const float* __restrict__ x,
    const float* __restrict__ g_ln, const float* __restrict__ b_ln,
    float* __restrict__ out)
{
    extern __shared__ float sm[];
    float* As = sm;                  // [32][68] (GEMM phase)
    float* Ms = sm + 32 * 68;        // [32][260] (GEMM phase)
    float* stg = sm;                 // [64][260] (epilogue; overlaps As/Ms)
    float* musm = sm + 64 * 260;     // [64]
    float* rssm = musm + 64;         // [64]

    const int tid = threadIdx.x;
    const int tile = blockIdx.x;     // 0..255
    const int b = blockIdx.y;
    const int n0 = tile * 64;
    const int y = n0 >> 7;
    const int x0 = (n0 & 127);
    const int cG = tid >> 3;         // co group (8 co)
    const int tG = tid & 7;          // token group (8 tokens)
    const float* xb = x + ((size_t)b * NC) * NTOK + n0;
    const float* Mb = g_M + (size_t)b * 65536;

    float acc[8][8];
#pragma unroll
    for (int i = 0; i < 8; i++)
#pragma unroll
        for (int j = 0; j < 8; j++) acc[i][j] = 0.f;

#pragma unroll 1
    for (int cc = 0; cc < 8; cc++) {
        __syncthreads();
#pragma unroll
        for (int p = 0; p < 8; p++) {
            int idx = tid + p * 256; int ci = idx >> 6, tok = idx & 63;
            As[ci * 68 + tok] = xb[(size_t)(cc * 32 + ci) * NTOK + tok];
        }
#pragma unroll
        for (int p = 0; p < 32; p++) {
            int idx = tid + p * 256; int ci = idx >> 8, co = idx & 255;
            Ms[ci * 260 + co] = Mb[(cc * 32 + ci) * NC + co];
        }
        __syncthreads();
#pragma unroll 4
        for (int k = 0; k < 32; k++) {
            float4 a0 = *(const float4*)&As[k * 68 + tG * 8];
            float4 a1 = *(const float4*)&As[k * 68 + tG * 8 + 4];
            float4 m0 = *(const float4*)&Ms[k * 260 + cG * 8];
            float4 m1 = *(const float4*)&Ms[k * 260 + cG * 8 + 4];
            float a[8] = {a0.x, a0.y, a0.z, a0.w, a1.x, a1.y, a1.z, a1.w};
            float m[8] = {m0.x, m0.y, m0.z, m0.w, m1.x, m1.y, m1.z, m1.w};
#pragma unroll
            for (int i = 0; i < 8; i++)
#pragma unroll
                for (int j = 0; j < 8; j++) acc[i][j] += a[i] * m[j];
        }
    }
    __syncthreads();   // GEMM reads done; smem reused as stage

    // epilogue: + RQ + PQ + biasq, x2, stage
    {
        int co0 = cG * 8;
        float4 rq0 = *(const float4*)&g_RQ[(b * 128 + y) * NC + co0];
        float4 rq1 = *(const float4*)&g_RQ[(b * 128 + y) * NC + co0 + 4];
        float4 qb0 = *(const float4*)&g_biasq[b * NC + co0];
        float4 qb1 = *(const float4*)&g_biasq[b * NC + co0 + 4];
        float r[8] = {rq0.x + qb0.x, rq0.y + qb0.y, rq0.z + qb0.z, rq0.w + qb0.w,
                      rq1.x + qb1.x, rq1.y + qb1.y, rq1.z + qb1.z, rq1.w + qb1.w};
#pragma unroll
        for (int i = 0; i < 8; i++) {
            int tl = tG * 8 + i;
            float4 pq0 = *(const float4*)&g_PQ[(b * 128 + x0 + tl) * NC + co0];
            float4 pq1 = *(const float4*)&g_PQ[(b * 128 + x0 + tl) * NC + co0 + 4];
            float pq[8] = {pq0.x, pq0.y, pq0.z, pq0.w, pq1.x, pq1.y, pq1.z, pq1.w};
            float4 o0, o1;
            o0.x = 2.f * (acc[i][0] + r[0] + pq[0]);
            o0.y = 2.f * (acc[i][1] + r[1] + pq[1]);
            o0.z = 2.f * (acc[i][2] + r[2] + pq[2]);
            o0.w = 2.f * (acc[i][3] + r[3] + pq[3]);
            o1.x = 2.f * (acc[i][4] + r[4] + pq[4]);
            o1.y = 2.f * (acc[i][5] + r[5] + pq[5]);
            o1.z = 2.f * (acc[i][6] + r[6] + pq[6]);
            o1.w = 2.f * (acc[i][7] + r[7] + pq[7]);
            *(float4*)&stg[tl * 260 + co0] = o0;
            *(float4*)&stg[tl * 260 + co0 + 4] = o1;
        }
    }
    __syncthreads();

    // LN statistics: 4 threads per token
    {
        int token = tid >> 2, q = tid & 3;
        float s = 0.f, s2 = 0.f;
#pragma unroll
        for (int jj = 0; jj < 16; jj++) {
            float4 v = *(const float4*)&stg[token * 260 + q * 64 + jj * 4];
            s  += v.x + v.y + v.z + v.w;
            s2 += v.x * v.x + v.y * v.y + v.z * v.z + v.w * v.w;
        }
#pragma unroll
        for (int off = 1; off < 4; off <<= 1) {
            s  += __shfl_xor_sync(0xffffffffu, s, off);
            s2 += __shfl_xor_sync(0xffffffffu, s2, off);
        }
        if (q == 0) {
            float mu = s * (1.f / 256.f);
            musm[token] = mu;
            rssm[token] = rsqrtf(s2 * (1.f / 256.f) - mu * mu + 1e-5f);
        }
    }
    __syncthreads();

    // normalize + transposed coalesced store
    {
        int t = tid & 63, cG2 = tid >> 6;
        float mu = musm[t], rs = rssm[t];
        size_t obase = ((size_t)b * NC) * NTOK + n0 + t;
#pragma unroll 4
        for (int p = 0; p < 64; p++) {
            int co = cG2 * 64 + p;
            float v = stg[t * 260 + co];
            out[obase + (size_t)co * NTOK] = (v - mu) * rs * g_ln[co] + b_ln[co];
        }
    }
}

// ------------------------- launch -------------------------
extern "C" void kernel_launch(void* const* d_in, const int* in_sizes, int n_in,
                              void* d_out, int out_size) {
    const float* x    = (const float*)d_in[0];
    const float* Wq   = (const float*)d_in[1];
    const float* bq   = (const float*)d_in[2];
    const float* Wk   = (const float*)d_in[3];
    const float* bk   = (const float*)d_in[4];
    const float* Wv   = (const float*)d_in[5];
    const float* bv   = (const float*)d_in[6];
    const float* gK   = (const float*)d_in[7];
    const float* bK   = (const float*)d_in[8];
    const float* gV   = (const float*)d_in[9];
    const float* bV   = (const float*)d_in[10];
    const float* g_ln = (const float*)d_in[11];
    const float* b_ln = (const float*)d_in[12];
    float* out = (float*)d_out;

    cudaFuncSetAttribute(k1_kvscores, cudaFuncAttributeMaxDynamicSharedMemorySize, 25984 * 4);
    cudaFuncSetAttribute(k3_out, cudaFuncAttributeMaxDynamicSharedMemorySize, 16768 * 4);

    prep0_kernel<<<256, 256>>>(Wk, Wv);
    prep1_kernel<<<16, 256>>>();
    k1_kvscores<<<dim3(128, 8), 256, 25984 * 4>>>(x, bk, bv, gK, bK, gV, bV);
    k2_reduce<<<64, 256>>>();
    k2b_buildM<<<dim3(8, 8), 256>>>(Wq, bq);
    k2c_rqpq<<<dim3(128, 8), 256>>>();
    k3_out<<<dim3(256, 8), 256, 16768 * 4>>>(x, g_ln, b_ln, out);
}

// round 3
// speedup vs baseline: 1.0670x; 1.0670x over previous
#include <cuda_runtime.h>
#include <math.h>

#define NB 8
#define NC 256
#define NHW 128
#define NTOK 16384
#define NHEADS 8
#define DK 32

typedef unsigned long long u64;

// ---- packed f32x2 helpers (FFMA2: 2 fp32 FMAs per issue; bit-exact) ----
__device__ __forceinline__ void fma2(u64 &d, u64 a, u64 b) {
    asm("fma.rn.f32x2 %0, %1, %2, %3;" : "=l"(d) : "l"(a), "l"(b), "l"(d));
}
__device__ __forceinline__ u64 dup2(float a) {
    u64 r; asm("mov.b64 %0, {%1, %1};" : "=l"(r) : "f"(a)); return r;
}
__device__ __forceinline__ float2 unpk(u64 v) {
    float2 r; asm("mov.b64 {%0, %1}, %2;" : "=f"(r.x), "=f"(r.y) : "l"(v)); return r;
}

// ------------------------- device scratch -------------------------
__device__ float g_T[NHW * 128];              // sine table (same for y and x; h==w)
__device__ float g_WkT[NC * NC];              // Wk transposed [ci][co]
__device__ float g_WvT[NC * NC];
__device__ float g_RK[NHW * NC];              // pos-y contribution to K proj
__device__ float g_PK[NHW * NC];              // pos-x contribution to K proj
__device__ float g_spart[(size_t)NB * NHW * NHEADS * DK * DK];  // per-row score partials
__device__ float g_S[NB * NHEADS * DK * DK];  // reduced scores / n
__device__ float g_M[NB * NC * NC];           // fused Wq^T @ blockdiag(S) per batch
__device__ float g_biasq[NB * NC];
__device__ float g_RQ[NB * NHW * NC];
__device__ float g_PQ[NB * NHW * NC];

// ------------------------- prep0: transposes + sine table -------------------------
__global__ void prep0_kernel(const float* __restrict__ Wk, const float* __restrict__ Wv) {
    int idx = blockIdx.x * 256 + threadIdx.x;   // 65536 threads
    int co = idx >> 8, ci = idx & 255;
    g_WkT[ci * NC + co] = Wk[idx];
    g_WvT[ci * NC + co] = Wv[idx];
    if (idx < NHW * 128) {
        int p = idx >> 7;          // position 0..127
        int c = idx & 127;         // channel 0..127
        int j = c >> 1;
        float dimt = powf(10000.0f, (float)j * (1.0f / 64.0f));
        float base = (float)(p + 1) * (6.283185307179586f / (128.0f + 1e-6f));
        float t = base / dimt;
        g_T[idx] = (c & 1) ? cosf(t) : sinf(t);
    }
}

// ------------------------- prep1: RK/PK tables from WkT -------------------------
__global__ void prep1_kernel() {
    int table = blockIdx.x >> 3, chunk = blockIdx.x & 7;  // 16 blocks
    int n = chunk * 32 + (threadIdx.x & 31);
    int yg = threadIdx.x >> 5;                            // 8 groups of 16 positions
    float acc[16];
#pragma unroll
    for (int i = 0; i < 16; i++) acc[i] = 0.f;
    const float* W = g_WkT + (table ? 128 * NC : 0);
#pragma unroll 4
    for (int c = 0; c < 128; c++) {
        float w = W[c * NC + n];
#pragma unroll
        for (int yy = 0; yy < 16; yy++)
            acc[yy] += g_T[(yg * 16 + yy) * 128 + c] * w;
    }
    float* dst = table ? g_PK : g_RK;
#pragma unroll
    for (int yy = 0; yy < 16; yy++) dst[(yg * 16 + yy) * NC + n] = acc[yy];
}

// ------------------------- K1: fused K/V proj + per-head LN + scores -------------------------
// grid (128 image rows, 8 batch), 256 threads, dyn smem 103936B
__global__ void __launch_bounds__(256, 2) k1_kvscores(
    const float* __restrict__ x,
    const float* __restrict__ bk, const float* __restrict__ bv,
    const float* __restrict__ gK, const float* __restrict__ bKp,
    const float* __restrict__ gV, const float* __restrict__ bVp)
{
    extern __shared__ float sm[];
    float* As  = sm;                 // [32][132]
    float* Wks = As + 32 * 132;      // [32][68]
    float* Wvs = Wks + 32 * 68;      // [32][68]
    float* Ksm = Wvs + 32 * 68;      // [128][68]
    float* Vsm = Ksm + 128 * 68;     // [128][68]

    const int tid = threadIdx.x;
    const int rb = blockIdx.x;       // image row (y)
    const int b  = blockIdx.y;
    const int ty = tid >> 4;         // token group (8 tokens)
    const int tx = tid & 15;         // co group (4 co)
    const float* xb = x + ((size_t)b * NC) * NTOK + rb * 128;

#pragma unroll 1
    for (int nc = 0; nc < 4; nc++) {             // 64-co chunk = heads 2nc, 2nc+1
        // token-pair (ip) x co (j) accumulators, packed f32x2
        u64 accK2[4][4], accV2[4][4];
#pragma unroll
        for (int i = 0; i < 4; i++)
#pragma unroll
            for (int j = 0; j < 4; j++) { accK2[i][j] = 0ull; accV2[i][j] = 0ull; }

#pragma unroll 1
        for (int cc = 0; cc < 8; cc++) {
            __syncthreads();
#pragma unroll
            for (int p = 0; p < 16; p++) {
                int idx = tid + p * 256; int ci = idx >> 7, tok = idx & 127;
                As[ci * 132 + tok] = xb[(size_t)(cc * 32 + ci) * NTOK + tok];
            }
#pragma unroll
            for (int p = 0; p < 8; p++) {
                int idx = tid + p * 256; int ci = idx >> 6, j = idx & 63;
                Wks[ci * 68 + j] = g_WkT[(cc * 32 + ci) * NC + nc * 64 + j];
                Wvs[ci * 68 + j] = g_WvT[(cc * 32 + ci) * NC + nc * 64 + j];
            }
            __syncthreads();
#pragma unroll 8
            for (int k = 0; k < 32; k++) {
                ulonglong2 a01 = *(const ulonglong2*)&As[k * 132 + ty * 8];
                ulonglong2 a23 = *(const ulonglong2*)&As[k * 132 + ty * 8 + 4];
                float4 wk = *(const float4*)&Wks[k * 68 + tx * 4];
                float4 wv = *(const float4*)&Wvs[k * 68 + tx * 4];
                u64 ap[4] = {a01.x, a01.y, a23.x, a23.y};
                u64 wkd[4] = {dup2(wk.x), dup2(wk.y), dup2(wk.z), dup2(wk.w)};
                u64 wvd[4] = {dup2(wv.x), dup2(wv.y), dup2(wv.z), dup2(wv.w)};
#pragma unroll
                for (int i = 0; i < 4; i++)
#pragma unroll
                    for (int j = 0; j < 4; j++) {
                        fma2(accK2[i][j], ap[i], wkd[j]);
                        fma2(accV2[i][j], ap[i], wvd[j]);
                    }
            }
        }
        __syncthreads();

        // unpack to scalar accumulators (token i = 2*ip + s)
        float accK[8][4], accV[8][4];
#pragma unroll
        for (int ip = 0; ip < 4; ip++)
#pragma unroll
            for (int j = 0; j < 4; j++) {
                float2 fk = unpk(accK2[ip][j]);
                float2 fv = unpk(accV2[ip][j]);
                accK[2 * ip][j] = fk.x; accK[2 * ip + 1][j] = fk.y;
                accV[2 * ip][j] = fv.x; accV[2 * ip + 1][j] = fv.y;
            }

        // epilogue: add pos tables + bias, stage to smem
        {
            int coB = nc * 64 + tx * 4;
            float4 rk  = *(const float4*)&g_RK[rb * NC + coB];
            float4 bk4 = *(const float4*)&bk[coB];
            float4 bv4 = *(const float4*)&bv[coB];
#pragma unroll
            for (int i = 0; i < 8; i++) {
                int tok = ty * 8 + i;
                float4 pk = *(const float4*)&g_PK[tok * NC + coB];
                float4 ko, vo;
                ko.x = accK[i][0] + rk.x + pk.x + bk4.x;
                ko.y = accK[i][1] + rk.y + pk.y + bk4.y;
                ko.z = accK[i][2] + rk.z + pk.z + bk4.z;
                ko.w = accK[i][3] + rk.w + pk.w + bk4.w;
                vo.x = accV[i][0] + bv4.x;
                vo.y = accV[i][1] + bv4.y;
                vo.z = accV[i][2] + bv4.z;
                vo.w = accV[i][3] + bv4.w;
                *(float4*)&Ksm[tok * 68 + tx * 4] = ko;
                *(float4*)&Vsm[tok * 68 + tx * 4] = vo;
            }
        }
        __syncthreads();

        // per-head LayerNorm in place (token, head-half per thread)
        {
            int tok = tid & 127, hl = tid >> 7;
            int head = nc * 2 + hl;
            float* kp = &Ksm[tok * 68 + hl * 32];
            float* vp = &Vsm[tok * 68 + hl * 32];
            const float4* gk4 = (const float4*)(gK + head * 32);
            const float4* bk4 = (const float4*)(bKp + head * 32);
            const float4* gv4 = (const float4*)(gV + head * 32);
            const float4* bv4 = (const float4*)(bVp + head * 32);

            float4 r[8]; float s = 0.f, s2 = 0.f;
#pragma unroll
            for (int jj = 0; jj < 8; jj++) {
                r[jj] = ((const float4*)kp)[jj];
                s  += r[jj].x + r[jj].y + r[jj].z + r[jj].w;
                s2 += r[jj].x * r[jj].x + r[jj].y * r[jj].y + r[jj].z * r[jj].z + r[jj].w * r[jj].w;
            }
            float mu = s * (1.f / 32.f);
            float rstd = rsqrtf(s2 * (1.f / 32.f) - mu * mu + 1e-5f);
#pragma unroll
            for (int jj = 0; jj < 8; jj++) {
                float4 g = gk4[jj], be = bk4[jj], o;
                o.x = (r[jj].x - mu) * rstd * g.x + be.x;
                o.y = (r[jj].y - mu) * rstd * g.y + be.y;
                o.z = (r[jj].z - mu) * rstd * g.z + be.z;
                o.w = (r[jj].w - mu) * rstd * g.w + be.w;
                ((float4*)kp)[jj] = o;
            }
            s = 0.f; s2 = 0.f;
#pragma unroll
            for (int jj = 0; jj < 8; jj++) {
                r[jj] = ((const float4*)vp)[jj];
                s  += r[jj].x + r[jj].y + r[jj].z + r[jj].w;
                s2 += r[jj].x * r[jj].x + r[jj].y * r[jj].y + r[jj].z * r[jj].z + r[jj].w * r[jj].w;
            }
            mu = s * (1.f / 32.f);
            rstd = rsqrtf(s2 * (1.f / 32.f) - mu * mu + 1e-5f);
#pragma unroll
            for (int jj = 0; jj < 8; jj++) {
                float4 g = gv4[jj], be = bv4[jj], o;
                o.x = (r[jj].x - mu) * rstd * g.x + be.x;
                o.y = (r[jj].y - mu) * rstd * g.y + be.y;
                o.z = (r[jj].z - mu) * rstd * g.z + be.z;
                o.w = (r[jj].w - mu) * rstd * g.w + be.w;
                ((float4*)vp)[jj] = o;
            }
        }
        __syncthreads();

        // score outer-product accumulation: S[head][d][e] over 128 tokens (f32x2)
        {
            int hl = tid >> 7, d = (tid >> 2) & 31, eg = tid & 3;
            u64 sacc2[4] = {0ull, 0ull, 0ull, 0ull};
#pragma unroll 4
            for (int tok = 0; tok < 128; tok++) {
                u64 kdd = dup2(Ksm[tok * 68 + hl * 32 + d]);
                ulonglong2 v01 = *(const ulonglong2*)&Vsm[tok * 68 + hl * 32 + eg * 8];
                ulonglong2 v23 = *(const ulonglong2*)&Vsm[tok * 68 + hl * 32 + eg * 8 + 4];
                fma2(sacc2[0], kdd, v01.x);
                fma2(sacc2[1], kdd, v01.y);
                fma2(sacc2[2], kdd, v23.x);
                fma2(sacc2[3], kdd, v23.y);
            }
            float* dst = g_spart + ((size_t)(b * 128 + rb)) * 8192
                         + (size_t)(nc * 2 + hl) * 1024 + d * 32 + eg * 8;
#pragma unroll
            for (int j = 0; j < 4; j++) *(u64*)&dst[2 * j] = sacc2[j];
        }
    }
}

// ------------------------- K2a: reduce partials -> S / n -------------------------
__global__ void k2_reduce() {
    int b = blockIdx.x >> 5, seg = blockIdx.x & 31;   // 256 blocks
    int base = seg * 256 + threadIdx.x;
    float s = 0.f;
#pragma unroll 8
    for (int rb = 0; rb < 128; rb++)
        s += g_spart[((size_t)(b * 128 + rb)) * 8192 + base];
    g_S[b * 8192 + base] = s * (1.0f / 16384.0f);
}

// ------------------------- K2b: M_b = Wq^T @ blockdiag(S_b), biasq -------------------------
__global__ void k2b_buildM(const float* __restrict__ Wq, const float* __restrict__ bq) {
    __shared__ float Wqs[256 * 33];
    int chunk = blockIdx.x, b = blockIdx.y;
    int co = threadIdx.x, h = co >> 5, e = co & 31;
    for (int idx = threadIdx.x; idx < 8192; idx += 256) {
        int row = idx >> 5, cil = idx & 31;
        Wqs[row * 33 + cil] = Wq[row * NC + chunk * 32 + cil];
    }
    float Scol[32];
#pragma unroll
    for (int d = 0; d < 32; d++) Scol[d] = g_S[b * 8192 + h * 1024 + d * 32 + e];
    __syncthreads();
    for (int cil = 0; cil < 32; cil++) {
        float m = 0.f;
#pragma unroll
        for (int d = 0; d < 32; d++) m += Wqs[(h * 32 + d) * 33 + cil] * Scol[d];
        g_M[(size_t)b * 65536 + (chunk * 32 + cil) * NC + co] = m;
    }
    if (chunk == 0) {
        float bb = 0.f;
#pragma unroll
        for (int d = 0; d < 32; d++) bb += bq[h * 32 + d] * Scol[d];
        g_biasq[b * NC + co] = bb;
    }
}

// ------------------------- K2c: RQ/PQ tables from M -------------------------
__global__ void k2c_rqpq() {
    int p = blockIdx.x, b = blockIdx.y;
    int co = threadIdx.x;
    float accR = 0.f, accP = 0.f;
#pragma unroll 4
    for (int c = 0; c < 128; c++) {
        float tv = g_T[p * 128 + c];
        accR += tv * g_M[(size_t)b * 65536 + c * NC + co];
        accP += tv * g_M[(size_t)b * 65536 + (128 + c) * NC + co];
    }
    g_RQ[(b * 128 + p) * NC + co] = accR;
    g_PQ[(b * 128 + p) * NC + co] = accP;
}

// ------------------------- K3: out GEMM + x2 + final LN + transposed store -------------------------
// grid (256 tiles of 64 tokens, 8 batch), 256 threads, dyn smem 67072B
__global__ void __launch_bounds__(256, 2) k3_out(
    const float* __restrict__ x,
    const float* __restrict__ g_ln, const float* __restrict__ b_ln,
    float* __restrict__ out)
{
    extern __shared__ float sm[];
    float* As = sm;                  // [32][68] (GEMM phase)
    float* Ms = sm + 32 * 68;        // [32][260] (GEMM phase)
    float* stg = sm;                 // [64][260] (epilogue; overlaps As/Ms)
    float* musm = sm + 64 * 260;     // [64]
    float* rssm = musm + 64;         // [64]

    const int tid = threadIdx.x;
    const int tile = blockIdx.x;     // 0..255
    const int b = blockIdx.y;
    const int n0 = tile * 64;
    const int y = n0 >> 7;
    const int x0 = (n0 & 127);
    const int cG = tid >> 3;         // co group (8 co)
    const int tG = tid & 7;          // token group (8 tokens)
    const float* xb = x + ((size_t)b * NC) * NTOK + n0;
    const float* Mb = g_M + (size_t)b * 65536;

    // token i x co-pair j2 accumulators, packed f32x2
    u64 acc2[8][4];
#pragma unroll
    for (int i = 0; i < 8; i++)
#pragma unroll
        for (int j = 0; j < 4; j++) acc2[i][j] = 0ull;

#pragma unroll 1
    for (int cc = 0; cc < 8; cc++) {
        __syncthreads();
#pragma unroll
        for (int p = 0; p < 8; p++) {
            int idx = tid + p * 256; int ci = idx >> 6, tok = idx & 63;
            As[ci * 68 + tok] = xb[(size_t)(cc * 32 + ci) * NTOK + tok];
        }
#pragma unroll
        for (int p = 0; p < 32; p++) {
            int idx = tid + p * 256; int ci = idx >> 8, co = idx & 255;
            Ms[ci * 260 + co] = Mb[(cc * 32 + ci) * NC + co];
        }
        __syncthreads();
#pragma unroll 4
        for (int k = 0; k < 32; k++) {
            float4 a0 = *(const float4*)&As[k * 68 + tG * 8];
            float4 a1 = *(const float4*)&As[k * 68 + tG * 8 + 4];
            ulonglong2 m01 = *(const ulonglong2*)&Ms[k * 260 + cG * 8];
            ulonglong2 m23 = *(const ulonglong2*)&Ms[k * 260 + cG * 8 + 4];
            u64 mp[4] = {m01.x, m01.y, m23.x, m23.y};
            float a[8] = {a0.x, a0.y, a0.z, a0.w, a1.x, a1.y, a1.z, a1.w};
#pragma unroll
            for (int i = 0; i < 8; i++) {
                u64 ad = dup2(a[i]);
#pragma unroll
                for (int j = 0; j < 4; j++) fma2(acc2[i][j], ad, mp[j]);
            }
        }
    }
    __syncthreads();   // GEMM reads done; smem reused as stage

    // unpack
    float acc[8][8];
#pragma unroll
    for (int i = 0; i < 8; i++)
#pragma unroll
        for (int j = 0; j < 4; j++) {
            float2 f = unpk(acc2[i][j]);
            acc[i][2 * j] = f.x; acc[i][2 * j + 1] = f.y;
        }

    // epilogue: + RQ + PQ + biasq, x2, stage
    {
        int co0 = cG * 8;
        float4 rq0 = *(const float4*)&g_RQ[(b * 128 + y) * NC + co0];
        float4 rq1 = *(const float4*)&g_RQ[(b * 128 + y) * NC + co0 + 4];
        float4 qb0 = *(const float4*)&g_biasq[b * NC + co0];
        float4 qb1 = *(const float4*)&g_biasq[b * NC + co0 + 4];
        float r[8] = {rq0.x + qb0.x, rq0.y + qb0.y, rq0.z + qb0.z, rq0.w + qb0.w,
                      rq1.x + qb1.x, rq1.y + qb1.y, rq1.z + qb1.z, rq1.w + qb1.w};
#pragma unroll
        for (int i = 0; i < 8; i++) {
            int tl = tG * 8 + i;
            float4 pq0 = *(const float4*)&g_PQ[(b * 128 + x0 + tl) * NC + co0];
            float4 pq1 = *(const float4*)&g_PQ[(b * 128 + x0 + tl) * NC + co0 + 4];
            float pq[8] = {pq0.x, pq0.y, pq0.z, pq0.w, pq1.x, pq1.y, pq1.z, pq1.w};
            float4 o0, o1;
            o0.x = 2.f * (acc[i][0] + r[0] + pq[0]);
            o0.y = 2.f * (acc[i][1] + r[1] + pq[1]);
            o0.z = 2.f * (acc[i][2] + r[2] + pq[2]);
            o0.w = 2.f * (acc[i][3] + r[3] + pq[3]);
            o1.x = 2.f * (acc[i][4] + r[4] + pq[4]);
            o1.y = 2.f * (acc[i][5] + r[5] + pq[5]);
            o1.z = 2.f * (acc[i][6] + r[6] + pq[6]);
            o1.w = 2.f * (acc[i][7] + r[7] + pq[7]);
            *(float4*)&stg[tl * 260 + co0] = o0;
            *(float4*)&stg[tl * 260 + co0 + 4] = o1;
        }
    }
    __syncthreads();

    // LN statistics: 4 threads per token
    {
        int token = tid >> 2, q = tid & 3;
        float s = 0.f, s2 = 0.f;
#pragma unroll
        for (int jj = 0; jj < 16; jj++) {
            float4 v = *(const float4*)&stg[token * 260 + q * 64 + jj * 4];
            s  += v.x + v.y + v.z + v.w;
            s2 += v.x * v.x + v.y * v.y + v.z * v.z + v.w * v.w;
        }
#pragma unroll
        for (int off = 1; off < 4; off <<= 1) {
            s  += __shfl_xor_sync(0xffffffffu, s, off);
            s2 += __shfl_xor_sync(0xffffffffu, s2, off);
        }
        if (q == 0) {
            float mu = s * (1.f / 256.f);
            musm[token] = mu;
            rssm[token] = rsqrtf(s2 * (1.f / 256.f) - mu * mu + 1e-5f);
        }
    }
    __syncthreads();

    // normalize + transposed coalesced store
    {
        int t = tid & 63, cG2 = tid >> 6;
        float mu = musm[t], rs = rssm[t];
        size_t obase = ((size_t)b * NC) * NTOK + n0 + t;
#pragma unroll 4
        for (int p = 0; p < 64; p++) {
            int co = cG2 * 64 + p;
            float v = stg[t * 260 + co];
            out[obase + (size_t)co * NTOK] = (v - mu) * rs * g_ln[co] + b_ln[co];
        }
    }
}

// ------------------------- launch -------------------------
extern "C" void kernel_launch(void* const* d_in, const int* in_sizes, int n_in,
                              void* d_out, int out_size) {
    const float* x    = (const float*)d_in[0];
    const float* Wq   = (const float*)d_in[1];
    const float* bq   = (const float*)d_in[2];
    const float* Wk   = (const float*)d_in[3];
    const float* bk   = (const float*)d_in[4];
    const float* Wv   = (const float*)d_in[5];
    const float* bv   = (const float*)d_in[6];
    const float* gK   = (const float*)d_in[7];
    const float* bK   = (const float*)d_in[8];
    const float* gV   = (const float*)d_in[9];
    const float* bV   = (const float*)d_in[10];
    const float* g_ln = (const float*)d_in[11];
    const float* b_ln = (const float*)d_in[12];
    float* out = (float*)d_out;

    cudaFuncSetAttribute(k1_kvscores, cudaFuncAttributeMaxDynamicSharedMemorySize, 25984 * 4);
    cudaFuncSetAttribute(k3_out, cudaFuncAttributeMaxDynamicSharedMemorySize, 16768 * 4);

    prep0_kernel<<<256, 256>>>(Wk, Wv);
    prep1_kernel<<<16, 256>>>();
    k1_kvscores<<<dim3(128, 8), 256, 25984 * 4>>>(x, bk, bv, gK, bK, gV, bV);
    k2_reduce<<<256, 256>>>();
    k2b_buildM<<<dim3(8, 8), 256>>>(Wq, bq);
    k2c_rqpq<<<dim3(128, 8), 256>>>();
    k3_out<<<dim3(256, 8), 256, 16768 * 4>>>(x, g_ln, b_ln, out);
}

// round 4
// speedup vs baseline: 1.0678x; 1.0007x over previous
#include <cuda_runtime.h>
#include <math.h>

#define NB 8
#define NC 256
#define NHW 128
#define NTOK 16384
#define NHEADS 8
#define DK 32

typedef unsigned long long u64;

// ---- packed f32x2 helpers (FFMA2: 2 fp32 FMAs per issue; bit-exact) ----
__device__ __forceinline__ void fma2(u64 &d, u64 a, u64 b) {
    asm("fma.rn.f32x2 %0, %1, %2, %3;" : "=l"(d) : "l"(a), "l"(b), "l"(d));
}
__device__ __forceinline__ u64 dup2(float a) {
    u64 r; asm("mov.b64 %0, {%1, %1};" : "=l"(r) : "f"(a)); return r;
}
__device__ __forceinline__ float2 unpk(u64 v) {
    float2 r; asm("mov.b64 {%0, %1}, %2;" : "=f"(r.x), "=f"(r.y) : "l"(v)); return r;
}

// ------------------------- device scratch -------------------------
__device__ float g_T[NHW * 128];              // sine table (same for y and x; h==w)
__device__ float g_WkT[NC * NC];              // Wk transposed [ci][co]
__device__ float g_WvT[NC * NC];
__device__ float g_RK[NHW * NC];              // pos-y contribution to K proj
__device__ float g_PK[NHW * NC];              // pos-x contribution to K proj
__device__ float g_spart[(size_t)NB * NHW * NHEADS * DK * DK];  // per-row score partials
__device__ float g_S[NB * NHEADS * DK * DK];  // reduced scores / n
__device__ float g_M[NB * NC * NC];           // fused Wq^T @ blockdiag(S) per batch
__device__ float g_biasq[NB * NC];
__device__ float g_RQ[NB * NHW * NC];
__device__ float g_PQ[NB * NHW * NC];

// ------------------------- prep0: transposes + sine table -------------------------
__global__ void prep0_kernel(const float* __restrict__ Wk, const float* __restrict__ Wv) {
    int idx = blockIdx.x * 256 + threadIdx.x;   // 65536 threads
    int co = idx >> 8, ci = idx & 255;
    g_WkT[ci * NC + co] = Wk[idx];
    g_WvT[ci * NC + co] = Wv[idx];
    if (idx < NHW * 128) {
        int p = idx >> 7;          // position 0..127
        int c = idx & 127;         // channel 0..127
        int j = c >> 1;
        float dimt = powf(10000.0f, (float)j * (1.0f / 64.0f));
        float base = (float)(p + 1) * (6.283185307179586f / (128.0f + 1e-6f));
        float t = base / dimt;
        g_T[idx] = (c & 1) ? cosf(t) : sinf(t);
    }
}

// ------------------------- prep1: RK/PK tables from WkT -------------------------
__global__ void prep1_kernel() {
    int table = blockIdx.x >> 3, chunk = blockIdx.x & 7;  // 16 blocks
    int n = chunk * 32 + (threadIdx.x & 31);
    int yg = threadIdx.x >> 5;                            // 8 groups of 16 positions
    float acc[16];
#pragma unroll
    for (int i = 0; i < 16; i++) acc[i] = 0.f;
    const float* W = g_WkT + (table ? 128 * NC : 0);
#pragma unroll 4
    for (int c = 0; c < 128; c++) {
        float w = W[c * NC + n];
#pragma unroll
        for (int yy = 0; yy < 16; yy++)
            acc[yy] += g_T[(yg * 16 + yy) * 128 + c] * w;
    }
    float* dst = table ? g_PK : g_RK;
#pragma unroll
    for (int yy = 0; yy < 16; yy++) dst[(yg * 16 + yy) * NC + n] = acc[yy];
}

// ------------------------- K1: fused K/V proj + per-head LN + scores -------------------------
// grid (128 image rows, 8 batch), 256 threads, dyn smem 103936B
__global__ void __launch_bounds__(256, 2) k1_kvscores(
    const float* __restrict__ x,
    const float* __restrict__ bk, const float* __restrict__ bv,
    const float* __restrict__ gK, const float* __restrict__ bKp,
    const float* __restrict__ gV, const float* __restrict__ bVp)
{
    extern __shared__ float sm[];
    float* As  = sm;                 // [32][132]
    float* Wks = As + 32 * 132;      // [32][68]
    float* Wvs = Wks + 32 * 68;      // [32][68]
    float* Ksm = Wvs + 32 * 68;      // [128][68]
    float* Vsm = Ksm + 128 * 68;     // [128][68]

    const int tid = threadIdx.x;
    const int rb = blockIdx.x;       // image row (y)
    const int b  = blockIdx.y;
    const int ty = tid >> 4;         // token group (8 tokens)
    const int tx = tid & 15;         // co group (4 co)
    const float* xb = x + ((size_t)b * NC) * NTOK + rb * 128;

#pragma unroll 1
    for (int nc = 0; nc < 4; nc++) {             // 64-co chunk = heads 2nc, 2nc+1
        // token-pair (ip) x co (j) accumulators, packed f32x2
        u64 accK2[4][4], accV2[4][4];
#pragma unroll
        for (int i = 0; i < 4; i++)
#pragma unroll
            for (int j = 0; j < 4; j++) { accK2[i][j] = 0ull; accV2[i][j] = 0ull; }

#pragma unroll 1
        for (int cc = 0; cc < 8; cc++) {
            __syncthreads();
#pragma unroll
            for (int p = 0; p < 16; p++) {
                int idx = tid + p * 256; int ci = idx >> 7, tok = idx & 127;
                As[ci * 132 + tok] = xb[(size_t)(cc * 32 + ci) * NTOK + tok];
            }
#pragma unroll
            for (int p = 0; p < 8; p++) {
                int idx = tid + p * 256; int ci = idx >> 6, j = idx & 63;
                Wks[ci * 68 + j] = g_WkT[(cc * 32 + ci) * NC + nc * 64 + j];
                Wvs[ci * 68 + j] = g_WvT[(cc * 32 + ci) * NC + nc * 64 + j];
            }
            __syncthreads();
#pragma unroll 8
            for (int k = 0; k < 32; k++) {
                ulonglong2 a01 = *(const ulonglong2*)&As[k * 132 + ty * 8];
                ulonglong2 a23 = *(const ulonglong2*)&As[k * 132 + ty * 8 + 4];
                float4 wk = *(const float4*)&Wks[k * 68 + tx * 4];
                float4 wv = *(const float4*)&Wvs[k * 68 + tx * 4];
                u64 ap[4] = {a01.x, a01.y, a23.x, a23.y};
                u64 wkd[4] = {dup2(wk.x), dup2(wk.y), dup2(wk.z), dup2(wk.w)};
                u64 wvd[4] = {dup2(wv.x), dup2(wv.y), dup2(wv.z), dup2(wv.w)};
#pragma unroll
                for (int i = 0; i < 4; i++)
#pragma unroll
                    for (int j = 0; j < 4; j++) {
                        fma2(accK2[i][j], ap[i], wkd[j]);
                        fma2(accV2[i][j], ap[i], wvd[j]);
                    }
            }
        }
        __syncthreads();

        // unpack to scalar accumulators (token i = 2*ip + s)
        float accK[8][4], accV[8][4];
#pragma unroll
        for (int ip = 0; ip < 4; ip++)
#pragma unroll
            for (int j = 0; j < 4; j++) {
                float2 fk = unpk(accK2[ip][j]);
                float2 fv = unpk(accV2[ip][j]);
                accK[2 * ip][j] = fk.x; accK[2 * ip + 1][j] = fk.y;
                accV[2 * ip][j] = fv.x; accV[2 * ip + 1][j] = fv.y;
            }

        // epilogue: add pos tables + bias, stage to smem
        {
            int coB = nc * 64 + tx * 4;
            float4 rk  = *(const float4*)&g_RK[rb * NC + coB];
            float4 bk4 = *(const float4*)&bk[coB];
            float4 bv4 = *(const float4*)&bv[coB];
#pragma unroll
            for (int i = 0; i < 8; i++) {
                int tok = ty * 8 + i;
                float4 pk = *(const float4*)&g_PK[tok * NC + coB];
                float4 ko, vo;
                ko.x = accK[i][0] + rk.x + pk.x + bk4.x;
                ko.y = accK[i][1] + rk.y + pk.y + bk4.y;
                ko.z = accK[i][2] + rk.z + pk.z + bk4.z;
                ko.w = accK[i][3] + rk.w + pk.w + bk4.w;
                vo.x = accV[i][0] + bv4.x;
                vo.y = accV[i][1] + bv4.y;
                vo.z = accV[i][2] + bv4.z;
                vo.w = accV[i][3] + bv4.w;
                *(float4*)&Ksm[tok * 68 + tx * 4] = ko;
                *(float4*)&Vsm[tok * 68 + tx * 4] = vo;
            }
        }
        __syncthreads();

        // per-head LayerNorm in place (token, head-half per thread)
        {
            int tok = tid & 127, hl = tid >> 7;
            int head = nc * 2 + hl;
            float* kp = &Ksm[tok * 68 + hl * 32];
            float* vp = &Vsm[tok * 68 + hl * 32];
            const float4* gk4 = (const float4*)(gK + head * 32);
            const float4* bk4 = (const float4*)(bKp + head * 32);
            const float4* gv4 = (const float4*)(gV + head * 32);
            const float4* bv4 = (const float4*)(bVp + head * 32);

            float4 r[8]; float s = 0.f, s2 = 0.f;
#pragma unroll
            for (int jj = 0; jj < 8; jj++) {
                r[jj] = ((const float4*)kp)[jj];
                s  += r[jj].x + r[jj].y + r[jj].z + r[jj].w;
                s2 += r[jj].x * r[jj].x + r[jj].y * r[jj].y + r[jj].z * r[jj].z + r[jj].w * r[jj].w;
            }
            float mu = s * (1.f / 32.f);
            float rstd = rsqrtf(s2 * (1.f / 32.f) - mu * mu + 1e-5f);
#pragma unroll
            for (int jj = 0; jj < 8; jj++) {
                float4 g = gk4[jj], be = bk4[jj], o;
                o.x = (r[jj].x - mu) * rstd * g.x + be.x;
                o.y = (r[jj].y - mu) * rstd * g.y + be.y;
                o.z = (r[jj].z - mu) * rstd * g.z + be.z;
                o.w = (r[jj].w - mu) * rstd * g.w + be.w;
                ((float4*)kp)[jj] = o;
            }
            s = 0.f; s2 = 0.f;
#pragma unroll
            for (int jj = 0; jj < 8; jj++) {
                r[jj] = ((const float4*)vp)[jj];
                s  += r[jj].x + r[jj].y + r[jj].z + r[jj].w;
                s2 += r[jj].x * r[jj].x + r[jj].y * r[jj].y + r[jj].z * r[jj].z + r[jj].w * r[jj].w;
            }
            mu = s * (1.f / 32.f);
            rstd = rsqrtf(s2 * (1.f / 32.f) - mu * mu + 1e-5f);
#pragma unroll
            for (int jj = 0; jj < 8; jj++) {
                float4 g = gv4[jj], be = bv4[jj], o;
                o.x = (r[jj].x - mu) * rstd * g.x + be.x;
                o.y = (r[jj].y - mu) * rstd * g.y + be.y;
                o.z = (r[jj].z - mu) * rstd * g.z + be.z;
                o.w = (r[jj].w - mu) * rstd * g.w + be.w;
                ((float4*)vp)[jj] = o;
            }
        }
        __syncthreads();

        // score outer-product accumulation: S[head][d][e] over 128 tokens (f32x2)
        {
            int hl = tid >> 7, d = (tid >> 2) & 31, eg = tid & 3;
            u64 sacc2[4] = {0ull, 0ull, 0ull, 0ull};
#pragma unroll 4
            for (int tok = 0; tok < 128; tok++) {
                u64 kdd = dup2(Ksm[tok * 68 + hl * 32 + d]);
                ulonglong2 v01 = *(const ulonglong2*)&Vsm[tok * 68 + hl * 32 + eg * 8];
                ulonglong2 v23 = *(const ulonglong2*)&Vsm[tok * 68 + hl * 32 + eg * 8 + 4];
                fma2(sacc2[0], kdd, v01.x);
                fma2(sacc2[1], kdd, v01.y);
                fma2(sacc2[2], kdd, v23.x);
                fma2(sacc2[3], kdd, v23.y);
            }
            float* dst = g_spart + ((size_t)(b * 128 + rb)) * 8192
                         + (size_t)(nc * 2 + hl) * 1024 + d * 32 + eg * 8;
#pragma unroll
            for (int j = 0; j < 4; j++) *(u64*)&dst[2 * j] = sacc2[j];
        }
    }
}

// ------------------------- K2a: reduce partials -> S / n -------------------------
__global__ void k2_reduce() {
    int b = blockIdx.x >> 5, seg = blockIdx.x & 31;   // 256 blocks
    int base = seg * 256 + threadIdx.x;
    float s = 0.f;
#pragma unroll 8
    for (int rb = 0; rb < 128; rb++)
        s += g_spart[((size_t)(b * 128 + rb)) * 8192 + base];
    g_S[b * 8192 + base] = s * (1.0f / 16384.0f);
}

// ------------------------- K2b: M_b = Wq^T @ blockdiag(S_b), biasq -------------------------
__global__ void k2b_buildM(const float* __restrict__ Wq, const float* __restrict__ bq) {
    __shared__ float Wqs[256 * 33];
    int chunk = blockIdx.x, b = blockIdx.y;
    int co = threadIdx.x, h = co >> 5, e = co & 31;
    for (int idx = threadIdx.x; idx < 8192; idx += 256) {
        int row = idx >> 5, cil = idx & 31;
        Wqs[row * 33 + cil] = Wq[row * NC + chunk * 32 + cil];
    }
    float Scol[32];
#pragma unroll
    for (int d = 0; d < 32; d++) Scol[d] = g_S[b * 8192 + h * 1024 + d * 32 + e];
    __syncthreads();
    for (int cil = 0; cil < 32; cil++) {
        float m = 0.f;
#pragma unroll
        for (int d = 0; d < 32; d++) m += Wqs[(h * 32 + d) * 33 + cil] * Scol[d];
        g_M[(size_t)b * 65536 + (chunk * 32 + cil) * NC + co] = m;
    }
    if (chunk == 0) {
        float bb = 0.f;
#pragma unroll
        for (int d = 0; d < 32; d++) bb += bq[h * 32 + d] * Scol[d];
        g_biasq[b * NC + co] = bb;
    }
}

// ------------------------- K2c: RQ/PQ tables from M -------------------------
__global__ void k2c_rqpq() {
    int p = blockIdx.x, b = blockIdx.y;
    int co = threadIdx.x;
    float accR = 0.f, accP = 0.f;
#pragma unroll 4
    for (int c = 0; c < 128; c++) {
        float tv = g_T[p * 128 + c];
        accR += tv * g_M[(size_t)b * 65536 + c * NC + co];
        accP += tv * g_M[(size_t)b * 65536 + (128 + c) * NC + co];
    }
    g_RQ[(b * 128 + p) * NC + co] = accR;
    g_PQ[(b * 128 + p) * NC + co] = accP;
}

// ------------------------- K3: out GEMM + x2 + final LN + transposed store -------------------------
// grid (256 tiles of 64 tokens, 8 batch), 256 threads, dyn smem 67072B
__global__ void __launch_bounds__(256, 2) k3_out(
    const float* __restrict__ x,
    const float* __restrict__ g_ln, const float* __restrict__ b_ln,
    float* __restrict__ out)
{
    extern __shared__ float sm[];
    float* As = sm;                  // [32][68] (GEMM phase)
    float* Ms = sm + 32 * 68;        // [32][260] (GEMM phase)
    float* stg = sm;                 // [64][260] (epilogue; overlaps As/Ms)
    float* musm = sm + 64 * 260;     // [64]
    float* rssm = musm + 64;         // [64]

    const int tid = threadIdx.x;
    const int tile = blockIdx.x;     // 0..255
    const int b = blockIdx.y;
    const int n0 = tile * 64;
    const int y = n0 >> 7;
    const int x0 = (n0 & 127);
    const int cG = tid >> 3;         // co group (8 co)
    const int tG = tid & 7;          // token group (8 tokens)
    const float* xb = x + ((size_t)b * NC) * NTOK + n0;
    const float* Mb = g_M + (size_t)b * 65536;

    // token i x co-pair j2 accumulators, packed f32x2
    u64 acc2[8][4];
#pragma unroll
    for (int i = 0; i < 8; i++)
#pragma unroll
        for (int j = 0; j < 4; j++) acc2[i][j] = 0ull;

#pragma unroll 1
    for (int cc = 0; cc < 8; cc++) {
        __syncthreads();
#pragma unroll
        for (int p = 0; p < 8; p++) {
            int idx = tid + p * 256; int ci = idx >> 6, tok = idx & 63;
            As[ci * 68 + tok] = xb[(size_t)(cc * 32 + ci) * NTOK + tok];
        }
#pragma unroll
        for (int p = 0; p < 32; p++) {
            int idx = tid + p * 256; int ci = idx >> 8, co = idx & 255;
            Ms[ci * 260 + co] = Mb[(cc * 32 + ci) * NC + co];
        }
        __syncthreads();
#pragma unroll 4
        for (int k = 0; k < 32; k++) {
            float4 a0 = *(const float4*)&As[k * 68 + tG * 8];
            float4 a1 = *(const float4*)&As[k * 68 + tG * 8 + 4];
            ulonglong2 m01 = *(const ulonglong2*)&Ms[k * 260 + cG * 8];
            ulonglong2 m23 = *(const ulonglong2*)&Ms[k * 260 + cG * 8 + 4];
            u64 mp[4] = {m01.x, m01.y, m23.x, m23.y};
            float a[8] = {a0.x, a0.y, a0.z, a0.w, a1.x, a1.y, a1.z, a1.w};
#pragma unroll
            for (int i = 0; i < 8; i++) {
                u64 ad = dup2(a[i]);
#pragma unroll
                for (int j = 0; j < 4; j++) fma2(acc2[i][j], ad, mp[j]);
            }
        }
    }
    __syncthreads();   // GEMM reads done; smem reused as stage

    // unpack
    float acc[8][8];
#pragma unroll
    for (int i = 0; i < 8; i++)
#pragma unroll
        for (int j = 0; j < 4; j++) {
            float2 f = unpk(acc2[i][j]);
            acc[i][2 * j] = f.x; acc[i][2 * j + 1] = f.y;
        }

    // epilogue: + RQ + PQ + biasq, x2, stage
    {
        int co0 = cG * 8;
        float4 rq0 = *(const float4*)&g_RQ[(b * 128 + y) * NC + co0];
        float4 rq1 = *(const float4*)&g_RQ[(b * 128 + y) * NC + co0 + 4];
        float4 qb0 = *(const float4*)&g_biasq[b * NC + co0];
        float4 qb1 = *(const float4*)&g_biasq[b * NC + co0 + 4];
        float r[8] = {rq0.x + qb0.x, rq0.y + qb0.y, rq0.z + qb0.z, rq0.w + qb0.w,
                      rq1.x + qb1.x, rq1.y + qb1.y, rq1.z + qb1.z, rq1.w + qb1.w};
#pragma unroll
        for (int i = 0; i < 8; i++) {
            int tl = tG * 8 + i;
            float4 pq0 = *(const float4*)&g_PQ[(b * 128 + x0 + tl) * NC + co0];
            float4 pq1 = *(const float4*)&g_PQ[(b * 128 + x0 + tl) * NC + co0 + 4];
            float pq[8] = {pq0.x, pq0.y, pq0.z, pq0.w, pq1.x, pq1.y, pq1.z, pq1.w};
            float4 o0, o1;
            o0.x = 2.f * (acc[i][0] + r[0] + pq[0]);
            o0.y = 2.f * (acc[i][1] + r[1] + pq[1]);
            o0.z = 2.f * (acc[i][2] + r[2] + pq[2]);
            o0.w = 2.f * (acc[i][3] + r[3] + pq[3]);
            o1.x = 2.f * (acc[i][4] + r[4] + pq[4]);
            o1.y = 2.f * (acc[i][5] + r[5] + pq[5]);
            o1.z = 2.f * (acc[i][6] + r[6] + pq[6]);
            o1.w = 2.f * (acc[i][7] + r[7] + pq[7]);
            *(float4*)&stg[tl * 260 + co0] = o0;
            *(float4*)&stg[tl * 260 + co0 + 4] = o1;
        }
    }
    __syncthreads();

    // LN statistics: 4 threads per token
    {
        int token = tid >> 2, q = tid & 3;
        float s = 0.f, s2 = 0.f;
#pragma unroll
        for (int jj = 0; jj < 16; jj++) {
            float4 v = *(const float4*)&stg[token * 260 + q * 64 + jj * 4];
            s  += v.x + v.y + v.z + v.w;
            s2 += v.x * v.x + v.y * v.y + v.z * v.z + v.w * v.w;
        }
#pragma unroll
        for (int off = 1; off < 4; off <<= 1) {
            s  += __shfl_xor_sync(0xffffffffu, s, off);
            s2 += __shfl_xor_sync(0xffffffffu, s2, off);
        }
        if (q == 0) {
            float mu = s * (1.f / 256.f);
            musm[token] = mu;
            rssm[token] = rsqrtf(s2 * (1.f / 256.f) - mu * mu + 1e-5f);
        }
    }
    __syncthreads();

    // normalize + transposed coalesced store
    {
        int t = tid & 63, cG2 = tid >> 6;
        float mu = musm[t], rs = rssm[t];
        size_t obase = ((size_t)b * NC) * NTOK + n0 + t;
#pragma unroll 4
        for (int p = 0; p < 64; p++) {
            int co = cG2 * 64 + p;
            float v = stg[t * 260 + co];
            out[obase + (size_t)co * NTOK] = (v - mu) * rs * g_ln[co] + b_ln[co];
        }
    }
}

// ------------------------- launch -------------------------
extern "C" void kernel_launch(void* const* d_in, const int* in_sizes, int n_in,
                              void* d_out, int out_size) {
    const float* x    = (const float*)d_in[0];
    const float* Wq   = (const float*)d_in[1];
    const float* bq   = (const float*)d_in[2];
    const float* Wk   = (const float*)d_in[3];
    const float* bk   = (const float*)d_in[4];
    const float* Wv   = (const float*)d_in[5];
    const float* bv   = (const float*)d_in[6];
    const float* gK   = (const float*)d_in[7];
    const float* bK   = (const float*)d_in[8];
    const float* gV   = (const float*)d_in[9];
    const float* bV   = (const float*)d_in[10];
    const float* g_ln = (const float*)d_in[11];
    const float* b_ln = (const float*)d_in[12];
    float* out = (float*)d_out;

    cudaFuncSetAttribute(k1_kvscores, cudaFuncAttributeMaxDynamicSharedMemorySize, 25984 * 4);
    cudaFuncSetAttribute(k3_out, cudaFuncAttributeMaxDynamicSharedMemorySize, 16768 * 4);

    prep0_kernel<<<256, 256>>>(Wk, Wv);
    prep1_kernel<<<16, 256>>>();
    k1_kvscores<<<dim3(128, 8), 256, 25984 * 4>>>(x, bk, bv, gK, bK, gV, bV);
    k2_reduce<<<256, 256>>>();
    k2b_buildM<<<dim3(8, 8), 256>>>(Wq, bq);
    k2c_rqpq<<<dim3(128, 8), 256>>>();
    k3_out<<<dim3(256, 8), 256, 16768 * 4>>>(x, g_ln, b_ln, out);
}

// round 6
// speedup vs baseline: 1.2457x; 1.1666x over previous
#include <cuda_runtime.h>
#include <cuda_bf16.h>
#include <math.h>
#include <stdint.h>

#define NB 8
#define NC 256
#define NTOK 16384

__device__ __forceinline__ uint32_t s2u(const void* p) {
    uint32_t a;
    asm("{ .reg .u64 t; cvta.to.shared.u64 t, %1; cvt.u32.u64 %0, t; }" : "=r"(a) : "l"(p));
    return a;
}
__device__ __forceinline__ unsigned short bfu(float v) {
    __nv_bfloat16 h = __float2bfloat16(v);
    return *(unsigned short*)&h;
}
__device__ __forceinline__ float bf2f(unsigned short u) {
    __nv_bfloat16 h = *(__nv_bfloat16*)&u;
    return __bfloat162float(h);
}
__device__ __forceinline__ uint32_t f2tf(float f) {
    uint32_t r; asm("cvt.rna.tf32.f32 %0, %1;" : "=r"(r) : "f"(f)); return r;
}
__device__ __forceinline__ void ldm_x4(uint32_t r[4], uint32_t addr) {
    asm volatile("ldmatrix.sync.aligned.m8n8.x4.shared.b16 {%0,%1,%2,%3}, [%4];"
        : "=r"(r[0]), "=r"(r[1]), "=r"(r[2]), "=r"(r[3]) : "r"(addr));
}
__device__ __forceinline__ void mma_bf16(float c[4], const uint32_t a[4], const uint32_t b[2]) {
    asm volatile("mma.sync.aligned.m16n8k16.row.col.f32.bf16.bf16.f32 "
        "{%0,%1,%2,%3}, {%4,%5,%6,%7}, {%8,%9}, {%0,%1,%2,%3};"
        : "+f"(c[0]), "+f"(c[1]), "+f"(c[2]), "+f"(c[3])
        : "r"(a[0]), "r"(a[1]), "r"(a[2]), "r"(a[3]), "r"(b[0]), "r"(b[1]));
}
__device__ __forceinline__ void mma_tf32(float c[4], const uint32_t a[4], const uint32_t b[2]) {
    asm volatile("mma.sync.aligned.m16n8k8.row.col.f32.tf32.tf32.f32 "
        "{%0,%1,%2,%3}, {%4,%5,%6,%7}, {%8,%9}, {%0,%1,%2,%3};"
        : "+f"(c[0]), "+f"(c[1]), "+f"(c[2]), "+f"(c[3])
        : "r"(a[0]), "r"(a[1]), "r"(a[2]), "r"(a[3]), "r"(b[0]), "r"(b[1]));
}

// ---------------- device scratch ----------------
__device__ float g_T[128 * 128];
__device__ float g_WkT[NC * NC];
__device__ float g_RK[128 * NC];
__device__ float g_PK[128 * NC];
__device__ float g_spart[(size_t)NB * 256 * 8192];
__device__ float g_S[NB * 8192];
__device__ float g_M[NB * NC * NC];          // transposed [co][ci]
__device__ float g_biasq[NB * NC];
__device__ float g_RQ[NB * 128 * NC];
__device__ float g_PQ[NB * 128 * NC];
__device__ __align__(16) unsigned short g_Bw[4][256][264];      // Khi,Klo,Vhi,Vlo
__device__ __align__(16) unsigned short g_Bm[NB][2][256][264];  // Mhi,Mlo

// smem maps (bytes)
#define T1_ALO 33792
#define T1_B   67584
#define T1_KS  135168
#define T1_VS  153600
#define T1_TOT 172032
#define T3_ALO 33792
#define T3_B   67584
#define T3_STG 101376
#define T3_MU  168960
#define T3_RS  169216
#define T3_TOT 169472

// ---------------- preps ----------------
__global__ void prep0_kernel(const float* __restrict__ Wk) {
    int idx = blockIdx.x * 256 + threadIdx.x;
    int co = idx >> 8, ci = idx & 255;
    g_WkT[ci * NC + co] = Wk[idx];
    if (idx < 128 * 128) {
        int p = idx >> 7, c = idx & 127, j = c >> 1;
        float dimt = powf(10000.0f, (float)j * (1.0f / 64.0f));
        float t = (float)(p + 1) * (6.283185307179586f / (128.0f + 1e-6f)) / dimt;
        g_T[idx] = (c & 1) ? cosf(t) : sinf(t);
    }
}

__global__ void prepw_kernel(const float* __restrict__ Wk, const float* __restrict__ Wv) {
    const float* W = blockIdx.x ? Wv : Wk;
    int hp = blockIdx.x * 2;
    for (int it = 0; it < 32; it++) {
        int pack = it * 256 + threadIdx.x;
        int row = pack >> 5, ci0 = (pack & 31) * 8;
        unsigned short hi[8], lo[8];
#pragma unroll
        for (int j = 0; j < 8; j++) {
            float v = W[row * NC + ci0 + j];
            hi[j] = bfu(v);
            lo[j] = bfu(v - bf2f(hi[j]));
        }
        *(uint4*)&g_Bw[hp][row][ci0] = *(uint4*)hi;
        *(uint4*)&g_Bw[hp + 1][row][ci0] = *(uint4*)lo;
    }
}

__global__ void prep1_kernel() {
    int table = blockIdx.x >> 3, chunk = blockIdx.x & 7;
    int n = chunk * 32 + (threadIdx.x & 31);
    int yg = threadIdx.x >> 5;
    float acc[16];
#pragma unroll
    for (int i = 0; i < 16; i++) acc[i] = 0.f;
    const float* W = g_WkT + (table ? 128 * NC : 0);
#pragma unroll 4
    for (int c = 0; c < 128; c++) {
        float w = W[c * NC + n];
#pragma unroll
        for (int yy = 0; yy < 16; yy++) acc[yy] += g_T[(yg * 16 + yy) * 128 + c] * w;
    }
    float* dst = table ? g_PK : g_RK;
#pragma unroll
    for (int yy = 0; yy < 16; yy++) dst[(yg * 16 + yy) * NC + n] = acc[yy];
}

// x[ci][tok] -> A[tok 64][ci 256 pad 264] bf16 hi/lo
__device__ __forceinline__ void load_x_tile(char* smem, const float* __restrict__ xb, int tid) {
    int tok = tid & 63, cig = tid >> 6;
#pragma unroll 1
    for (int p = 0; p < 8; p++) {
        int ci0 = (cig + p * 4) * 8;
        unsigned short hi[8], lo[8];
#pragma unroll
        for (int j = 0; j < 8; j++) {
            float v = xb[(size_t)(ci0 + j) * NTOK + tok];
            hi[j] = bfu(v);
            lo[j] = bfu(v - bf2f(hi[j]));
        }
        *(uint4*)(smem + tok * 528 + ci0 * 2) = *(uint4*)hi;
        *(uint4*)(smem + T1_ALO + tok * 528 + ci0 * 2) = *(uint4*)lo;
    }
}

// ---------------- T1: HMMA K/V proj + LN + tf32 scores ----------------
__global__ void __launch_bounds__(256, 1) t1_kernel(
    const float* __restrict__ x,
    const float* __restrict__ bk, const float* __restrict__ bv,
    const float* __restrict__ gK, const float* __restrict__ bKp,
    const float* __restrict__ gV, const float* __restrict__ bVp)
{
    extern __shared__ char smem[];
    const int tid = threadIdx.x, w = tid >> 5, lane = tid & 31;
    const int blk = blockIdx.x, b = blockIdx.y;
    const int n0 = blk * 64, y = n0 >> 7, x0 = n0 & 127;
    uint32_t sb = s2u(smem);
    float* Ksm = (float*)(smem + T1_KS);
    float* Vsm = (float*)(smem + T1_VS);

    load_x_tile(smem, x + ((size_t)b * NC) * NTOK + n0, tid);

    const int mt = w & 3, ch = w >> 2;
    const int arow = mt * 16 + (lane & 15);
    const int acol2 = (lane & 16) ? 16 : 0;
    const int blrow = (lane & 7) + ((lane & 16) ? 8 : 0);
    const int blcol2 = (lane & 8) ? 16 : 0;

#pragma unroll 1
    for (int nc = 0; nc < 4; nc++) {
        float accK[4][4], accV[4][4];
#pragma unroll
        for (int t = 0; t < 4; t++)
#pragma unroll
            for (int j = 0; j < 4; j++) { accK[t][j] = 0.f; accV[t][j] = 0.f; }

#pragma unroll 1
        for (int plane = 0; plane < 2; plane++) {
            __syncthreads();
            {
                const uint4* sK = (const uint4*)&g_Bw[plane][nc * 64][0];
                const uint4* sV = (const uint4*)&g_Bw[2 + plane][nc * 64][0];
                uint4* d0 = (uint4*)(smem + T1_B);
                uint4* d1 = (uint4*)(smem + T1_B + 33792);
                for (int i = tid; i < 2112; i += 256) { d0[i] = sK[i]; d1[i] = sV[i]; }
            }
            __syncthreads();
            int npass = plane ? 1 : 2;
#pragma unroll 1
            for (int ps = 0; ps < npass; ps++) {
                uint32_t aA = sb + ((plane == 0 && ps == 1) ? T1_ALO : 0) + arow * 528 + acol2;
#pragma unroll 4
                for (int k = 0; k < 16; k++) {
                    uint32_t a[4];
                    ldm_x4(a, aA + k * 32);
#pragma unroll
                    for (int q = 0; q < 2; q++) {
                        uint32_t bb[4];
                        int nb0 = ch * 32 + q * 16;
                        ldm_x4(bb, sb + T1_B + (nb0 + blrow) * 528 + k * 32 + blcol2);
                        mma_bf16(accK[q * 2], a, bb);
                        mma_bf16(accK[q * 2 + 1], a, bb + 2);
                    }
#pragma unroll
                    for (int q = 0; q < 2; q++) {
                        uint32_t bb[4];
                        int nb0 = ch * 32 + q * 16;
                        ldm_x4(bb, sb + T1_B + 33792 + (nb0 + blrow) * 528 + k * 32 + blcol2);
                        mma_bf16(accV[q * 2], a, bb);
                        mma_bf16(accV[q * 2 + 1], a, bb + 2);
                    }
                }
            }
        }

        // epilogue: c-frag -> +pos+bias -> Ksm/Vsm
        {
            int r0 = mt * 16 + (lane >> 2), cq = (lane & 3) * 2;
#pragma unroll
            for (int t = 0; t < 4; t++) {
                int lc = ch * 32 + t * 8 + cq;
                int co = nc * 64 + lc;
                float2 rk = *(const float2*)&g_RK[y * NC + co];
                float2 bk2 = *(const float2*)&bk[co];
                float2 bv2 = *(const float2*)&bv[co];
                float2 pa = *(const float2*)&g_PK[(x0 + r0) * NC + co];
                float2 pb = *(const float2*)&g_PK[(x0 + r0 + 8) * NC + co];
                float2 o;
                o.x = accK[t][0] + rk.x + pa.x + bk2.x;
                o.y = accK[t][1] + rk.y + pa.y + bk2.y;
                *(float2*)&Ksm[r0 * 72 + lc] = o;
                o.x = accK[t][2] + rk.x + pb.x + bk2.x;
                o.y = accK[t][3] + rk.y + pb.y + bk2.y;
                *(float2*)&Ksm[(r0 + 8) * 72 + lc] = o;
                o.x = accV[t][0] + bv2.x; o.y = accV[t][1] + bv2.y;
                *(float2*)&Vsm[r0 * 72 + lc] = o;
                o.x = accV[t][2] + bv2.x; o.y = accV[t][3] + bv2.y;
                *(float2*)&Vsm[(r0 + 8) * 72 + lc] = o;
            }
        }
        __syncthreads();

        // per-head LN in place
        if (tid < 128) {
            int tok = tid & 63, hl = tid >> 6;
            int head = nc * 2 + hl;
            float* kp = &Ksm[tok * 72 + hl * 32];
            float* vp = &Vsm[tok * 72 + hl * 32];
            const float4* gk4 = (const float4*)(gK + head * 32);
            const float4* bkk = (const float4*)(bKp + head * 32);
            const float4* gv4 = (const float4*)(gV + head * 32);
            const float4* bvv = (const float4*)(bVp + head * 32);
            float4 r[8]; float s = 0.f, s2 = 0.f;
#pragma unroll
            for (int jj = 0; jj < 8; jj++) {
                r[jj] = ((const float4*)kp)[jj];
                s += r[jj].x + r[jj].y + r[jj].z + r[jj].w;
                s2 += r[jj].x * r[jj].x + r[jj].y * r[jj].y + r[jj].z * r[jj].z + r[jj].w * r[jj].w;
            }
            float mu = s * (1.f / 32.f);
            float rstd = rsqrtf(s2 * (1.f / 32.f) - mu * mu + 1e-5f);
#pragma unroll
            for (int jj = 0; jj < 8; jj++) {
                float4 g = gk4[jj], be = bkk[jj], o;
                o.x = (r[jj].x - mu) * rstd * g.x + be.x;
                o.y = (r[jj].y - mu) * rstd * g.y + be.y;
                o.z = (r[jj].z - mu) * rstd * g.z + be.z;
                o.w = (r[jj].w - mu) * rstd * g.w + be.w;
                ((float4*)kp)[jj] = o;
            }
            s = 0.f; s2 = 0.f;
#pragma unroll
            for (int jj = 0; jj < 8; jj++) {
                r[jj] = ((const float4*)vp)[jj];
                s += r[jj].x + r[jj].y + r[jj].z + r[jj].w;
                s2 += r[jj].x * r[jj].x + r[jj].y * r[jj].y + r[jj].z * r[jj].z + r[jj].w * r[jj].w;
            }
            mu = s * (1.f / 32.f);
            rstd = rsqrtf(s2 * (1.f / 32.f) - mu * mu + 1e-5f);
#pragma unroll
            for (int jj = 0; jj < 8; jj++) {
                float4 g = gv4[jj], be = bvv[jj], o;
                o.x = (r[jj].x - mu) * rstd * g.x + be.x;
                o.y = (r[jj].y - mu) * rstd * g.y + be.y;
                o.z = (r[jj].z - mu) * rstd * g.z + be.z;
                o.w = (r[jj].w - mu) * rstd * g.w + be.w;
                ((float4*)vp)[jj] = o;
            }
        }
        __syncthreads();

        // scores: S_h += K^T V via tf32 mma (k = 64 tokens)
        {
            int hl = w >> 2, v = w & 3, smt = v & 1, np = v >> 1;
            int dcol = hl * 32 + smt * 16 + (lane >> 2);
            float sc[2][4];
#pragma unroll
            for (int t = 0; t < 2; t++)
#pragma unroll
                for (int j = 0; j < 4; j++) sc[t][j] = 0.f;
#pragma unroll 2
            for (int k0 = 0; k0 < 64; k0 += 8) {
                int trow = k0 + (lane & 3);
                uint32_t a[4];
                a[0] = f2tf(Ksm[trow * 72 + dcol]);
                a[1] = f2tf(Ksm[trow * 72 + dcol + 8]);
                a[2] = f2tf(Ksm[(trow + 4) * 72 + dcol]);
                a[3] = f2tf(Ksm[(trow + 4) * 72 + dcol + 8]);
#pragma unroll
                for (int t = 0; t < 2; t++) {
                    int ecol = hl * 32 + np * 16 + t * 8 + (lane >> 2);
                    uint32_t bb[2];
                    bb[0] = f2tf(Vsm[trow * 72 + ecol]);
                    bb[1] = f2tf(Vsm[(trow + 4) * 72 + ecol]);
                    mma_tf32(sc[t], a, bb);
                }
            }
            int head = nc * 2 + hl;
            float* dst = g_spart + ((size_t)(b * 256 + blk)) * 8192 + head * 1024;
            int d0 = smt * 16 + (lane >> 2);
#pragma unroll
            for (int t = 0; t < 2; t++) {
                int e0 = np * 16 + t * 8 + (lane & 3) * 2;
                dst[d0 * 32 + e0] = sc[t][0];
                dst[d0 * 32 + e0 + 1] = sc[t][1];
                dst[(d0 + 8) * 32 + e0] = sc[t][2];
                dst[(d0 + 8) * 32 + e0 + 1] = sc[t][3];
            }
        }
    }
}

// ---------------- k2 chain ----------------
__global__ void k2_reduce() {
    int b = blockIdx.x >> 5, seg = blockIdx.x & 31;
    int base = seg * 256 + threadIdx.x;
    float s = 0.f;
#pragma unroll 8
    for (int rb = 0; rb < 256; rb++) s += g_spart[((size_t)(b * 256 + rb)) * 8192 + base];
    g_S[b * 8192 + base] = s * (1.0f / 16384.0f);
}

__global__ void k2b_buildM(const float* __restrict__ Wq, const float* __restrict__ bq) {
    __shared__ float Wqs[256 * 33];
    int chunk = blockIdx.x, b = blockIdx.y;
    int co = threadIdx.x, h = co >> 5, e = co & 31;
    for (int idx = threadIdx.x; idx < 8192; idx += 256) {
        int row = idx >> 5, cil = idx & 31;
        Wqs[row * 33 + cil] = Wq[row * NC + chunk * 32 + cil];
    }
    float Scol[32];
#pragma unroll
    for (int d = 0; d < 32; d++) Scol[d] = g_S[b * 8192 + h * 1024 + d * 32 + e];
    __syncthreads();
    for (int cil = 0; cil < 32; cil++) {
        float m = 0.f;
#pragma unroll
        for (int d = 0; d < 32; d++) m += Wqs[(h * 32 + d) * 33 + cil] * Scol[d];
        g_M[(size_t)b * 65536 + (size_t)co * NC + chunk * 32 + cil] = m;
    }
    if (chunk == 0) {
        float bb = 0.f;
#pragma unroll
        for (int d = 0; d < 32; d++) bb += bq[h * 32 + d] * Scol[d];
        g_biasq[b * NC + co] = bb;
    }
}

__global__ void k2m_conv() {
    int rg = blockIdx.x, b = blockIdx.y;
    for (int it = 0; it < 4; it++) {
        int pack = it * 256 + threadIdx.x;
        int row = rg * 32 + (pack >> 5), ci0 = (pack & 31) * 8;
        unsigned short hi[8], lo[8];
#pragma unroll
        for (int j = 0; j < 8; j++) {
            float v = g_M[(size_t)b * 65536 + (size_t)row * NC + ci0 + j];
            hi[j] = bfu(v);
            lo[j] = bfu(v - bf2f(hi[j]));
        }
        *(uint4*)&g_Bm[b][0][row][ci0] = *(uint4*)hi;
        *(uint4*)&g_Bm[b][1][row][ci0] = *(uint4*)lo;
    }
}

__global__ void k2c_rqpq() {
    __shared__ float Ts[128];
    int p = blockIdx.x, b = blockIdx.y;
    int co = threadIdx.x;
    if (co < 128) Ts[co] = g_T[p * 128 + co];
    __syncthreads();
    const float4* Mr = (const float4*)(g_M + (size_t)b * 65536 + (size_t)co * NC);
    float accR = 0.f, accP = 0.f;
#pragma unroll 8
    for (int c4 = 0; c4 < 32; c4++) {
        float4 m0 = Mr[c4], m1 = Mr[32 + c4];
        float4 t4 = *(const float4*)&Ts[c4 * 4];
        accR += t4.x * m0.x + t4.y * m0.y + t4.z * m0.z + t4.w * m0.w;
        accP += t4.x * m1.x + t4.y * m1.y + t4.z * m1.z + t4.w * m1.w;
    }
    g_RQ[(b * 128 + p) * NC + co] = accR;
    g_PQ[(b * 128 + p) * NC + co] = accP;
}

// ---------------- T3: HMMA out GEMM + x2 + LN + transposed store ----------------
__global__ void __launch_bounds__(256, 1) t3_kernel(
    const float* __restrict__ x,
    const float* __restrict__ g_ln, const float* __restrict__ b_ln,
    float* __restrict__ out)
{
    extern __shared__ char smem[];
    const int tid = threadIdx.x, w = tid >> 5, lane = tid & 31;
    const int blk = blockIdx.x, b = blockIdx.y;
    const int n0 = blk * 64, y = n0 >> 7, x0 = n0 & 127;
    uint32_t sb = s2u(smem);
    float* stg = (float*)(smem + T3_STG);
    float* mus = (float*)(smem + T3_MU);
    float* rss = (float*)(smem + T3_RS);

    load_x_tile(smem, x + ((size_t)b * NC) * NTOK + n0, tid);

    const int mt = w & 3, ch = w >> 2;
    const int arow = mt * 16 + (lane & 15);
    const int acol2 = (lane & 16) ? 16 : 0;
    const int blrow = (lane & 7) + ((lane & 16) ? 8 : 0);
    const int blcol2 = (lane & 8) ? 16 : 0;

#pragma unroll 1
    for (int nc = 0; nc < 4; nc++) {
        float acc[4][4];
#pragma unroll
        for (int t = 0; t < 4; t++)
#pragma unroll
            for (int j = 0; j < 4; j++) acc[t][j] = 0.f;

#pragma unroll 1
        for (int plane = 0; plane < 2; plane++) {
            __syncthreads();
            {
                const uint4* src = (const uint4*)&g_Bm[b][plane][nc * 64][0];
                uint4* d0 = (uint4*)(smem + T3_B);
                for (int i = tid; i < 2112; i += 256) d0[i] = src[i];
            }
            __syncthreads();
            int npass = plane ? 1 : 2;
#pragma unroll 1
            for (int ps = 0; ps < npass; ps++) {
                uint32_t aA = sb + ((plane == 0 && ps == 1) ? T3_ALO : 0) + arow * 528 + acol2;
#pragma unroll 4
                for (int k = 0; k < 16; k++) {
                    uint32_t a[4];
                    ldm_x4(a, aA + k * 32);
#pragma unroll
                    for (int q = 0; q < 2; q++) {
                        uint32_t bb[4];
                        int nb0 = ch * 32 + q * 16;
                        ldm_x4(bb, sb + T3_B + (nb0 + blrow) * 528 + k * 32 + blcol2);
                        mma_bf16(acc[q * 2], a, bb);
                        mma_bf16(acc[q * 2 + 1], a, bb + 2);
                    }
                }
            }
        }
        // stage with +RQ+PQ+biasq, x2
        {
            int r0 = mt * 16 + (lane >> 2), cq = (lane & 3) * 2;
#pragma unroll
            for (int t = 0; t < 4; t++) {
                int co = nc * 64 + ch * 32 + t * 8 + cq;
                float2 rq = *(const float2*)&g_RQ[(b * 128 + y) * NC + co];
                float2 qb = *(const float2*)&g_biasq[b * NC + co];
                float2 pa = *(const float2*)&g_PQ[(b * 128 + x0 + r0) * NC + co];
                float2 pb = *(const float2*)&g_PQ[(b * 128 + x0 + r0 + 8) * NC + co];
                stg[r0 * 264 + co] = 2.f * (acc[t][0] + rq.x + qb.x + pa.x);
                stg[r0 * 264 + co + 1] = 2.f * (acc[t][1] + rq.y + qb.y + pa.y);
                stg[(r0 + 8) * 264 + co] = 2.f * (acc[t][2] + rq.x + qb.x + pb.x);
                stg[(r0 + 8) * 264 + co + 1] = 2.f * (acc[t][3] + rq.y + qb.y + pb.y);
            }
        }
    }
    __syncthreads();

    // LN stats: 4 threads per token
    {
        int token = tid >> 2, q = tid & 3;
        float s = 0.f, s2 = 0.f;
#pragma unroll
        for (int jj = 0; jj < 16; jj++) {
            float4 v = *(const float4*)&stg[token * 264 + q * 64 + jj * 4];
            s += v.x + v.y + v.z + v.w;
            s2 += v.x * v.x + v.y * v.y + v.z * v.z + v.w * v.w;
        }
#pragma unroll
        for (int off = 1; off < 4; off <<= 1) {
            s += __shfl_xor_sync(0xffffffffu, s, off);
            s2 += __shfl_xor_sync(0xffffffffu, s2, off);
        }
        if (q == 0) {
            float mu = s * (1.f / 256.f);
            mus[token] = mu;
            rss[token] = rsqrtf(s2 * (1.f / 256.f) - mu * mu + 1e-5f);
        }
    }
    __syncthreads();

    // normalize + transposed coalesced store
    {
        int t = tid & 63, cg = tid >> 6;
        float mu = mus[t], rs = rss[t];
        size_t obase = ((size_t)b * NC) * NTOK + n0 + t;
#pragma unroll 4
        for (int p = 0; p < 64; p++) {
            int co = cg * 64 + p;
            out[obase + (size_t)co * NTOK] = (stg[t * 264 + co] - mu) * rs * g_ln[co] + b_ln[co];
        }
    }
}

// ---------------- launch ----------------
extern "C" void kernel_launch(void* const* d_in, const int* in_sizes, int n_in,
                              void* d_out, int out_size) {
    const float* x    = (const float*)d_in[0];
    const float* Wq   = (const float*)d_in[1];
    const float* bq   = (const float*)d_in[2];
    const float* Wk   = (const float*)d_in[3];
    const float* bk   = (const float*)d_in[4];
    const float* Wv   = (const float*)d_in[5];
    const float* bv   = (const float*)d_in[6];
    const float* gK   = (const float*)d_in[7];
    const float* bK   = (const float*)d_in[8];
    const float* gV   = (const float*)d_in[9];
    const float* bV   = (const float*)d_in[10];
    const float* g_ln = (const float*)d_in[11];
    const float* b_ln = (const float*)d_in[12];
    float* out = (float*)d_out;

    cudaFuncSetAttribute(t1_kernel, cudaFuncAttributeMaxDynamicSharedMemorySize, T1_TOT);
    cudaFuncSetAttribute(t3_kernel, cudaFuncAttributeMaxDynamicSharedMemorySize, T3_TOT);

    prep0_kernel<<<256, 256>>>(Wk);
    prepw_kernel<<<2, 256>>>(Wk, Wv);
    prep1_kernel<<<16, 256>>>();
    t1_kernel<<<dim3(256, 8), 256, T1_TOT>>>(x, bk, bv, gK, bK, gV, bV);
    k2_reduce<<<256, 256>>>();
    k2b_buildM<<<dim3(8, 8), 256>>>(Wq, bq);
    k2m_conv<<<dim3(8, 8), 256>>>();
    k2c_rqpq<<<dim3(128, 8), 256>>>();
    t3_kernel<<<dim3(256, 8), 256, T3_TOT>>>(x, g_ln, b_ln, out);
}

// round 7
// speedup vs baseline: 1.3596x; 1.0914x over previous
#include <cuda_runtime.h>
#include <cuda_bf16.h>
#include <math.h>
#include <stdint.h>

#define NB 8
#define NC 256
#define NTOK 16384

__device__ __forceinline__ uint32_t s2u(const void* p) {
    uint32_t a;
    asm("{ .reg .u64 t; cvta.to.shared.u64 t, %1; cvt.u32.u64 %0, t; }" : "=r"(a) : "l"(p));
    return a;
}
__device__ __forceinline__ unsigned short bfu(float v) {
    __nv_bfloat16 h = __float2bfloat16(v);
    return *(unsigned short*)&h;
}
__device__ __forceinline__ float bf2f(unsigned short u) {
    __nv_bfloat16 h = *(__nv_bfloat16*)&u;
    return __bfloat162float(h);
}
__device__ __forceinline__ uint32_t f2tf(float f) {
    uint32_t r; asm("cvt.rna.tf32.f32 %0, %1;" : "=r"(r) : "f"(f)); return r;
}
__device__ __forceinline__ void ldm_x4(uint32_t r[4], uint32_t addr) {
    asm volatile("ldmatrix.sync.aligned.m8n8.x4.shared.b16 {%0,%1,%2,%3}, [%4];"
        : "=r"(r[0]), "=r"(r[1]), "=r"(r[2]), "=r"(r[3]) : "r"(addr));
}
__device__ __forceinline__ void mma_bf16(float c[4], const uint32_t a[4], const uint32_t b[2]) {
    asm volatile("mma.sync.aligned.m16n8k16.row.col.f32.bf16.bf16.f32 "
        "{%0,%1,%2,%3}, {%4,%5,%6,%7}, {%8,%9}, {%0,%1,%2,%3};"
        : "+f"(c[0]), "+f"(c[1]), "+f"(c[2]), "+f"(c[3])
        : "r"(a[0]), "r"(a[1]), "r"(a[2]), "r"(a[3]), "r"(b[0]), "r"(b[1]));
}
__device__ __forceinline__ void mma_tf32(float c[4], const uint32_t a[4], const uint32_t b[2]) {
    asm volatile("mma.sync.aligned.m16n8k8.row.col.f32.tf32.tf32.f32 "
        "{%0,%1,%2,%3}, {%4,%5,%6,%7}, {%8,%9}, {%0,%1,%2,%3};"
        : "+f"(c[0]), "+f"(c[1]), "+f"(c[2]), "+f"(c[3])
        : "r"(a[0]), "r"(a[1]), "r"(a[2]), "r"(a[3]), "r"(b[0]), "r"(b[1]));
}

// ---------------- device scratch ----------------
__device__ float g_T[128 * 128];
__device__ float g_WkT[NC * NC];
__device__ float g_RK[128 * NC];
__device__ float g_PK[128 * NC];
__device__ float g_spart[(size_t)NB * 256 * 8192];
__device__ float g_S[NB * 8192];
__device__ float g_M[NB * NC * NC];          // transposed [co][ci]
__device__ float g_biasq[NB * NC];
__device__ float g_RQ[NB * 128 * NC];
__device__ float g_PQ[NB * 128 * NC];
__device__ __align__(16) unsigned short g_Bw[4][256][264];      // Khi,Klo,Vhi,Vlo
__device__ __align__(16) unsigned short g_Bm[NB][2][256][264];  // Mhi,Mlo

// smem maps (bytes)
#define T1_ALO 33792
#define T1_B   67584
#define T1_KS  135168
#define T1_VS  153600
#define T1_TOT 172032
#define T3_ALO 33792
#define T3_B   67584
#define T3_STG 135168
#define T3_MU  202752
#define T3_RS  203008
#define T3_TOT 203264

// ---------------- preps ----------------
__global__ void prep0_kernel(const float* __restrict__ Wk) {
    int idx = blockIdx.x * 256 + threadIdx.x;
    int co = idx >> 8, ci = idx & 255;
    g_WkT[ci * NC + co] = Wk[idx];
    if (idx < 128 * 128) {
        int p = idx >> 7, c = idx & 127, j = c >> 1;
        float dimt = powf(10000.0f, (float)j * (1.0f / 64.0f));
        float t = (float)(p + 1) * (6.283185307179586f / (128.0f + 1e-6f)) / dimt;
        g_T[idx] = (c & 1) ? cosf(t) : sinf(t);
    }
}

__global__ void prepw_kernel(const float* __restrict__ Wk, const float* __restrict__ Wv) {
    const float* W = blockIdx.x ? Wv : Wk;
    int hp = blockIdx.x * 2;
    for (int it = 0; it < 32; it++) {
        int pack = it * 256 + threadIdx.x;
        int row = pack >> 5, ci0 = (pack & 31) * 8;
        unsigned short hi[8], lo[8];
#pragma unroll
        for (int j = 0; j < 8; j++) {
            float v = W[row * NC + ci0 + j];
            hi[j] = bfu(v);
            lo[j] = bfu(v - bf2f(hi[j]));
        }
        *(uint4*)&g_Bw[hp][row][ci0] = *(uint4*)hi;
        *(uint4*)&g_Bw[hp + 1][row][ci0] = *(uint4*)lo;
    }
}

__global__ void prep1_kernel() {
    int table = blockIdx.x >> 3, chunk = blockIdx.x & 7;
    int n = chunk * 32 + (threadIdx.x & 31);
    int yg = threadIdx.x >> 5;
    float acc[16];
#pragma unroll
    for (int i = 0; i < 16; i++) acc[i] = 0.f;
    const float* W = g_WkT + (table ? 128 * NC : 0);
#pragma unroll 4
    for (int c = 0; c < 128; c++) {
        float w = W[c * NC + n];
#pragma unroll
        for (int yy = 0; yy < 16; yy++) acc[yy] += g_T[(yg * 16 + yy) * 128 + c] * w;
    }
    float* dst = table ? g_PK : g_RK;
#pragma unroll
    for (int yy = 0; yy < 16; yy++) dst[(yg * 16 + yy) * NC + n] = acc[yy];
}

// x[ci][tok] -> A[tok 64][ci 256 pad 264] bf16 hi/lo
__device__ __forceinline__ void load_x_tile(char* smem, const float* __restrict__ xb, int tid) {
    int tok = tid & 63, cig = tid >> 6;
#pragma unroll 1
    for (int p = 0; p < 8; p++) {
        int ci0 = (cig + p * 4) * 8;
        unsigned short hi[8], lo[8];
#pragma unroll
        for (int j = 0; j < 8; j++) {
            float v = xb[(size_t)(ci0 + j) * NTOK + tok];
            hi[j] = bfu(v);
            lo[j] = bfu(v - bf2f(hi[j]));
        }
        *(uint4*)(smem + tok * 528 + ci0 * 2) = *(uint4*)hi;
        *(uint4*)(smem + T1_ALO + tok * 528 + ci0 * 2) = *(uint4*)lo;
    }
}

// ---------------- T1: HMMA K/V proj + LN + tf32 scores ----------------
__global__ void __launch_bounds__(256, 1) t1_kernel(
    const float* __restrict__ x,
    const float* __restrict__ bk, const float* __restrict__ bv,
    const float* __restrict__ gK, const float* __restrict__ bKp,
    const float* __restrict__ gV, const float* __restrict__ bVp)
{
    extern __shared__ char smem[];
    const int tid = threadIdx.x, w = tid >> 5, lane = tid & 31;
    const int blk = blockIdx.x, b = blockIdx.y;
    const int n0 = blk * 64, y = n0 >> 7, x0 = n0 & 127;
    uint32_t sb = s2u(smem);
    float* Ksm = (float*)(smem + T1_KS);
    float* Vsm = (float*)(smem + T1_VS);

    load_x_tile(smem, x + ((size_t)b * NC) * NTOK + n0, tid);

    // warp roles: op (K/V) x m32 tile x n32 chunk
    const int op = w >> 2, mt = (w >> 1) & 1, ch = w & 1;
    const int acol2 = (lane & 16) ? 16 : 0;
    const int blrow = (lane & 7) + ((lane & 16) ? 8 : 0);
    const int blcol2 = (lane & 8) ? 16 : 0;
    const uint32_t aH0 = sb + (mt * 32 + (lane & 15)) * 528 + acol2;
    const uint32_t aL0 = aH0 + T1_ALO;
    const uint32_t bB0 = sb + T1_B + op * 33792 + (ch * 32 + blrow) * 528 + blcol2;

#pragma unroll 1
    for (int nc = 0; nc < 4; nc++) {
        float acc[2][4][4];
#pragma unroll
        for (int t = 0; t < 2; t++)
#pragma unroll
            for (int f = 0; f < 4; f++)
#pragma unroll
                for (int j = 0; j < 4; j++) acc[t][f][j] = 0.f;

#pragma unroll 1
        for (int plane = 0; plane < 2; plane++) {
            __syncthreads();
            {
                const uint4* sK = (const uint4*)&g_Bw[plane][nc * 64][0];
                const uint4* sV = (const uint4*)&g_Bw[2 + plane][nc * 64][0];
                uint4* d0 = (uint4*)(smem + T1_B);
                uint4* d1 = (uint4*)(smem + T1_B + 33792);
                for (int i = tid; i < 2112; i += 256) { d0[i] = sK[i]; d1[i] = sV[i]; }
            }
            __syncthreads();
            if (plane == 0) {
#pragma unroll 2
                for (int k = 0; k < 16; k++) {
                    uint32_t ah0[4], ah1[4], al0[4], al1[4];
                    ldm_x4(ah0, aH0 + k * 32);
                    ldm_x4(ah1, aH0 + 16 * 528 + k * 32);
                    ldm_x4(al0, aL0 + k * 32);
                    ldm_x4(al1, aL0 + 16 * 528 + k * 32);
#pragma unroll
                    for (int q = 0; q < 2; q++) {
                        uint32_t bb[4];
                        ldm_x4(bb, bB0 + q * 16 * 528 + k * 32);
                        mma_bf16(acc[0][q * 2], ah0, bb);
                        mma_bf16(acc[0][q * 2 + 1], ah0, bb + 2);
                        mma_bf16(acc[1][q * 2], ah1, bb);
                        mma_bf16(acc[1][q * 2 + 1], ah1, bb + 2);
                        mma_bf16(acc[0][q * 2], al0, bb);
                        mma_bf16(acc[0][q * 2 + 1], al0, bb + 2);
                        mma_bf16(acc[1][q * 2], al1, bb);
                        mma_bf16(acc[1][q * 2 + 1], al1, bb + 2);
                    }
                }
            } else {
#pragma unroll 2
                for (int k = 0; k < 16; k++) {
                    uint32_t ah0[4], ah1[4];
                    ldm_x4(ah0, aH0 + k * 32);
                    ldm_x4(ah1, aH0 + 16 * 528 + k * 32);
#pragma unroll
                    for (int q = 0; q < 2; q++) {
                        uint32_t bb[4];
                        ldm_x4(bb, bB0 + q * 16 * 528 + k * 32);
                        mma_bf16(acc[0][q * 2], ah0, bb);
                        mma_bf16(acc[0][q * 2 + 1], ah0, bb + 2);
                        mma_bf16(acc[1][q * 2], ah1, bb);
                        mma_bf16(acc[1][q * 2 + 1], ah1, bb + 2);
                    }
                }
            }
        }

        // epilogue: frags -> (+pos,+bias) -> Ksm/Vsm
        {
            int r0 = lane >> 2, cq = (lane & 3) * 2;
            if (op == 0) {
#pragma unroll
                for (int t = 0; t < 2; t++)
#pragma unroll
                    for (int f = 0; f < 4; f++) {
                        int lc = ch * 32 + f * 8 + cq;
                        int co = nc * 64 + lc;
                        int row = mt * 32 + t * 16 + r0;
                        float2 rk = *(const float2*)&g_RK[y * NC + co];
                        float2 bk2 = *(const float2*)&bk[co];
                        float2 pa = *(const float2*)&g_PK[(x0 + row) * NC + co];
                        float2 pb = *(const float2*)&g_PK[(x0 + row + 8) * NC + co];
                        float2 o;
                        o.x = acc[t][f][0] + rk.x + pa.x + bk2.x;
                        o.y = acc[t][f][1] + rk.y + pa.y + bk2.y;
                        *(float2*)&Ksm[row * 72 + lc] = o;
                        o.x = acc[t][f][2] + rk.x + pb.x + bk2.x;
                        o.y = acc[t][f][3] + rk.y + pb.y + bk2.y;
                        *(float2*)&Ksm[(row + 8) * 72 + lc] = o;
                    }
            } else {
#pragma unroll
                for (int t = 0; t < 2; t++)
#pragma unroll
                    for (int f = 0; f < 4; f++) {
                        int lc = ch * 32 + f * 8 + cq;
                        int co = nc * 64 + lc;
                        int row = mt * 32 + t * 16 + r0;
                        float2 bv2 = *(const float2*)&bv[co];
                        float2 o;
                        o.x = acc[t][f][0] + bv2.x;
                        o.y = acc[t][f][1] + bv2.y;
                        *(float2*)&Vsm[row * 72 + lc] = o;
                        o.x = acc[t][f][2] + bv2.x;
                        o.y = acc[t][f][3] + bv2.y;
                        *(float2*)&Vsm[(row + 8) * 72 + lc] = o;
                    }
            }
        }
        __syncthreads();

        // per-head LN in place
        if (tid < 128) {
            int tok = tid & 63, hl = tid >> 6;
            int head = nc * 2 + hl;
            float* kp = &Ksm[tok * 72 + hl * 32];
            float* vp = &Vsm[tok * 72 + hl * 32];
            const float4* gk4 = (const float4*)(gK + head * 32);
            const float4* bkk = (const float4*)(bKp + head * 32);
            const float4* gv4 = (const float4*)(gV + head * 32);
            const float4* bvv = (const float4*)(bVp + head * 32);
            float4 r[8]; float s = 0.f, s2 = 0.f;
#pragma unroll
            for (int jj = 0; jj < 8; jj++) {
                r[jj] = ((const float4*)kp)[jj];
                s += r[jj].x + r[jj].y + r[jj].z + r[jj].w;
                s2 += r[jj].x * r[jj].x + r[jj].y * r[jj].y + r[jj].z * r[jj].z + r[jj].w * r[jj].w;
            }
            float mu = s * (1.f / 32.f);
            float rstd = rsqrtf(s2 * (1.f / 32.f) - mu * mu + 1e-5f);
#pragma unroll
            for (int jj = 0; jj < 8; jj++) {
                float4 g = gk4[jj], be = bkk[jj], o;
                o.x = (r[jj].x - mu) * rstd * g.x + be.x;
                o.y = (r[jj].y - mu) * rstd * g.y + be.y;
                o.z = (r[jj].z - mu) * rstd * g.z + be.z;
                o.w = (r[jj].w - mu) * rstd * g.w + be.w;
                ((float4*)kp)[jj] = o;
            }
            s = 0.f; s2 = 0.f;
#pragma unroll
            for (int jj = 0; jj < 8; jj++) {
                r[jj] = ((const float4*)vp)[jj];
                s += r[jj].x + r[jj].y + r[jj].z + r[jj].w;
                s2 += r[jj].x * r[jj].x + r[jj].y * r[jj].y + r[jj].z * r[jj].z + r[jj].w * r[jj].w;
            }
            mu = s * (1.f / 32.f);
            rstd = rsqrtf(s2 * (1.f / 32.f) - mu * mu + 1e-5f);
#pragma unroll
            for (int jj = 0; jj < 8; jj++) {
                float4 g = gv4[jj], be = bvv[jj], o;
                o.x = (r[jj].x - mu) * rstd * g.x + be.x;
                o.y = (r[jj].y - mu) * rstd * g.y + be.y;
                o.z = (r[jj].z - mu) * rstd * g.z + be.z;
                o.w = (r[jj].w - mu) * rstd * g.w + be.w;
                ((float4*)vp)[jj] = o;
            }
        }
        __syncthreads();

        // scores: S_h += K^T V via tf32 mma (k = 64 tokens)
        {
            int hl = w >> 2, v = w & 3, smt = v & 1, np = v >> 1;
            int dcol = hl * 32 + smt * 16 + (lane >> 2);
            float sc[2][4];
#pragma unroll
            for (int t = 0; t < 2; t++)
#pragma unroll
                for (int j = 0; j < 4; j++) sc[t][j] = 0.f;
#pragma unroll 2
            for (int k0 = 0; k0 < 64; k0 += 8) {
                int trow = k0 + (lane & 3);
                uint32_t a[4];
                a[0] = f2tf(Ksm[trow * 72 + dcol]);
                a[1] = f2tf(Ksm[trow * 72 + dcol + 8]);
                a[2] = f2tf(Ksm[(trow + 4) * 72 + dcol]);
                a[3] = f2tf(Ksm[(trow + 4) * 72 + dcol + 8]);
#pragma unroll
                for (int t = 0; t < 2; t++) {
                    int ecol = hl * 32 + np * 16 + t * 8 + (lane >> 2);
                    uint32_t bb[2];
                    bb[0] = f2tf(Vsm[trow * 72 + ecol]);
                    bb[1] = f2tf(Vsm[(trow + 4) * 72 + ecol]);
                    mma_tf32(sc[t], a, bb);
                }
            }
            int head = nc * 2 + hl;
            float* dst = g_spart + ((size_t)(b * 256 + blk)) * 8192 + head * 1024;
            int d0 = smt * 16 + (lane >> 2);
#pragma unroll
            for (int t = 0; t < 2; t++) {
                int e0 = np * 16 + t * 8 + (lane & 3) * 2;
                dst[d0 * 32 + e0] = sc[t][0];
                dst[d0 * 32 + e0 + 1] = sc[t][1];
                dst[(d0 + 8) * 32 + e0] = sc[t][2];
                dst[(d0 + 8) * 32 + e0 + 1] = sc[t][3];
            }
        }
    }
}

// ---------------- k2 chain ----------------
__global__ void k2_reduce() {
    int b = blockIdx.x >> 5, seg = blockIdx.x & 31;
    int base = seg * 256 + threadIdx.x;
    float s = 0.f;
#pragma unroll 8
    for (int rb = 0; rb < 256; rb++) s += g_spart[((size_t)(b * 256 + rb)) * 8192 + base];
    g_S[b * 8192 + base] = s * (1.0f / 16384.0f);
}

__global__ void k2b_buildM(const float* __restrict__ Wq, const float* __restrict__ bq) {
    __shared__ float Wqs[256 * 33];
    int chunk = blockIdx.x, b = blockIdx.y;
    int co = threadIdx.x, h = co >> 5, e = co & 31;
    for (int idx = threadIdx.x; idx < 8192; idx += 256) {
        int row = idx >> 5, cil = idx & 31;
        Wqs[row * 33 + cil] = Wq[row * NC + chunk * 32 + cil];
    }
    float Scol[32];
#pragma unroll
    for (int d = 0; d < 32; d++) Scol[d] = g_S[b * 8192 + h * 1024 + d * 32 + e];
    __syncthreads();
    for (int cil = 0; cil < 32; cil++) {
        float m = 0.f;
#pragma unroll
        for (int d = 0; d < 32; d++) m += Wqs[(h * 32 + d) * 33 + cil] * Scol[d];
        g_M[(size_t)b * 65536 + (size_t)co * NC + chunk * 32 + cil] = m;
    }
    if (chunk == 0) {
        float bb = 0.f;
#pragma unroll
        for (int d = 0; d < 32; d++) bb += bq[h * 32 + d] * Scol[d];
        g_biasq[b * NC + co] = bb;
    }
}

__global__ void k2m_conv() {
    int rg = blockIdx.x, b = blockIdx.y;
    for (int it = 0; it < 4; it++) {
        int pack = it * 256 + threadIdx.x;
        int row = rg * 32 + (pack >> 5), ci0 = (pack & 31) * 8;
        unsigned short hi[8], lo[8];
#pragma unroll
        for (int j = 0; j < 8; j++) {
            float v = g_M[(size_t)b * 65536 + (size_t)row * NC + ci0 + j];
            hi[j] = bfu(v);
            lo[j] = bfu(v - bf2f(hi[j]));
        }
        *(uint4*)&g_Bm[b][0][row][ci0] = *(uint4*)hi;
        *(uint4*)&g_Bm[b][1][row][ci0] = *(uint4*)lo;
    }
}

__global__ void k2c_rqpq() {
    __shared__ float Ts[128];
    int p = blockIdx.x, b = blockIdx.y;
    int co = threadIdx.x;
    if (co < 128) Ts[co] = g_T[p * 128 + co];
    __syncthreads();
    const float4* Mr = (const float4*)(g_M + (size_t)b * 65536 + (size_t)co * NC);
    float accR = 0.f, accP = 0.f;
#pragma unroll 8
    for (int c4 = 0; c4 < 32; c4++) {
        float4 m0 = Mr[c4], m1 = Mr[32 + c4];
        float4 t4 = *(const float4*)&Ts[c4 * 4];
        accR += t4.x * m0.x + t4.y * m0.y + t4.z * m0.z + t4.w * m0.w;
        accP += t4.x * m1.x + t4.y * m1.y + t4.z * m1.z + t4.w * m1.w;
    }
    g_RQ[(b * 128 + p) * NC + co] = accR;
    g_PQ[(b * 128 + p) * NC + co] = accP;
}

// ---------------- T3: HMMA out GEMM + x2 + LN + transposed store ----------------
__global__ void __launch_bounds__(256, 1) t3_kernel(
    const float* __restrict__ x,
    const float* __restrict__ g_ln, const float* __restrict__ b_ln,
    float* __restrict__ out)
{
    extern __shared__ char smem[];
    const int tid = threadIdx.x, w = tid >> 5, lane = tid & 31;
    const int blk = blockIdx.x, b = blockIdx.y;
    const int n0 = blk * 64, y = n0 >> 7, x0 = n0 & 127;
    uint32_t sb = s2u(smem);
    float* stg = (float*)(smem + T3_STG);
    float* mus = (float*)(smem + T3_MU);
    float* rss = (float*)(smem + T3_RS);

    load_x_tile(smem, x + ((size_t)b * NC) * NTOK + n0, tid);

    // warp roles: nc within pair x m32 tile x n32 chunk
    const int nc2 = w >> 2, mt = (w >> 1) & 1, ch = w & 1;
    const int acol2 = (lane & 16) ? 16 : 0;
    const int blrow = (lane & 7) + ((lane & 16) ? 8 : 0);
    const int blcol2 = (lane & 8) ? 16 : 0;
    const uint32_t aH0 = sb + (mt * 32 + (lane & 15)) * 528 + acol2;
    const uint32_t aL0 = aH0 + T3_ALO;
    const uint32_t bB0 = sb + T3_B + nc2 * 33792 + (ch * 32 + blrow) * 528 + blcol2;

#pragma unroll 1
    for (int ncp = 0; ncp < 2; ncp++) {
        const int nc = ncp * 2 + nc2;
        float acc[2][4][4];
#pragma unroll
        for (int t = 0; t < 2; t++)
#pragma unroll
            for (int f = 0; f < 4; f++)
#pragma unroll
                for (int j = 0; j < 4; j++) acc[t][f][j] = 0.f;

#pragma unroll 1
        for (int plane = 0; plane < 2; plane++) {
            __syncthreads();
            {
                const uint4* src = (const uint4*)&g_Bm[b][plane][ncp * 128][0];
                uint4* d0 = (uint4*)(smem + T3_B);
                for (int i = tid; i < 4224; i += 256) d0[i] = src[i];
            }
            __syncthreads();
            if (plane == 0) {
#pragma unroll 2
                for (int k = 0; k < 16; k++) {
                    uint32_t ah0[4], ah1[4], al0[4], al1[4];
                    ldm_x4(ah0, aH0 + k * 32);
                    ldm_x4(ah1, aH0 + 16 * 528 + k * 32);
                    ldm_x4(al0, aL0 + k * 32);
                    ldm_x4(al1, aL0 + 16 * 528 + k * 32);
#pragma unroll
                    for (int q = 0; q < 2; q++) {
                        uint32_t bb[4];
                        ldm_x4(bb, bB0 + q * 16 * 528 + k * 32);
                        mma_bf16(acc[0][q * 2], ah0, bb);
                        mma_bf16(acc[0][q * 2 + 1], ah0, bb + 2);
                        mma_bf16(acc[1][q * 2], ah1, bb);
                        mma_bf16(acc[1][q * 2 + 1], ah1, bb + 2);
                        mma_bf16(acc[0][q * 2], al0, bb);
                        mma_bf16(acc[0][q * 2 + 1], al0, bb + 2);
                        mma_bf16(acc[1][q * 2], al1, bb);
                        mma_bf16(acc[1][q * 2 + 1], al1, bb + 2);
                    }
                }
            } else {
#pragma unroll 2
                for (int k = 0; k < 16; k++) {
                    uint32_t ah0[4], ah1[4];
                    ldm_x4(ah0, aH0 + k * 32);
                    ldm_x4(ah1, aH0 + 16 * 528 + k * 32);
#pragma unroll
                    for (int q = 0; q < 2; q++) {
                        uint32_t bb[4];
                        ldm_x4(bb, bB0 + q * 16 * 528 + k * 32);
                        mma_bf16(acc[0][q * 2], ah0, bb);
                        mma_bf16(acc[0][q * 2 + 1], ah0, bb + 2);
                        mma_bf16(acc[1][q * 2], ah1, bb);
                        mma_bf16(acc[1][q * 2 + 1], ah1, bb + 2);
                    }
                }
            }
        }

        // stage with +RQ+PQ+biasq, x2
        {
            int r0 = lane >> 2, cq = (lane & 3) * 2;
#pragma unroll
            for (int t = 0; t < 2; t++)
#pragma unroll
                for (int f = 0; f < 4; f++) {
                    int co = nc * 64 + ch * 32 + f * 8 + cq;
                    int row = mt * 32 + t * 16 + r0;
                    float2 rq = *(const float2*)&g_RQ[(b * 128 + y) * NC + co];
                    float2 qb = *(const float2*)&g_biasq[b * NC + co];
                    float2 pa = *(const float2*)&g_PQ[(b * 128 + x0 + row) * NC + co];
                    float2 pb = *(const float2*)&g_PQ[(b * 128 + x0 + row + 8) * NC + co];
                    stg[row * 264 + co] = 2.f * (acc[t][f][0] + rq.x + qb.x + pa.x);
                    stg[row * 264 + co + 1] = 2.f * (acc[t][f][1] + rq.y + qb.y + pa.y);
                    stg[(row + 8) * 264 + co] = 2.f * (acc[t][f][2] + rq.x + qb.x + pb.x);
                    stg[(row + 8) * 264 + co + 1] = 2.f * (acc[t][f][3] + rq.y + qb.y + pb.y);
                }
        }
    }
    __syncthreads();

    // LN stats: 4 threads per token
    {
        int token = tid >> 2, q = tid & 3;
        float s = 0.f, s2 = 0.f;
#pragma unroll
        for (int jj = 0; jj < 16; jj++) {
            float4 v = *(const float4*)&stg[token * 264 + q * 64 + jj * 4];
            s += v.x + v.y + v.z + v.w;
            s2 += v.x * v.x + v.y * v.y + v.z * v.z + v.w * v.w;
        }
#pragma unroll
        for (int off = 1; off < 4; off <<= 1) {
            s += __shfl_xor_sync(0xffffffffu, s, off);
            s2 += __shfl_xor_sync(0xffffffffu, s2, off);
        }
        if (q == 0) {
            float mu = s * (1.f / 256.f);
            mus[token] = mu;
            rss[token] = rsqrtf(s2 * (1.f / 256.f) - mu * mu + 1e-5f);
        }
    }
    __syncthreads();

    // normalize + transposed coalesced store
    {
        int t = tid & 63, cg = tid >> 6;
        float mu = mus[t], rs = rss[t];
        size_t obase = ((size_t)b * NC) * NTOK + n0 + t;
#pragma unroll 4
        for (int p = 0; p < 64; p++) {
            int co = cg * 64 + p;
            out[obase + (size_t)co * NTOK] = (stg[t * 264 + co] - mu) * rs * g_ln[co] + b_ln[co];
        }
    }
}

// ---------------- launch ----------------
extern "C" void kernel_launch(void* const* d_in, const int* in_sizes, int n_in,
                              void* d_out, int out_size) {
    const float* x    = (const float*)d_in[0];
    const float* Wq   = (const float*)d_in[1];
    const float* bq   = (const float*)d_in[2];
    const float* Wk   = (const float*)d_in[3];
    const float* bk   = (const float*)d_in[4];
    const float* Wv   = (const float*)d_in[5];
    const float* bv   = (const float*)d_in[6];
    const float* gK   = (const float*)d_in[7];
    const float* bK   = (const float*)d_in[8];
    const float* gV   = (const float*)d_in[9];
    const float* bV   = (const float*)d_in[10];
    const float* g_ln = (const float*)d_in[11];
    const float* b_ln = (const float*)d_in[12];
    float* out = (float*)d_out;

    cudaFuncSetAttribute(t1_kernel, cudaFuncAttributeMaxDynamicSharedMemorySize, T1_TOT);
    cudaFuncSetAttribute(t3_kernel, cudaFuncAttributeMaxDynamicSharedMemorySize, T3_TOT);

    prep0_kernel<<<256, 256>>>(Wk);
    prepw_kernel<<<2, 256>>>(Wk, Wv);
    prep1_kernel<<<16, 256>>>();
    t1_kernel<<<dim3(256, 8), 256, T1_TOT>>>(x, bk, bv, gK, bK, gV, bV);
    k2_reduce<<<256, 256>>>();
    k2b_buildM<<<dim3(8, 8), 256>>>(Wq, bq);
    k2m_conv<<<dim3(8, 8), 256>>>();
    k2c_rqpq<<<dim3(128, 8), 256>>>();
    t3_kernel<<<dim3(256, 8), 256, T3_TOT>>>(x, g_ln, b_ln, out);
}

// round 8
// speedup vs baseline: 1.3684x; 1.0065x over previous
#include <cuda_runtime.h>
#include <cuda_bf16.h>
#include <math.h>
#include <stdint.h>

#define NB 8
#define NC 256
#define NTOK 16384

__device__ __forceinline__ uint32_t s2u(const void* p) {
    uint32_t a;
    asm("{ .reg .u64 t; cvta.to.shared.u64 t, %1; cvt.u32.u64 %0, t; }" : "=r"(a) : "l"(p));
    return a;
}
__device__ __forceinline__ unsigned short bfu(float v) {
    __nv_bfloat16 h = __float2bfloat16(v);
    return *(unsigned short*)&h;
}
__device__ __forceinline__ float bf2f(unsigned short u) {
    __nv_bfloat16 h = *(__nv_bfloat16*)&u;
    return __bfloat162float(h);
}
__device__ __forceinline__ uint32_t f2tf(float f) {
    uint32_t r; asm("cvt.rna.tf32.f32 %0, %1;" : "=r"(r) : "f"(f)); return r;
}
__device__ __forceinline__ void ldm_x4(uint32_t r[4], uint32_t addr) {
    asm volatile("ldmatrix.sync.aligned.m8n8.x4.shared.b16 {%0,%1,%2,%3}, [%4];"
        : "=r"(r[0]), "=r"(r[1]), "=r"(r[2]), "=r"(r[3]) : "r"(addr));
}
__device__ __forceinline__ void mma_bf16(float c[4], const uint32_t a[4], const uint32_t b[2]) {
    asm volatile("mma.sync.aligned.m16n8k16.row.col.f32.bf16.bf16.f32 "
        "{%0,%1,%2,%3}, {%4,%5,%6,%7}, {%8,%9}, {%0,%1,%2,%3};"
        : "+f"(c[0]), "+f"(c[1]), "+f"(c[2]), "+f"(c[3])
        : "r"(a[0]), "r"(a[1]), "r"(a[2]), "r"(a[3]), "r"(b[0]), "r"(b[1]));
}
__device__ __forceinline__ void mma_tf32(float c[4], const uint32_t a[4], const uint32_t b[2]) {
    asm volatile("mma.sync.aligned.m16n8k8.row.col.f32.tf32.tf32.f32 "
        "{%0,%1,%2,%3}, {%4,%5,%6,%7}, {%8,%9}, {%0,%1,%2,%3};"
        : "+f"(c[0]), "+f"(c[1]), "+f"(c[2]), "+f"(c[3])
        : "r"(a[0]), "r"(a[1]), "r"(a[2]), "r"(a[3]), "r"(b[0]), "r"(b[1]));
}
__device__ __forceinline__ void cpa16(uint32_t s, const void* g) {
    asm volatile("cp.async.cg.shared.global [%0], [%1], 16;"
        :: "r"(s), "l"(__cvta_generic_to_global(g)));
}
#define CP_COMMIT() asm volatile("cp.async.commit_group;" ::: "memory")
#define CP_WAIT0() asm volatile("cp.async.wait_group 0;" ::: "memory")
#define CP_WAIT1() asm volatile("cp.async.wait_group 1;" ::: "memory")

// ---------------- device scratch ----------------
__device__ float g_T[128 * 128];
__device__ float g_WkT[NC * NC];
__device__ float g_RK[128 * NC];
__device__ float g_PK[128 * NC];
__device__ float g_K[(size_t)NB * NTOK * NC];
__device__ float g_V[(size_t)NB * NTOK * NC];
__device__ float g_spart[(size_t)NB * 256 * 8192];
__device__ float g_S[NB * 8192];
__device__ float g_M[NB * NC * NC];          // transposed [co][ci]
__device__ float g_biasq[NB * NC];
__device__ float g_RQ[NB * 128 * NC];
__device__ float g_PQ[NB * 128 * NC];
__device__ __align__(16) unsigned short g_Bw[4][256][264];      // Khi,Klo,Vhi,Vlo
__device__ __align__(16) unsigned short g_Bm[NB][2][256][264];  // Mhi,Mlo

// smem maps (bytes)
#define T1_ALO 33792
#define T1_B   67584
#define T1_TOT 202752
#define T3_ALO 33792
#define T3_B   67584
#define T3_STG 135168
#define T3_MU  202752
#define T3_RS  203008
#define T3_TOT 203264

// ---------------- preps ----------------
__global__ void prep0_kernel(const float* __restrict__ Wk) {
    int idx = blockIdx.x * 256 + threadIdx.x;
    int co = idx >> 8, ci = idx & 255;
    g_WkT[ci * NC + co] = Wk[idx];
    if (idx < 128 * 128) {
        int p = idx >> 7, c = idx & 127, j = c >> 1;
        float dimt = powf(10000.0f, (float)j * (1.0f / 64.0f));
        float t = (float)(p + 1) * (6.283185307179586f / (128.0f + 1e-6f)) / dimt;
        g_T[idx] = (c & 1) ? cosf(t) : sinf(t);
    }
}

__global__ void prepw_kernel(const float* __restrict__ Wk, const float* __restrict__ Wv) {
    const float* W = blockIdx.x ? Wv : Wk;
    int hp = blockIdx.x * 2;
    for (int it = 0; it < 32; it++) {
        int pack = it * 256 + threadIdx.x;
        int row = pack >> 5, ci0 = (pack & 31) * 8;
        unsigned short hi[8], lo[8];
#pragma unroll
        for (int j = 0; j < 8; j++) {
            float v = W[row * NC + ci0 + j];
            hi[j] = bfu(v);
            lo[j] = bfu(v - bf2f(hi[j]));
        }
        *(uint4*)&g_Bw[hp][row][ci0] = *(uint4*)hi;
        *(uint4*)&g_Bw[hp + 1][row][ci0] = *(uint4*)lo;
    }
}

__global__ void prep1_kernel() {
    int table = blockIdx.x >> 3, chunk = blockIdx.x & 7;
    int n = chunk * 32 + (threadIdx.x & 31);
    int yg = threadIdx.x >> 5;
    float acc[16];
#pragma unroll
    for (int i = 0; i < 16; i++) acc[i] = 0.f;
    const float* W = g_WkT + (table ? 128 * NC : 0);
#pragma unroll 4
    for (int c = 0; c < 128; c++) {
        float w = W[c * NC + n];
#pragma unroll
        for (int yy = 0; yy < 16; yy++) acc[yy] += g_T[(yg * 16 + yy) * 128 + c] * w;
    }
    float* dst = table ? g_PK : g_RK;
#pragma unroll
    for (int yy = 0; yy < 16; yy++) dst[(yg * 16 + yy) * NC + n] = acc[yy];
}

// x[ci][tok] -> A[tok 64][ci 256 pad 264] bf16 hi/lo
__device__ __forceinline__ void load_x_tile(char* smem, const float* __restrict__ xb, int tid) {
    int tok = tid & 63, cig = tid >> 6;
#pragma unroll 1
    for (int p = 0; p < 8; p++) {
        int ci0 = (cig + p * 4) * 8;
        unsigned short hi[8], lo[8];
#pragma unroll
        for (int j = 0; j < 8; j++) {
            float v = xb[(size_t)(ci0 + j) * NTOK + tok];
            hi[j] = bfu(v);
            lo[j] = bfu(v - bf2f(hi[j]));
        }
        *(uint4*)(smem + tok * 528 + ci0 * 2) = *(uint4*)hi;
        *(uint4*)(smem + T1_ALO + tok * 528 + ci0 * 2) = *(uint4*)lo;
    }
}

// ---------------- T1: pure HMMA K/V projection, double-buffered B ----------------
__global__ void __launch_bounds__(256, 1) t1_kernel(
    const float* __restrict__ x,
    const float* __restrict__ bk, const float* __restrict__ bv)
{
    extern __shared__ char smem[];
    const int tid = threadIdx.x, w = tid >> 5, lane = tid & 31;
    const int blk = blockIdx.x, b = blockIdx.y;
    const int n0 = blk * 64, y = n0 >> 7, x0 = n0 & 127;
    uint32_t sb = s2u(smem);

    const int op = w >> 2, mt = (w >> 1) & 1, ch = w & 1;
    const int acol2 = (lane & 16) ? 16 : 0;
    const int blrow = (lane & 7) + ((lane & 16) ? 8 : 0);
    const int blcol2 = (lane & 8) ? 16 : 0;
    const uint32_t aH0 = sb + (mt * 32 + (lane & 15)) * 528 + acol2;
    const uint32_t aL0 = aH0 + T1_ALO;

    // prefetch s=0 (plane0 of nc 0, K+V)
    {
        uint32_t dst = sb + T1_B;
        for (int i = tid; i < 4224; i += 256) {
            const uint4* src = (i < 2112) ? ((const uint4*)&g_Bw[0][0][0]) + i
                                          : ((const uint4*)&g_Bw[2][0][0]) + (i - 2112);
            cpa16(dst + i * 16, src);
        }
        CP_COMMIT();
    }
    load_x_tile(smem, x + ((size_t)b * NC) * NTOK + n0, tid);

    float acc[2][4][4];
#pragma unroll 1
    for (int s = 0; s < 8; s++) {
        const int nc = s >> 1, plane = s & 1;
        if (s < 7) {
            int nn = (s + 1) >> 1, pp = (s + 1) & 1;
            uint32_t dst = sb + T1_B + ((s + 1) & 1) * 67584;
            for (int i = tid; i < 4224; i += 256) {
                const uint4* src = (i < 2112) ? ((const uint4*)&g_Bw[pp][nn * 64][0]) + i
                                              : ((const uint4*)&g_Bw[2 + pp][nn * 64][0]) + (i - 2112);
                cpa16(dst + i * 16, src);
            }
            CP_COMMIT();
            CP_WAIT1();
        } else {
            CP_WAIT0();
        }
        __syncthreads();

        const uint32_t bB0 = sb + T1_B + (s & 1) * 67584 + op * 33792
                           + (ch * 32 + blrow) * 528 + blcol2;
        if (plane == 0) {
#pragma unroll
            for (int t = 0; t < 2; t++)
#pragma unroll
                for (int f = 0; f < 4; f++)
#pragma unroll
                    for (int j = 0; j < 4; j++) acc[t][f][j] = 0.f;
#pragma unroll 2
            for (int k = 0; k < 16; k++) {
                uint32_t ah0[4], ah1[4], al0[4], al1[4];
                ldm_x4(ah0, aH0 + k * 32);
                ldm_x4(ah1, aH0 + 16 * 528 + k * 32);
                ldm_x4(al0, aL0 + k * 32);
                ldm_x4(al1, aL0 + 16 * 528 + k * 32);
#pragma unroll
                for (int q = 0; q < 2; q++) {
                    uint32_t bb[4];
                    ldm_x4(bb, bB0 + q * 16 * 528 + k * 32);
                    mma_bf16(acc[0][q * 2], ah0, bb);
                    mma_bf16(acc[0][q * 2 + 1], ah0, bb + 2);
                    mma_bf16(acc[1][q * 2], ah1, bb);
                    mma_bf16(acc[1][q * 2 + 1], ah1, bb + 2);
                    mma_bf16(acc[0][q * 2], al0, bb);
                    mma_bf16(acc[0][q * 2 + 1], al0, bb + 2);
                    mma_bf16(acc[1][q * 2], al1, bb);
                    mma_bf16(acc[1][q * 2 + 1], al1, bb + 2);
                }
            }
        } else {
#pragma unroll 2
            for (int k = 0; k < 16; k++) {
                uint32_t ah0[4], ah1[4];
                ldm_x4(ah0, aH0 + k * 32);
                ldm_x4(ah1, aH0 + 16 * 528 + k * 32);
#pragma unroll
                for (int q = 0; q < 2; q++) {
                    uint32_t bb[4];
                    ldm_x4(bb, bB0 + q * 16 * 528 + k * 32);
                    mma_bf16(acc[0][q * 2], ah0, bb);
                    mma_bf16(acc[0][q * 2 + 1], ah0, bb + 2);
                    mma_bf16(acc[1][q * 2], ah1, bb);
                    mma_bf16(acc[1][q * 2 + 1], ah1, bb + 2);
                }
            }
            // epilogue: +pos/bias, store K/V to global
            int r0 = lane >> 2, cq = (lane & 3) * 2;
            if (op == 0) {
#pragma unroll
                for (int t = 0; t < 2; t++)
#pragma unroll
                    for (int f = 0; f < 4; f++) {
                        int co = nc * 64 + ch * 32 + f * 8 + cq;
                        int row = mt * 32 + t * 16 + r0;
                        float2 rk = *(const float2*)&g_RK[y * NC + co];
                        float2 bk2 = *(const float2*)&bk[co];
                        float2 pa = *(const float2*)&g_PK[(x0 + row) * NC + co];
                        float2 pb = *(const float2*)&g_PK[(x0 + row + 8) * NC + co];
                        float2 o;
                        o.x = acc[t][f][0] + rk.x + pa.x + bk2.x;
                        o.y = acc[t][f][1] + rk.y + pa.y + bk2.y;
                        *(float2*)&g_K[((size_t)b * NTOK + n0 + row) * NC + co] = o;
                        o.x = acc[t][f][2] + rk.x + pb.x + bk2.x;
                        o.y = acc[t][f][3] + rk.y + pb.y + bk2.y;
                        *(float2*)&g_K[((size_t)b * NTOK + n0 + row + 8) * NC + co] = o;
                    }
            } else {
#pragma unroll
                for (int t = 0; t < 2; t++)
#pragma unroll
                    for (int f = 0; f < 4; f++) {
                        int co = nc * 64 + ch * 32 + f * 8 + cq;
                        int row = mt * 32 + t * 16 + r0;
                        float2 bv2 = *(const float2*)&bv[co];
                        float2 o;
                        o.x = acc[t][f][0] + bv2.x;
                        o.y = acc[t][f][1] + bv2.y;
                        *(float2*)&g_V[((size_t)b * NTOK + n0 + row) * NC + co] = o;
                        o.x = acc[t][f][2] + bv2.x;
                        o.y = acc[t][f][3] + bv2.y;
                        *(float2*)&g_V[((size_t)b * NTOK + n0 + row + 8) * NC + co] = o;
                    }
            }
        }
        __syncthreads();
    }
}

// ---------------- T2: per-head LN + tf32 scores (high occupancy) ----------------
__global__ void __launch_bounds__(256) t2_kernel(
    const float* __restrict__ gK, const float* __restrict__ bKp,
    const float* __restrict__ gV, const float* __restrict__ bVp)
{
    __shared__ float Ksm[64 * 68];
    __shared__ float Vsm[64 * 68];
    const int tid = threadIdx.x, w = tid >> 5, lane = tid & 31;
    const int blk = blockIdx.x, b = blockIdx.y;
    const int n0 = blk * 64;

#pragma unroll 1
    for (int nc = 0; nc < 4; nc++) {
        // load K/V chunk [64 tok][64 co]
        for (int i = tid; i < 1024; i += 256) {
            int row = i >> 4, c4 = (i & 15) * 4;
            size_t gidx = ((size_t)b * NTOK + n0 + row) * NC + nc * 64 + c4;
            *(float4*)&Ksm[row * 68 + c4] = *(const float4*)&g_K[gidx];
            *(float4*)&Vsm[row * 68 + c4] = *(const float4*)&g_V[gidx];
        }
        __syncthreads();

        // per-head LN in place
        if (tid < 128) {
            int tok = tid & 63, hl = tid >> 6;
            int head = nc * 2 + hl;
            float* kp = &Ksm[tok * 68 + hl * 32];
            float* vp = &Vsm[tok * 68 + hl * 32];
            const float4* gk4 = (const float4*)(gK + head * 32);
            const float4* bkk = (const float4*)(bKp + head * 32);
            const float4* gv4 = (const float4*)(gV + head * 32);
            const float4* bvv = (const float4*)(bVp + head * 32);
            float4 r[8]; float s = 0.f, s2 = 0.f;
#pragma unroll
            for (int jj = 0; jj < 8; jj++) {
                r[jj] = ((const float4*)kp)[jj];
                s += r[jj].x + r[jj].y + r[jj].z + r[jj].w;
                s2 += r[jj].x * r[jj].x + r[jj].y * r[jj].y + r[jj].z * r[jj].z + r[jj].w * r[jj].w;
            }
            float mu = s * (1.f / 32.f);
            float rstd = rsqrtf(s2 * (1.f / 32.f) - mu * mu + 1e-5f);
#pragma unroll
            for (int jj = 0; jj < 8; jj++) {
                float4 g = gk4[jj], be = bkk[jj], o;
                o.x = (r[jj].x - mu) * rstd * g.x + be.x;
                o.y = (r[jj].y - mu) * rstd * g.y + be.y;
                o.z = (r[jj].z - mu) * rstd * g.z + be.z;
                o.w = (r[jj].w - mu) * rstd * g.w + be.w;
                ((float4*)kp)[jj] = o;
            }
            s = 0.f; s2 = 0.f;
#pragma unroll
            for (int jj = 0; jj < 8; jj++) {
                r[jj] = ((const float4*)vp)[jj];
                s += r[jj].x + r[jj].y + r[jj].z + r[jj].w;
                s2 += r[jj].x * r[jj].x + r[jj].y * r[jj].y + r[jj].z * r[jj].z + r[jj].w * r[jj].w;
            }
            mu = s * (1.f / 32.f);
            rstd = rsqrtf(s2 * (1.f / 32.f) - mu * mu + 1e-5f);
#pragma unroll
            for (int jj = 0; jj < 8; jj++) {
                float4 g = gv4[jj], be = bvv[jj], o;
                o.x = (r[jj].x - mu) * rstd * g.x + be.x;
                o.y = (r[jj].y - mu) * rstd * g.y + be.y;
                o.z = (r[jj].z - mu) * rstd * g.z + be.z;
                o.w = (r[jj].w - mu) * rstd * g.w + be.w;
                ((float4*)vp)[jj] = o;
            }
        }
        __syncthreads();

        // scores: S_h += K^T V via tf32 mma (k = 64 tokens)
        {
            int hl = w >> 2, v = w & 3, smt = v & 1, np = v >> 1;
            int dcol = hl * 32 + smt * 16 + (lane >> 2);
            float sc[2][4];
#pragma unroll
            for (int t = 0; t < 2; t++)
#pragma unroll
                for (int j = 0; j < 4; j++) sc[t][j] = 0.f;
#pragma unroll 2
            for (int k0 = 0; k0 < 64; k0 += 8) {
                int trow = k0 + (lane & 3);
                uint32_t a[4];
                a[0] = f2tf(Ksm[trow * 68 + dcol]);
                a[1] = f2tf(Ksm[trow * 68 + dcol + 8]);
                a[2] = f2tf(Ksm[(trow + 4) * 68 + dcol]);
                a[3] = f2tf(Ksm[(trow + 4) * 68 + dcol + 8]);
#pragma unroll
                for (int t = 0; t < 2; t++) {
                    int ecol = hl * 32 + np * 16 + t * 8 + (lane >> 2);
                    uint32_t bb[2];
                    bb[0] = f2tf(Vsm[trow * 68 + ecol]);
                    bb[1] = f2tf(Vsm[(trow + 4) * 68 + ecol]);
                    mma_tf32(sc[t], a, bb);
                }
            }
            int head = nc * 2 + hl;
            float* dst = g_spart + ((size_t)(b * 256 + blk)) * 8192 + head * 1024;
            int d0 = smt * 16 + (lane >> 2);
#pragma unroll
            for (int t = 0; t < 2; t++) {
                int e0 = np * 16 + t * 8 + (lane & 3) * 2;
                dst[d0 * 32 + e0] = sc[t][0];
                dst[d0 * 32 + e0 + 1] = sc[t][1];
                dst[(d0 + 8) * 32 + e0] = sc[t][2];
                dst[(d0 + 8) * 32 + e0 + 1] = sc[t][3];
            }
        }
        __syncthreads();
    }
}

// ---------------- k2 chain ----------------
__global__ void k2_reduce() {
    int b = blockIdx.x >> 5, seg = blockIdx.x & 31;
    int base = seg * 256 + threadIdx.x;
    float s = 0.f;
#pragma unroll 8
    for (int rb = 0; rb < 256; rb++) s += g_spart[((size_t)(b * 256 + rb)) * 8192 + base];
    g_S[b * 8192 + base] = s * (1.0f / 16384.0f);
}

__global__ void k2b_buildM(const float* __restrict__ Wq, const float* __restrict__ bq) {
    __shared__ float Wqs[256 * 33];
    int chunk = blockIdx.x, b = blockIdx.y;
    int co = threadIdx.x, h = co >> 5, e = co & 31;
    for (int idx = threadIdx.x; idx < 8192; idx += 256) {
        int row = idx >> 5, cil = idx & 31;
        Wqs[row * 33 + cil] = Wq[row * NC + chunk * 32 + cil];
    }
    float Scol[32];
#pragma unroll
    for (int d = 0; d < 32; d++) Scol[d] = g_S[b * 8192 + h * 1024 + d * 32 + e];
    __syncthreads();
    for (int cil = 0; cil < 32; cil++) {
        float m = 0.f;
#pragma unroll
        for (int d = 0; d < 32; d++) m += Wqs[(h * 32 + d) * 33 + cil] * Scol[d];
        g_M[(size_t)b * 65536 + (size_t)co * NC + chunk * 32 + cil] = m;
    }
    if (chunk == 0) {
        float bb = 0.f;
#pragma unroll
        for (int d = 0; d < 32; d++) bb += bq[h * 32 + d] * Scol[d];
        g_biasq[b * NC + co] = bb;
    }
}

__global__ void k2m_conv() {
    int rg = blockIdx.x, b = blockIdx.y;
    for (int it = 0; it < 4; it++) {
        int pack = it * 256 + threadIdx.x;
        int row = rg * 32 + (pack >> 5), ci0 = (pack & 31) * 8;
        unsigned short hi[8], lo[8];
#pragma unroll
        for (int j = 0; j < 8; j++) {
            float v = g_M[(size_t)b * 65536 + (size_t)row * NC + ci0 + j];
            hi[j] = bfu(v);
            lo[j] = bfu(v - bf2f(hi[j]));
        }
        *(uint4*)&g_Bm[b][0][row][ci0] = *(uint4*)hi;
        *(uint4*)&g_Bm[b][1][row][ci0] = *(uint4*)lo;
    }
}

__global__ void k2c_rqpq() {
    __shared__ float Ts[128];
    int p = blockIdx.x, b = blockIdx.y;
    int co = threadIdx.x;
    if (co < 128) Ts[co] = g_T[p * 128 + co];
    __syncthreads();
    const float4* Mr = (const float4*)(g_M + (size_t)b * 65536 + (size_t)co * NC);
    float accR = 0.f, accP = 0.f;
#pragma unroll 8
    for (int c4 = 0; c4 < 32; c4++) {
        float4 m0 = Mr[c4], m1 = Mr[32 + c4];
        float4 t4 = *(const float4*)&Ts[c4 * 4];
        accR += t4.x * m0.x + t4.y * m0.y + t4.z * m0.z + t4.w * m0.w;
        accP += t4.x * m1.x + t4.y * m1.y + t4.z * m1.z + t4.w * m1.w;
    }
    g_RQ[(b * 128 + p) * NC + co] = accR;
    g_PQ[(b * 128 + p) * NC + co] = accP;
}

// ---------------- T3: HMMA out GEMM + x2 + LN + transposed store ----------------
__global__ void __launch_bounds__(256, 1) t3_kernel(
    const float* __restrict__ x,
    const float* __restrict__ g_ln, const float* __restrict__ b_ln,
    float* __restrict__ out)
{
    extern __shared__ char smem[];
    const int tid = threadIdx.x, w = tid >> 5, lane = tid & 31;
    const int blk = blockIdx.x, b = blockIdx.y;
    const int n0 = blk * 64, y = n0 >> 7, x0 = n0 & 127;
    uint32_t sb = s2u(smem);
    float* stg = (float*)(smem + T3_STG);
    float* mus = (float*)(smem + T3_MU);
    float* rss = (float*)(smem + T3_RS);

    // prefetch (ncp=0, plane=0)
    for (int i = tid; i < 4224; i += 256)
        cpa16(sb + T3_B + i * 16, ((const uint4*)&g_Bm[b][0][0][0]) + i);
    CP_COMMIT();
    load_x_tile(smem, x + ((size_t)b * NC) * NTOK + n0, tid);

    const int nc2 = w >> 2, mt = (w >> 1) & 1, ch = w & 1;
    const int acol2 = (lane & 16) ? 16 : 0;
    const int blrow = (lane & 7) + ((lane & 16) ? 8 : 0);
    const int blcol2 = (lane & 8) ? 16 : 0;
    const uint32_t aH0 = sb + (mt * 32 + (lane & 15)) * 528 + acol2;
    const uint32_t aL0 = aH0 + T3_ALO;
    const uint32_t bB0 = sb + T3_B + nc2 * 33792 + (ch * 32 + blrow) * 528 + blcol2;

#pragma unroll 1
    for (int ncp = 0; ncp < 2; ncp++) {
        const int nc = ncp * 2 + nc2;
        float acc[2][4][4];
#pragma unroll
        for (int t = 0; t < 2; t++)
#pragma unroll
            for (int f = 0; f < 4; f++)
#pragma unroll
                for (int j = 0; j < 4; j++) acc[t][f][j] = 0.f;

        CP_WAIT0();
        __syncthreads();
        // plane0: hi B, A hi + lo
#pragma unroll 2
        for (int k = 0; k < 16; k++) {
            uint32_t ah0[4], ah1[4], al0[4], al1[4];
            ldm_x4(ah0, aH0 + k * 32);
            ldm_x4(ah1, aH0 + 16 * 528 + k * 32);
            ldm_x4(al0, aL0 + k * 32);
            ldm_x4(al1, aL0 + 16 * 528 + k * 32);
#pragma unroll
            for (int q = 0; q < 2; q++) {
                uint32_t bb[4];
                ldm_x4(bb, bB0 + q * 16 * 528 + k * 32);
                mma_bf16(acc[0][q * 2], ah0, bb);
                mma_bf16(acc[0][q * 2 + 1], ah0, bb + 2);
                mma_bf16(acc[1][q * 2], ah1, bb);
                mma_bf16(acc[1][q * 2 + 1], ah1, bb + 2);
                mma_bf16(acc[0][q * 2], al0, bb);
                mma_bf16(acc[0][q * 2 + 1], al0, bb + 2);
                mma_bf16(acc[1][q * 2], al1, bb);
                mma_bf16(acc[1][q * 2 + 1], al1, bb + 2);
            }
        }
        __syncthreads();
        // load plane1 (lo B)
        for (int i = tid; i < 4224; i += 256)
            cpa16(sb + T3_B + i * 16, ((const uint4*)&g_Bm[b][1][ncp * 128][0]) + i);
        CP_COMMIT();
        CP_WAIT0();
        __syncthreads();
#pragma unroll 2
        for (int k = 0; k < 16; k++) {
            uint32_t ah0[4], ah1[4];
            ldm_x4(ah0, aH0 + k * 32);
            ldm_x4(ah1, aH0 + 16 * 528 + k * 32);
#pragma unroll
            for (int q = 0; q < 2; q++) {
                uint32_t bb[4];
                ldm_x4(bb, bB0 + q * 16 * 528 + k * 32);
                mma_bf16(acc[0][q * 2], ah0, bb);
                mma_bf16(acc[0][q * 2 + 1], ah0, bb + 2);
                mma_bf16(acc[1][q * 2], ah1, bb);
                mma_bf16(acc[1][q * 2 + 1], ah1, bb + 2);
            }
        }
        __syncthreads();
        if (ncp == 0) {
            // prefetch next ncp plane0 while staging
            for (int i = tid; i < 4224; i += 256)
                cpa16(sb + T3_B + i * 16, ((const uint4*)&g_Bm[b][0][128][0]) + i);
            CP_COMMIT();
        }

        // stage with +RQ+PQ+biasq, x2
        {
            int r0 = lane >> 2, cq = (lane & 3) * 2;
#pragma unroll
            for (int t = 0; t < 2; t++)
#pragma unroll
                for (int f = 0; f < 4; f++) {
                    int co = nc * 64 + ch * 32 + f * 8 + cq;
                    int row = mt * 32 + t * 16 + r0;
                    float2 rq = *(const float2*)&g_RQ[(b * 128 + y) * NC + co];
                    float2 qb = *(const float2*)&g_biasq[b * NC + co];
                    float2 pa = *(const float2*)&g_PQ[(b * 128 + x0 + row) * NC + co];
                    float2 pb = *(const float2*)&g_PQ[(b * 128 + x0 + row + 8) * NC + co];
                    stg[row * 264 + co] = 2.f * (acc[t][f][0] + rq.x + qb.x + pa.x);
                    stg[row * 264 + co + 1] = 2.f * (acc[t][f][1] + rq.y + qb.y + pa.y);
                    stg[(row + 8) * 264 + co] = 2.f * (acc[t][f][2] + rq.x + qb.x + pb.x);
                    stg[(row + 8) * 264 + co + 1] = 2.f * (acc[t][f][3] + rq.y + qb.y + pb.y);
                }
        }
    }
    __syncthreads();

    // LN stats: 4 threads per token
    {
        int token = tid >> 2, q = tid & 3;
        float s = 0.f, s2 = 0.f;
#pragma unroll
        for (int jj = 0; jj < 16; jj++) {
            float4 v = *(const float4*)&stg[token * 264 + q * 64 + jj * 4];
            s += v.x + v.y + v.z + v.w;
            s2 += v.x * v.x + v.y * v.y + v.z * v.z + v.w * v.w;
        }
#pragma unroll
        for (int off = 1; off < 4; off <<= 1) {
            s += __shfl_xor_sync(0xffffffffu, s, off);
            s2 += __shfl_xor_sync(0xffffffffu, s2, off);
        }
        if (q == 0) {
            float mu = s * (1.f / 256.f);
            mus[token] = mu;
            rss[token] = rsqrtf(s2 * (1.f / 256.f) - mu * mu + 1e-5f);
        }
    }
    __syncthreads();

    // normalize + transposed coalesced store
    {
        int t = tid & 63, cg = tid >> 6;
        float mu = mus[t], rs = rss[t];
        size_t obase = ((size_t)b * NC) * NTOK + n0 + t;
#pragma unroll 4
        for (int p = 0; p < 64; p++) {
            int co = cg * 64 + p;
            out[obase + (size_t)co * NTOK] = (stg[t * 264 + co] - mu) * rs * g_ln[co] + b_ln[co];
        }
    }
}

// ---------------- launch ----------------
extern "C" void kernel_launch(void* const* d_in, const int* in_sizes, int n_in,
                              void* d_out, int out_size) {
    const float* x    = (const float*)d_in[0];
    const float* Wq   = (const float*)d_in[1];
    const float* bq   = (const float*)d_in[2];
    const float* Wk   = (const float*)d_in[3];
    const float* bk   = (const float*)d_in[4];
    const float* Wv   = (const float*)d_in[5];
    const float* bv   = (const float*)d_in[6];
    const float* gK   = (const float*)d_in[7];
    const float* bK   = (const float*)d_in[8];
    const float* gV   = (const float*)d_in[9];
    const float* bV   = (const float*)d_in[10];
    const float* g_ln = (const float*)d_in[11];
    const float* b_ln = (const float*)d_in[12];
    float* out = (float*)d_out;

    cudaFuncSetAttribute(t1_kernel, cudaFuncAttributeMaxDynamicSharedMemorySize, T1_TOT);
    cudaFuncSetAttribute(t3_kernel, cudaFuncAttributeMaxDynamicSharedMemorySize, T3_TOT);

    prep0_kernel<<<256, 256>>>(Wk);
    prepw_kernel<<<2, 256>>>(Wk, Wv);
    prep1_kernel<<<16, 256>>>();
    t1_kernel<<<dim3(256, 8), 256, T1_TOT>>>(x, bk, bv);
    t2_kernel<<<dim3(256, 8), 256>>>(gK, bK, gV, bV);
    k2_reduce<<<256, 256>>>();
    k2b_buildM<<<dim3(8, 8), 256>>>(Wq, bq);
    k2m_conv<<<dim3(8, 8), 256>>>();
    k2c_rqpq<<<dim3(128, 8), 256>>>();
    t3_kernel<<<dim3(256, 8), 256, T3_TOT>>>(x, g_ln, b_ln, out);
}

// round 9
// speedup vs baseline: 1.9524x; 1.4268x over previous
#include <cuda_runtime.h>
#include <cuda_fp16.h>
#include <math.h>
#include <stdint.h>

#define NB 8
#define NC 256
#define NTOK 16384

__device__ __forceinline__ uint32_t s2u(const void* p) {
    uint32_t a;
    asm("{ .reg .u64 t; cvta.to.shared.u64 t, %1; cvt.u32.u64 %0, t; }" : "=r"(a) : "l"(p));
    return a;
}
__device__ __forceinline__ uint32_t f2tf(float f) {
    uint32_t r; asm("cvt.rna.tf32.f32 %0, %1;" : "=r"(r) : "f"(f)); return r;
}
__device__ __forceinline__ void ldm_x4(uint32_t r[4], uint32_t addr) {
    asm volatile("ldmatrix.sync.aligned.m8n8.x4.shared.b16 {%0,%1,%2,%3}, [%4];"
        : "=r"(r[0]), "=r"(r[1]), "=r"(r[2]), "=r"(r[3]) : "r"(addr));
}
__device__ __forceinline__ void mma_f16(float c[4], const uint32_t a[4], const uint32_t b[2]) {
    asm volatile("mma.sync.aligned.m16n8k16.row.col.f32.f16.f16.f32 "
        "{%0,%1,%2,%3}, {%4,%5,%6,%7}, {%8,%9}, {%0,%1,%2,%3};"
        : "+f"(c[0]), "+f"(c[1]), "+f"(c[2]), "+f"(c[3])
        : "r"(a[0]), "r"(a[1]), "r"(a[2]), "r"(a[3]), "r"(b[0]), "r"(b[1]));
}
__device__ __forceinline__ void mma_tf32(float c[4], const uint32_t a[4], const uint32_t b[2]) {
    asm volatile("mma.sync.aligned.m16n8k8.row.col.f32.tf32.tf32.f32 "
        "{%0,%1,%2,%3}, {%4,%5,%6,%7}, {%8,%9}, {%0,%1,%2,%3};"
        : "+f"(c[0]), "+f"(c[1]), "+f"(c[2]), "+f"(c[3])
        : "r"(a[0]), "r"(a[1]), "r"(a[2]), "r"(a[3]), "r"(b[0]), "r"(b[1]));
}
__device__ __forceinline__ void cpa16(uint32_t s, const void* g) {
    asm volatile("cp.async.cg.shared.global [%0], [%1], 16;"
        :: "r"(s), "l"(__cvta_generic_to_global(g)));
}
#define CP_COMMIT() asm volatile("cp.async.commit_group;" ::: "memory")
#define CP_WAIT0() asm volatile("cp.async.wait_group 0;" ::: "memory")
#define CP_WAIT1() asm volatile("cp.async.wait_group 1;" ::: "memory")

// ---------------- device scratch ----------------
__device__ float g_T[128 * 128];
__device__ float g_WkT[NC * NC];
__device__ float g_RK[128 * NC];
__device__ float g_PK[128 * NC];
__device__ __half g_K[(size_t)NB * NTOK * NC];
__device__ __half g_V[(size_t)NB * NTOK * NC];
__device__ float g_spart[(size_t)NB * 256 * 8192];
__device__ float g_S[NB * 8192];
__device__ float g_M[NB * NC * NC];          // transposed [co][ci]
__device__ float g_biasq[NB * NC];
__device__ float g_RQ[NB * 128 * NC];
__device__ float g_PQ[NB * 128 * NC];
__device__ __align__(16) __half g_Bw[2][256][264];      // Wk, Wv fp16 [co][ci]
__device__ __align__(16) __half g_Bm[NB][256][264];     // M fp16 [co][ci]

// smem maps (bytes)
#define A_LO  67584
#define B_OFF 135168        // two slots of 33792 @135168, @168960
#define T_TOT 202752
#define T3_MU 202752
#define T3_RS 203264
#define T3_TOT 203776

// ---------------- preps ----------------
__global__ void prep0_kernel(const float* __restrict__ Wk, const float* __restrict__ Wv) {
    int idx = blockIdx.x * 256 + threadIdx.x;
    int co = idx >> 8, ci = idx & 255;
    g_WkT[ci * NC + co] = Wk[idx];
    g_Bw[0][co][ci] = __float2half_rn(Wk[idx]);
    g_Bw[1][co][ci] = __float2half_rn(Wv[idx]);
    if (idx < 128 * 128) {
        int p = idx >> 7, c = idx & 127, j = c >> 1;
        float dimt = powf(10000.0f, (float)j * (1.0f / 64.0f));
        float t = (float)(p + 1) * (6.283185307179586f / (128.0f + 1e-6f)) / dimt;
        g_T[idx] = (c & 1) ? cosf(t) : sinf(t);
    }
}

__global__ void prep1_kernel() {
    int table = blockIdx.x >> 3, chunk = blockIdx.x & 7;
    int n = chunk * 32 + (threadIdx.x & 31);
    int yg = threadIdx.x >> 5;
    float acc[16];
#pragma unroll
    for (int i = 0; i < 16; i++) acc[i] = 0.f;
    const float* W = g_WkT + (table ? 128 * NC : 0);
#pragma unroll 4
    for (int c = 0; c < 128; c++) {
        float w = W[c * NC + n];
#pragma unroll
        for (int yy = 0; yy < 16; yy++) acc[yy] += g_T[(yg * 16 + yy) * 128 + c] * w;
    }
    float* dst = table ? g_PK : g_RK;
#pragma unroll
    for (int yy = 0; yy < 16; yy++) dst[(yg * 16 + yy) * NC + n] = acc[yy];
}

// x[ci][tok] -> A[tok 128][ci 256 pad 264] fp16 hi/lo
__device__ __forceinline__ void load_x_tile(char* smem, const float* __restrict__ xb, int tid) {
    int tok = tid & 127, cig = tid >> 7;
#pragma unroll 1
    for (int p = 0; p < 8; p++) {
        int ci0 = (cig + p * 4) * 8;
        __half hi[8], lo[8];
#pragma unroll
        for (int j = 0; j < 8; j++) {
            float v = xb[(size_t)(ci0 + j) * NTOK + tok];
            hi[j] = __float2half_rn(v);
            lo[j] = __float2half_rn(v - __half2float(hi[j]));
        }
        *(uint4*)(smem + tok * 528 + ci0 * 2) = *(uint4*)hi;
        *(uint4*)(smem + A_LO + tok * 528 + ci0 * 2) = *(uint4*)lo;
    }
}

// ---------------- T1: fp16 2-pass K/V projection ----------------
__global__ void __launch_bounds__(512, 1) t1_kernel(
    const float* __restrict__ x,
    const float* __restrict__ bk, const float* __restrict__ bv)
{
    extern __shared__ char smem[];
    const int tid = threadIdx.x, w = tid >> 5, lane = tid & 31;
    const int rb = blockIdx.x, b = blockIdx.y;
    const int n0 = rb * 128;
    uint32_t sb = s2u(smem);

    const int mt = w >> 1, ch = w & 1;
    const uint32_t aH0 = sb + (mt * 16 + (lane & 15)) * 528 + ((lane & 16) ? 16 : 0);
    const uint32_t aL0 = aH0 + A_LO;
    const int blrow = (lane & 7) + ((lane & 16) ? 8 : 0);
    const int blcol2 = (lane & 8) ? 16 : 0;

    for (int i = tid; i < 2112; i += 512)
        cpa16(sb + B_OFF + i * 16, ((const uint4*)&g_Bw[0][0][0]) + i);
    CP_COMMIT();
    load_x_tile(smem, x + ((size_t)b * NC) * NTOK + n0, tid);

#pragma unroll 1
    for (int s = 0; s < 8; s++) {
        const int nc = s >> 1, op = s & 1;
        if (s < 7) {
            int nn = (s + 1) >> 1, oo = (s + 1) & 1;
            uint32_t dst = sb + B_OFF + ((s + 1) & 1) * 33792;
            for (int i = tid; i < 2112; i += 512)
                cpa16(dst + i * 16, ((const uint4*)&g_Bw[oo][nn * 64][0]) + i);
            CP_COMMIT(); CP_WAIT1();
        } else CP_WAIT0();
        __syncthreads();

        float acc[4][4];
#pragma unroll
        for (int f = 0; f < 4; f++)
#pragma unroll
            for (int j = 0; j < 4; j++) acc[f][j] = 0.f;

        const uint32_t bbase = sb + B_OFF + (s & 1) * 33792 + (ch * 32 + blrow) * 528 + blcol2;
#pragma unroll 4
        for (int k = 0; k < 16; k++) {
            uint32_t ah[4], al[4];
            ldm_x4(ah, aH0 + k * 32);
            ldm_x4(al, aL0 + k * 32);
#pragma unroll
            for (int q = 0; q < 2; q++) {
                uint32_t bb[4];
                ldm_x4(bb, bbase + q * 16 * 528 + k * 32);
                mma_f16(acc[q * 2], ah, bb);
                mma_f16(acc[q * 2 + 1], ah, bb + 2);
                mma_f16(acc[q * 2], al, bb);
                mma_f16(acc[q * 2 + 1], al, bb + 2);
            }
        }
        __syncthreads();

        // epilogue: +pos/bias, store fp16 K/V
        {
            int r0 = lane >> 2, cq = (lane & 3) * 2;
            int row = mt * 16 + r0;
            if (op == 0) {
#pragma unroll
                for (int f = 0; f < 4; f++) {
                    int co = nc * 64 + ch * 32 + f * 8 + cq;
                    float2 rk = *(const float2*)&g_RK[rb * NC + co];
                    float2 bk2 = *(const float2*)&bk[co];
                    float2 pa = *(const float2*)&g_PK[row * NC + co];
                    float2 pb = *(const float2*)&g_PK[(row + 8) * NC + co];
                    *(__half2*)&g_K[((size_t)b * NTOK + n0 + row) * NC + co] =
                        __floats2half2_rn(acc[f][0] + rk.x + pa.x + bk2.x,
                                          acc[f][1] + rk.y + pa.y + bk2.y);
                    *(__half2*)&g_K[((size_t)b * NTOK + n0 + row + 8) * NC + co] =
                        __floats2half2_rn(acc[f][2] + rk.x + pb.x + bk2.x,
                                          acc[f][3] + rk.y + pb.y + bk2.y);
                }
            } else {
#pragma unroll
                for (int f = 0; f < 4; f++) {
                    int co = nc * 64 + ch * 32 + f * 8 + cq;
                    float2 bv2 = *(const float2*)&bv[co];
                    *(__half2*)&g_V[((size_t)b * NTOK + n0 + row) * NC + co] =
                        __floats2half2_rn(acc[f][0] + bv2.x, acc[f][1] + bv2.y);
                    *(__half2*)&g_V[((size_t)b * NTOK + n0 + row + 8) * NC + co] =
                        __floats2half2_rn(acc[f][2] + bv2.x, acc[f][3] + bv2.y);
                }
            }
        }
    }
}

// ---------------- T2: per-head LN + tf32 scores ----------------
__global__ void __launch_bounds__(256) t2_kernel(
    const float* __restrict__ gK, const float* __restrict__ bKp,
    const float* __restrict__ gV, const float* __restrict__ bVp)
{
    __shared__ float Ksm[64 * 68];
    __shared__ float Vsm[64 * 68];
    const int tid = threadIdx.x, w = tid >> 5, lane = tid & 31;
    const int blk = blockIdx.x, b = blockIdx.y;
    const int n0 = blk * 64;

#pragma unroll 1
    for (int nc = 0; nc < 4; nc++) {
        for (int i = tid; i < 512; i += 256) {
            int row = i >> 3, c8 = (i & 7) * 8;
            size_t gidx = ((size_t)b * NTOK + n0 + row) * NC + nc * 64 + c8;
            uint4 kr = *(const uint4*)&g_K[gidx];
            uint4 vr = *(const uint4*)&g_V[gidx];
            const __half* kh = (const __half*)&kr;
            const __half* vh = (const __half*)&vr;
#pragma unroll
            for (int j = 0; j < 8; j++) {
                Ksm[row * 68 + c8 + j] = __half2float(kh[j]);
                Vsm[row * 68 + c8 + j] = __half2float(vh[j]);
            }
        }
        __syncthreads();

        if (tid < 128) {
            int tok = tid & 63, hl = tid >> 6;
            int head = nc * 2 + hl;
            float* kp = &Ksm[tok * 68 + hl * 32];
            float* vp = &Vsm[tok * 68 + hl * 32];
            const float4* gk4 = (const float4*)(gK + head * 32);
            const float4* bkk = (const float4*)(bKp + head * 32);
            const float4* gv4 = (const float4*)(gV + head * 32);
            const float4* bvv = (const float4*)(bVp + head * 32);
            float4 r[8]; float s = 0.f, s2 = 0.f;
#pragma unroll
            for (int jj = 0; jj < 8; jj++) {
                r[jj] = ((const float4*)kp)[jj];
                s += r[jj].x + r[jj].y + r[jj].z + r[jj].w;
                s2 += r[jj].x * r[jj].x + r[jj].y * r[jj].y + r[jj].z * r[jj].z + r[jj].w * r[jj].w;
            }
            float mu = s * (1.f / 32.f);
            float rstd = rsqrtf(s2 * (1.f / 32.f) - mu * mu + 1e-5f);
#pragma unroll
            for (int jj = 0; jj < 8; jj++) {
                float4 g = gk4[jj], be = bkk[jj], o;
                o.x = (r[jj].x - mu) * rstd * g.x + be.x;
                o.y = (r[jj].y - mu) * rstd * g.y + be.y;
                o.z = (r[jj].z - mu) * rstd * g.z + be.z;
                o.w = (r[jj].w - mu) * rstd * g.w + be.w;
                ((float4*)kp)[jj] = o;
            }
            s = 0.f; s2 = 0.f;
#pragma unroll
            for (int jj = 0; jj < 8; jj++) {
                r[jj] = ((const float4*)vp)[jj];
                s += r[jj].x + r[jj].y + r[jj].z + r[jj].w;
                s2 += r[jj].x * r[jj].x + r[jj].y * r[jj].y + r[jj].z * r[jj].z + r[jj].w * r[jj].w;
            }
            mu = s * (1.f / 32.f);
            rstd = rsqrtf(s2 * (1.f / 32.f) - mu * mu + 1e-5f);
#pragma unroll
            for (int jj = 0; jj < 8; jj++) {
                float4 g = gv4[jj], be = bvv[jj], o;
                o.x = (r[jj].x - mu) * rstd * g.x + be.x;
                o.y = (r[jj].y - mu) * rstd * g.y + be.y;
                o.z = (r[jj].z - mu) * rstd * g.z + be.z;
                o.w = (r[jj].w - mu) * rstd * g.w + be.w;
                ((float4*)vp)[jj] = o;
            }
        }
        __syncthreads();

        {
            int hl = w >> 2, v = w & 3, smt = v & 1, np = v >> 1;
            int dcol = hl * 32 + smt * 16 + (lane >> 2);
            float sc[2][4];
#pragma unroll
            for (int t = 0; t < 2; t++)
#pragma unroll
                for (int j = 0; j < 4; j++) sc[t][j] = 0.f;
#pragma unroll 2
            for (int k0 = 0; k0 < 64; k0 += 8) {
                int trow = k0 + (lane & 3);
                uint32_t a[4];
                a[0] = f2tf(Ksm[trow * 68 + dcol]);
                a[1] = f2tf(Ksm[trow * 68 + dcol + 8]);
                a[2] = f2tf(Ksm[(trow + 4) * 68 + dcol]);
                a[3] = f2tf(Ksm[(trow + 4) * 68 + dcol + 8]);
#pragma unroll
                for (int t = 0; t < 2; t++) {
                    int ecol = hl * 32 + np * 16 + t * 8 + (lane >> 2);
                    uint32_t bb[2];
                    bb[0] = f2tf(Vsm[trow * 68 + ecol]);
                    bb[1] = f2tf(Vsm[(trow + 4) * 68 + ecol]);
                    mma_tf32(sc[t], a, bb);
                }
            }
            int head = nc * 2 + hl;
            float* dst = g_spart + ((size_t)(b * 256 + blk)) * 8192 + head * 1024;
            int d0 = smt * 16 + (lane >> 2);
#pragma unroll
            for (int t = 0; t < 2; t++) {
                int e0 = np * 16 + t * 8 + (lane & 3) * 2;
                dst[d0 * 32 + e0] = sc[t][0];
                dst[d0 * 32 + e0 + 1] = sc[t][1];
                dst[(d0 + 8) * 32 + e0] = sc[t][2];
                dst[(d0 + 8) * 32 + e0 + 1] = sc[t][3];
            }
        }
        __syncthreads();
    }
}

// ---------------- k2 chain ----------------
__global__ void k2_reduce() {
    int b = blockIdx.x >> 5, seg = blockIdx.x & 31;
    int base = seg * 256 + threadIdx.x;
    float s = 0.f;
#pragma unroll 8
    for (int rb = 0; rb < 256; rb++) s += g_spart[((size_t)(b * 256 + rb)) * 8192 + base];
    g_S[b * 8192 + base] = s * (1.0f / 16384.0f);
}

__global__ void k2b_buildM(const float* __restrict__ Wq, const float* __restrict__ bq) {
    __shared__ float Wqs[256 * 33];
    int chunk = blockIdx.x, b = blockIdx.y;
    int co = threadIdx.x, h = co >> 5, e = co & 31;
    for (int idx = threadIdx.x; idx < 8192; idx += 256) {
        int row = idx >> 5, cil = idx & 31;
        Wqs[row * 33 + cil] = Wq[row * NC + chunk * 32 + cil];
    }
    float Scol[32];
#pragma unroll
    for (int d = 0; d < 32; d++) Scol[d] = g_S[b * 8192 + h * 1024 + d * 32 + e];
    __syncthreads();
    for (int cil = 0; cil < 32; cil++) {
        float m = 0.f;
#pragma unroll
        for (int d = 0; d < 32; d++) m += Wqs[(h * 32 + d) * 33 + cil] * Scol[d];
        g_M[(size_t)b * 65536 + (size_t)co * NC + chunk * 32 + cil] = m;
    }
    if (chunk == 0) {
        float bb = 0.f;
#pragma unroll
        for (int d = 0; d < 32; d++) bb += bq[h * 32 + d] * Scol[d];
        g_biasq[b * NC + co] = bb;
    }
}

__global__ void k2m_conv() {
    int b = blockIdx.y;
    int base = blockIdx.x * 2048 + threadIdx.x;
#pragma unroll
    for (int j = 0; j < 8; j++) {
        int idx = base + j * 256;
        int row = idx >> 8, ci = idx & 255;
        g_Bm[b][row][ci] = __float2half_rn(g_M[(size_t)b * 65536 + idx]);
    }
}

__global__ void k2c_rqpq() {
    __shared__ float Ts[128];
    int p = blockIdx.x, b = blockIdx.y;
    int co = threadIdx.x;
    if (co < 128) Ts[co] = g_T[p * 128 + co];
    __syncthreads();
    const float4* Mr = (const float4*)(g_M + (size_t)b * 65536 + (size_t)co * NC);
    float accR = 0.f, accP = 0.f;
#pragma unroll 8
    for (int c4 = 0; c4 < 32; c4++) {
        float4 m0 = Mr[c4], m1 = Mr[32 + c4];
        float4 t4 = *(const float4*)&Ts[c4 * 4];
        accR += t4.x * m0.x + t4.y * m0.y + t4.z * m0.z + t4.w * m0.w;
        accP += t4.x * m1.x + t4.y * m1.y + t4.z * m1.z + t4.w * m1.w;
    }
    g_RQ[(b * 128 + p) * NC + co] = accR;
    g_PQ[(b * 128 + p) * NC + co] = accP;
}

// ---------------- T3: fp16 2-pass out GEMM + x2 + LN + transposed store ----------------
__global__ void __launch_bounds__(512, 1) t3_kernel(
    const float* __restrict__ x,
    const float* __restrict__ g_ln, const float* __restrict__ b_ln,
    float* __restrict__ out)
{
    extern __shared__ char smem[];
    const int tid = threadIdx.x, w = tid >> 5, lane = tid & 31;
    const int rb = blockIdx.x, b = blockIdx.y;
    const int n0 = rb * 128;
    uint32_t sb = s2u(smem);

    const int mt = w >> 1, ch = w & 1;
    const uint32_t aH0 = sb + (mt * 16 + (lane & 15)) * 528 + ((lane & 16) ? 16 : 0);
    const uint32_t aL0 = aH0 + A_LO;
    const int blrow = (lane & 7) + ((lane & 16) ? 8 : 0);
    const int blcol2 = (lane & 8) ? 16 : 0;

    for (int i = tid; i < 2112; i += 512)
        cpa16(sb + B_OFF + i * 16, ((const uint4*)&g_Bm[b][0][0]) + i);
    CP_COMMIT();
    load_x_tile(smem, x + ((size_t)b * NC) * NTOK + n0, tid);

    float acc[4][4][4];
#pragma unroll
    for (int s = 0; s < 4; s++) {
        if (s < 3) {
            uint32_t dst = sb + B_OFF + ((s + 1) & 1) * 33792;
            for (int i = tid; i < 2112; i += 512)
                cpa16(dst + i * 16, ((const uint4*)&g_Bm[b][(s + 1) * 64][0]) + i);
            CP_COMMIT(); CP_WAIT1();
        } else CP_WAIT0();
        __syncthreads();

#pragma unroll
        for (int f = 0; f < 4; f++)
#pragma unroll
            for (int j = 0; j < 4; j++) acc[s][f][j] = 0.f;

        const uint32_t bbase = sb + B_OFF + (s & 1) * 33792 + (ch * 32 + blrow) * 528 + blcol2;
#pragma unroll 4
        for (int k = 0; k < 16; k++) {
            uint32_t ah[4], al[4];
            ldm_x4(ah, aH0 + k * 32);
            ldm_x4(al, aL0 + k * 32);
#pragma unroll
            for (int q = 0; q < 2; q++) {
                uint32_t bb[4];
                ldm_x4(bb, bbase + q * 16 * 528 + k * 32);
                mma_f16(acc[s][q * 2], ah, bb);
                mma_f16(acc[s][q * 2 + 1], ah, bb + 2);
                mma_f16(acc[s][q * 2], al, bb);
                mma_f16(acc[s][q * 2 + 1], al, bb + 2);
            }
        }
        __syncthreads();
    }

    // stage (+RQ+PQ+biasq, x2) into stg overlaying A
    float* stg = (float*)smem;          // [128][264]
    float* mus = (float*)(smem + T3_MU);
    float* rss = (float*)(smem + T3_RS);
    {
        int r0 = lane >> 2, cq = (lane & 3) * 2;
        int row = mt * 16 + r0;
#pragma unroll
        for (int s = 0; s < 4; s++)
#pragma unroll
            for (int f = 0; f < 4; f++) {
                int co = s * 64 + ch * 32 + f * 8 + cq;
                float2 rq = *(const float2*)&g_RQ[(b * 128 + rb) * NC + co];
                float2 qb = *(const float2*)&g_biasq[b * NC + co];
                float2 pa = *(const float2*)&g_PQ[(b * 128 + row) * NC + co];
                float2 pb = *(const float2*)&g_PQ[(b * 128 + row + 8) * NC + co];
                stg[row * 264 + co] = 2.f * (acc[s][f][0] + rq.x + qb.x + pa.x);
                stg[row * 264 + co + 1] = 2.f * (acc[s][f][1] + rq.y + qb.y + pa.y);
                stg[(row + 8) * 264 + co] = 2.f * (acc[s][f][2] + rq.x + qb.x + pb.x);
                stg[(row + 8) * 264 + co + 1] = 2.f * (acc[s][f][3] + rq.y + qb.y + pb.y);
            }
    }
    __syncthreads();

    // LN stats: 4 threads per token
    {
        int token = tid >> 2, q = tid & 3;
        float s = 0.f, s2 = 0.f;
#pragma unroll
        for (int jj = 0; jj < 16; jj++) {
            float4 v = *(const float4*)&stg[token * 264 + q * 64 + jj * 4];
            s += v.x + v.y + v.z + v.w;
            s2 += v.x * v.x + v.y * v.y + v.z * v.z + v.w * v.w;
        }
#pragma unroll
        for (int off = 1; off < 4; off <<= 1) {
            s += __shfl_xor_sync(0xffffffffu, s, off);
            s2 += __shfl_xor_sync(0xffffffffu, s2, off);
        }
        if (q == 0) {
            float mu = s * (1.f / 256.f);
            mus[token] = mu;
            rss[token] = rsqrtf(s2 * (1.f / 256.f) - mu * mu + 1e-5f);
        }
    }
    __syncthreads();

    // normalize + transposed coalesced store
    {
        int t = tid & 127, cg = tid >> 7;
        float mu = mus[t], rs = rss[t];
        size_t obase = ((size_t)b * NC) * NTOK + n0 + t;
#pragma unroll 4
        for (int p = 0; p < 64; p++) {
            int co = cg * 64 + p;
            out[obase + (size_t)co * NTOK] = (stg[t * 264 + co] - mu) * rs * g_ln[co] + b_ln[co];
        }
    }
}

// ---------------- launch ----------------
extern "C" void kernel_launch(void* const* d_in, const int* in_sizes, int n_in,
                              void* d_out, int out_size) {
    const float* x    = (const float*)d_in[0];
    const float* Wq   = (const float*)d_in[1];
    const float* bq   = (const float*)d_in[2];
    const float* Wk   = (const float*)d_in[3];
    const float* bk   = (const float*)d_in[4];
    const float* Wv   = (const float*)d_in[5];
    const float* bv   = (const float*)d_in[6];
    const float* gK   = (const float*)d_in[7];
    const float* bK   = (const float*)d_in[8];
    const float* gV   = (const float*)d_in[9];
    const float* bV   = (const float*)d_in[10];
    const float* g_ln = (const float*)d_in[11];
    const float* b_ln = (const float*)d_in[12];
    float* out = (float*)d_out;

    cudaFuncSetAttribute(t1_kernel, cudaFuncAttributeMaxDynamicSharedMemorySize, T_TOT);
    cudaFuncSetAttribute(t3_kernel, cudaFuncAttributeMaxDynamicSharedMemorySize, T3_TOT);

    prep0_kernel<<<256, 256>>>(Wk, Wv);
    prep1_kernel<<<16, 256>>>();
    t1_kernel<<<dim3(128, 8), 512, T_TOT>>>(x, bk, bv);
    t2_kernel<<<dim3(256, 8), 256>>>(gK, bK, gV, bV);
    k2_reduce<<<256, 256>>>();
    k2b_buildM<<<dim3(8, 8), 256>>>(Wq, bq);
    k2m_conv<<<dim3(32, 8), 256>>>();
    k2c_rqpq<<<dim3(128, 8), 256>>>();
    t3_kernel<<<dim3(128, 8), 512, T3_TOT>>>(x, g_ln, b_ln, out);
}

// round 10
// speedup vs baseline: 2.4732x; 1.2667x over previous
#include <cuda_runtime.h>
#include <cuda_fp16.h>
#include <math.h>
#include <stdint.h>

#define NB 8
#define NC 256
#define NTOK 16384

__device__ __forceinline__ uint32_t s2u(const void* p) {
    uint32_t a;
    asm("{ .reg .u64 t; cvta.to.shared.u64 t, %1; cvt.u32.u64 %0, t; }" : "=r"(a) : "l"(p));
    return a;
}
__device__ __forceinline__ void ldm_x4(uint32_t r[4], uint32_t addr) {
    asm volatile("ldmatrix.sync.aligned.m8n8.x4.shared.b16 {%0,%1,%2,%3}, [%4];"
        : "=r"(r[0]), "=r"(r[1]), "=r"(r[2]), "=r"(r[3]) : "r"(addr));
}
__device__ __forceinline__ void mma_f16(float c[4], const uint32_t a[4], const uint32_t b[2]) {
    asm volatile("mma.sync.aligned.m16n8k16.row.col.f32.f16.f16.f32 "
        "{%0,%1,%2,%3}, {%4,%5,%6,%7}, {%8,%9}, {%0,%1,%2,%3};"
        : "+f"(c[0]), "+f"(c[1]), "+f"(c[2]), "+f"(c[3])
        : "r"(a[0]), "r"(a[1]), "r"(a[2]), "r"(a[3]), "r"(b[0]), "r"(b[1]));
}
__device__ __forceinline__ void cpa16(uint32_t s, const void* g) {
    asm volatile("cp.async.cg.shared.global [%0], [%1], 16;"
        :: "r"(s), "l"(__cvta_generic_to_global(g)));
}
#define CP_COMMIT() asm volatile("cp.async.commit_group;" ::: "memory")
#define CP_WAIT0() asm volatile("cp.async.wait_group 0;" ::: "memory")
#define CP_WAIT1() asm volatile("cp.async.wait_group 1;" ::: "memory")

// ---------------- device scratch ----------------
__device__ float g_T[128 * 128];
__device__ float g_WkT[NC * NC];
__device__ float g_RK[128 * NC];
__device__ float g_PK[128 * NC];
__device__ float g_spart[(size_t)NB * 128 * 8192];
__device__ float g_S[NB * 8192];
__device__ float g_M[NB * NC * NC];          // transposed [co][ci]
__device__ float g_biasq[NB * NC];
__device__ float g_RQ[NB * 128 * NC];
__device__ float g_PQ[NB * 128 * NC];
__device__ __align__(16) __half g_Bw[2][256][264];      // Wk, Wv fp16 [co][ci]
__device__ __align__(16) __half g_Bm[NB][256][264];     // M fp16 [co][ci]

// t1 smem map (bytes): A 0..67584 | B slots @67584, @101376 | KT @135168 | VT @152576
#define B_OFF  67584
#define KT_OFF 135168
#define VT_OFF 152576
#define T1_TOT 169984
// t3: A 0..67584 | B 2 slots 67584..135168 | stg overlays 0..135168 | mu/rs after
#define T3_MU  135168
#define T3_RS  135680
#define T3_TOT 136192

// ---------------- preps ----------------
__global__ void prep0_kernel(const float* __restrict__ Wk, const float* __restrict__ Wv) {
    int idx = blockIdx.x * 256 + threadIdx.x;
    int co = idx >> 8, ci = idx & 255;
    g_WkT[ci * NC + co] = Wk[idx];
    g_Bw[0][co][ci] = __float2half_rn(Wk[idx]);
    g_Bw[1][co][ci] = __float2half_rn(Wv[idx]);
    if (idx < 128 * 128) {
        int p = idx >> 7, c = idx & 127, j = c >> 1;
        float dimt = powf(10000.0f, (float)j * (1.0f / 64.0f));
        float t = (float)(p + 1) * (6.283185307179586f / (128.0f + 1e-6f)) / dimt;
        g_T[idx] = (c & 1) ? cosf(t) : sinf(t);
    }
}

__global__ void prep1_kernel() {
    int table = blockIdx.x >> 3, chunk = blockIdx.x & 7;
    int n = chunk * 32 + (threadIdx.x & 31);
    int yg = threadIdx.x >> 5;
    float acc[16];
#pragma unroll
    for (int i = 0; i < 16; i++) acc[i] = 0.f;
    const float* W = g_WkT + (table ? 128 * NC : 0);
#pragma unroll 4
    for (int c = 0; c < 128; c++) {
        float w = W[c * NC + n];
#pragma unroll
        for (int yy = 0; yy < 16; yy++) acc[yy] += g_T[(yg * 16 + yy) * 128 + c] * w;
    }
    float* dst = table ? g_PK : g_RK;
#pragma unroll
    for (int yy = 0; yy < 16; yy++) dst[(yg * 16 + yy) * NC + n] = acc[yy];
}

// x[ci][tok] -> A[tok 128][ci 256 pad 264] fp16 (single plane)
__device__ __forceinline__ void load_x_tile(char* smem, const float* __restrict__ xb, int tid) {
    int tok = tid & 127, cig = tid >> 7;
#pragma unroll 1
    for (int p = 0; p < 8; p++) {
        int ci0 = (cig + p * 4) * 8;
        __half hv[8];
#pragma unroll
        for (int j = 0; j < 8; j++)
            hv[j] = __float2half_rn(xb[(size_t)(ci0 + j) * NTOK + tok]);
        *(uint4*)(smem + tok * 528 + ci0 * 2) = *(uint4*)hv;
    }
}

// ---------------- T1: fp16 K/V proj + register LN + fp16 scores ----------------
__global__ void __launch_bounds__(512, 1) t1_kernel(
    const float* __restrict__ x,
    const float* __restrict__ bk, const float* __restrict__ bv,
    const float* __restrict__ gK, const float* __restrict__ bKp,
    const float* __restrict__ gV, const float* __restrict__ bVp)
{
    extern __shared__ char smem[];
    const int tid = threadIdx.x, w = tid >> 5, lane = tid & 31;
    const int rb = blockIdx.x, b = blockIdx.y;
    const int n0 = rb * 128;
    uint32_t sb = s2u(smem);

    const int mt = w >> 1, ch = w & 1;
    const uint32_t aH0 = sb + (mt * 16 + (lane & 15)) * 528 + ((lane & 16) ? 16 : 0);
    const int blrow = (lane & 7) + ((lane & 16) ? 8 : 0);
    const int blcol2 = (lane & 8) ? 16 : 0;

    for (int i = tid; i < 2112; i += 512)
        cpa16(sb + B_OFF + i * 16, ((const uint4*)&g_Bw[0][0][0]) + i);
    CP_COMMIT();
    load_x_tile(smem, x + ((size_t)b * NC) * NTOK + n0, tid);

#pragma unroll 1
    for (int s = 0; s < 8; s++) {
        const int nc = s >> 1, op = s & 1;
        if (s < 7) {
            int nn = (s + 1) >> 1, oo = (s + 1) & 1;
            uint32_t dst = sb + B_OFF + ((s + 1) & 1) * 33792;
            for (int i = tid; i < 2112; i += 512)
                cpa16(dst + i * 16, ((const uint4*)&g_Bw[oo][nn * 64][0]) + i);
            CP_COMMIT(); CP_WAIT1();
        } else CP_WAIT0();
        __syncthreads();

        float acc[4][4];
#pragma unroll
        for (int f = 0; f < 4; f++)
#pragma unroll
            for (int j = 0; j < 4; j++) acc[f][j] = 0.f;

        const uint32_t bbase = sb + B_OFF + (s & 1) * 33792 + (ch * 32 + blrow) * 528 + blcol2;
#pragma unroll 4
        for (int k = 0; k < 16; k++) {
            uint32_t ah[4];
            ldm_x4(ah, aH0 + k * 32);
#pragma unroll
            for (int q = 0; q < 2; q++) {
                uint32_t bb[4];
                ldm_x4(bb, bbase + q * 16 * 528 + k * 32);
                mma_f16(acc[q * 2], ah, bb);
                mma_f16(acc[q * 2 + 1], ah, bb + 2);
            }
        }

        // epilogue: +pos/bias -> register LN -> transposed fp16 store
        {
            const int r0 = lane >> 2, cq = (lane & 3) * 2;
            const int rowA = mt * 16 + r0, rowB = rowA + 8;
            const int head = nc * 2 + ch;
            float vA[8], vB[8];
            if (op == 0) {
#pragma unroll
                for (int f = 0; f < 4; f++) {
                    int co = nc * 64 + ch * 32 + f * 8 + cq;
                    float2 rk = *(const float2*)&g_RK[rb * NC + co];
                    float2 bk2 = *(const float2*)&bk[co];
                    float2 pa = *(const float2*)&g_PK[rowA * NC + co];
                    float2 pb = *(const float2*)&g_PK[rowB * NC + co];
                    vA[f * 2] = acc[f][0] + rk.x + pa.x + bk2.x;
                    vA[f * 2 + 1] = acc[f][1] + rk.y + pa.y + bk2.y;
                    vB[f * 2] = acc[f][2] + rk.x + pb.x + bk2.x;
                    vB[f * 2 + 1] = acc[f][3] + rk.y + pb.y + bk2.y;
                }
            } else {
#pragma unroll
                for (int f = 0; f < 4; f++) {
                    int co = nc * 64 + ch * 32 + f * 8 + cq;
                    float2 bv2 = *(const float2*)&bv[co];
                    vA[f * 2] = acc[f][0] + bv2.x;
                    vA[f * 2 + 1] = acc[f][1] + bv2.y;
                    vB[f * 2] = acc[f][2] + bv2.x;
                    vB[f * 2 + 1] = acc[f][3] + bv2.y;
                }
            }
            float sA = 0.f, s2A = 0.f, sB = 0.f, s2B = 0.f;
#pragma unroll
            for (int j = 0; j < 8; j++) {
                sA += vA[j]; s2A += vA[j] * vA[j];
                sB += vB[j]; s2B += vB[j] * vB[j];
            }
#pragma unroll
            for (int off = 1; off < 4; off <<= 1) {
                sA += __shfl_xor_sync(0xffffffffu, sA, off);
                s2A += __shfl_xor_sync(0xffffffffu, s2A, off);
                sB += __shfl_xor_sync(0xffffffffu, sB, off);
                s2B += __shfl_xor_sync(0xffffffffu, s2B, off);
            }
            float muA = sA * (1.f / 32.f);
            float rsA = rsqrtf(s2A * (1.f / 32.f) - muA * muA + 1e-5f);
            float muB = sB * (1.f / 32.f);
            float rsB = rsqrtf(s2B * (1.f / 32.f) - muB * muB + 1e-5f);
            const float* gg = op ? gV : gK;
            const float* be = op ? bVp : bKp;
            uint32_t base = sb + (op ? VT_OFF : KT_OFF);
#pragma unroll
            for (int f = 0; f < 4; f++)
#pragma unroll
                for (int j = 0; j < 2; j++) {
                    int d = f * 8 + cq + j;
                    float g = gg[head * 32 + d], bb2 = be[head * 32 + d];
                    uint32_t rowoff = (uint32_t)(ch * 32 + d) * 272;
                    __half ha = __float2half_rn((vA[f * 2 + j] - muA) * rsA * g + bb2);
                    __half hb = __float2half_rn((vB[f * 2 + j] - muB) * rsB * g + bb2);
                    asm volatile("st.shared.u16 [%0], %1;" :: "r"(base + rowoff + rowA * 2), "h"(*(unsigned short*)&ha));
                    asm volatile("st.shared.u16 [%0], %1;" :: "r"(base + rowoff + rowB * 2), "h"(*(unsigned short*)&hb));
                }
        }

        if (op == 1) {
            __syncthreads();
            if (w < 8) {   // fp16 score mma: S_h[d][e] = sum_tok K[tok][d] V[tok][e]
                const int hl = w >> 2, dt = (w >> 1) & 1, et = w & 1;
                const uint32_t aB = sb + KT_OFF + (hl * 32 + dt * 16 + (lane & 15)) * 272
                                  + ((lane & 16) ? 16 : 0);
                const uint32_t bB = sb + VT_OFF + (hl * 32 + et * 16 + blrow) * 272 + blcol2;
                float sc[2][4];
#pragma unroll
                for (int q = 0; q < 2; q++)
#pragma unroll
                    for (int j = 0; j < 4; j++) sc[q][j] = 0.f;
#pragma unroll
                for (int k = 0; k < 8; k++) {
                    uint32_t a[4], bb[4];
                    ldm_x4(a, aB + k * 32);
                    ldm_x4(bb, bB + k * 32);
                    mma_f16(sc[0], a, bb);
                    mma_f16(sc[1], a, bb + 2);
                }
                float* dst = g_spart + ((size_t)(b * 128 + rb)) * 8192 + (nc * 2 + hl) * 1024;
                int d0 = dt * 16 + (lane >> 2);
#pragma unroll
                for (int q = 0; q < 2; q++) {
                    int e0 = et * 16 + q * 8 + (lane & 3) * 2;
                    dst[d0 * 32 + e0] = sc[q][0];
                    dst[d0 * 32 + e0 + 1] = sc[q][1];
                    dst[(d0 + 8) * 32 + e0] = sc[q][2];
                    dst[(d0 + 8) * 32 + e0 + 1] = sc[q][3];
                }
            }
        }
    }
}

// ---------------- k2 chain ----------------
__global__ void k2_reduce() {
    int b = blockIdx.x >> 5, seg = blockIdx.x & 31;
    int base = seg * 256 + threadIdx.x;
    float s = 0.f;
#pragma unroll 8
    for (int rb = 0; rb < 128; rb++) s += g_spart[((size_t)(b * 128 + rb)) * 8192 + base];
    g_S[b * 8192 + base] = s * (1.0f / 16384.0f);
}

__global__ void k2b_buildM(const float* __restrict__ Wq, const float* __restrict__ bq) {
    __shared__ float Wqs[256 * 33];
    int chunk = blockIdx.x, b = blockIdx.y;
    int co = threadIdx.x, h = co >> 5, e = co & 31;
    for (int idx = threadIdx.x; idx < 8192; idx += 256) {
        int row = idx >> 5, cil = idx & 31;
        Wqs[row * 33 + cil] = Wq[row * NC + chunk * 32 + cil];
    }
    float Scol[32];
#pragma unroll
    for (int d = 0; d < 32; d++) Scol[d] = g_S[b * 8192 + h * 1024 + d * 32 + e];
    __syncthreads();
    for (int cil = 0; cil < 32; cil++) {
        float m = 0.f;
#pragma unroll
        for (int d = 0; d < 32; d++) m += Wqs[(h * 32 + d) * 33 + cil] * Scol[d];
        g_M[(size_t)b * 65536 + (size_t)co * NC + chunk * 32 + cil] = m;
    }
    if (chunk == 0) {
        float bb = 0.f;
#pragma unroll
        for (int d = 0; d < 32; d++) bb += bq[h * 32 + d] * Scol[d];
        g_biasq[b * NC + co] = bb;
    }
}

__global__ void k2m_conv() {
    int b = blockIdx.y;
    int base = blockIdx.x * 2048 + threadIdx.x;
#pragma unroll
    for (int j = 0; j < 8; j++) {
        int idx = base + j * 256;
        int row = idx >> 8, ci = idx & 255;
        g_Bm[b][row][ci] = __float2half_rn(g_M[(size_t)b * 65536 + idx]);
    }
}

__global__ void k2c_rqpq() {
    __shared__ float Ts[128];
    int p = blockIdx.x, b = blockIdx.y;
    int co = threadIdx.x;
    if (co < 128) Ts[co] = g_T[p * 128 + co];
    __syncthreads();
    const float4* Mr = (const float4*)(g_M + (size_t)b * 65536 + (size_t)co * NC);
    float accR = 0.f, accP = 0.f;
#pragma unroll 8
    for (int c4 = 0; c4 < 32; c4++) {
        float4 m0 = Mr[c4], m1 = Mr[32 + c4];
        float4 t4 = *(const float4*)&Ts[c4 * 4];
        accR += t4.x * m0.x + t4.y * m0.y + t4.z * m0.z + t4.w * m0.w;
        accP += t4.x * m1.x + t4.y * m1.y + t4.z * m1.z + t4.w * m1.w;
    }
    g_RQ[(b * 128 + p) * NC + co] = accR;
    g_PQ[(b * 128 + p) * NC + co] = accP;
}

// ---------------- T3: fp16 out GEMM + x2 + LN + transposed store ----------------
__global__ void __launch_bounds__(512, 1) t3_kernel(
    const float* __restrict__ x,
    const float* __restrict__ g_ln, const float* __restrict__ b_ln,
    float* __restrict__ out)
{
    extern __shared__ char smem[];
    const int tid = threadIdx.x, w = tid >> 5, lane = tid & 31;
    const int rb = blockIdx.x, b = blockIdx.y;
    const int n0 = rb * 128;
    uint32_t sb = s2u(smem);

    const int mt = w >> 1, ch = w & 1;
    const uint32_t aH0 = sb + (mt * 16 + (lane & 15)) * 528 + ((lane & 16) ? 16 : 0);
    const int blrow = (lane & 7) + ((lane & 16) ? 8 : 0);
    const int blcol2 = (lane & 8) ? 16 : 0;

    for (int i = tid; i < 2112; i += 512)
        cpa16(sb + B_OFF + i * 16, ((const uint4*)&g_Bm[b][0][0]) + i);
    CP_COMMIT();
    load_x_tile(smem, x + ((size_t)b * NC) * NTOK + n0, tid);

    float acc[4][4][4];
#pragma unroll 1
    for (int s = 0; s < 4; s++) {
        if (s < 3) {
            uint32_t dst = sb + B_OFF + ((s + 1) & 1) * 33792;
            for (int i = tid; i < 2112; i += 512)
                cpa16(dst + i * 16, ((const uint4*)&g_Bm[b][(s + 1) * 64][0]) + i);
            CP_COMMIT(); CP_WAIT1();
        } else CP_WAIT0();
        __syncthreads();

#pragma unroll
        for (int f = 0; f < 4; f++)
#pragma unroll
            for (int j = 0; j < 4; j++) acc[s][f][j] = 0.f;

        const uint32_t bbase = sb + B_OFF + (s & 1) * 33792 + (ch * 32 + blrow) * 528 + blcol2;
#pragma unroll 4
        for (int k = 0; k < 16; k++) {
            uint32_t ah[4];
            ldm_x4(ah, aH0 + k * 32);
#pragma unroll
            for (int q = 0; q < 2; q++) {
                uint32_t bb[4];
                ldm_x4(bb, bbase + q * 16 * 528 + k * 32);
                mma_f16(acc[s][q * 2], ah, bb);
                mma_f16(acc[s][q * 2 + 1], ah, bb + 2);
            }
        }
        __syncthreads();
    }

    float* stg = (float*)smem;          // [128][264]
    float* mus = (float*)(smem + T3_MU);
    float* rss = (float*)(smem + T3_RS);
    {
        int r0 = lane >> 2, cq = (lane & 3) * 2;
        int row = mt * 16 + r0;
#pragma unroll
        for (int s = 0; s < 4; s++)
#pragma unroll
            for (int f = 0; f < 4; f++) {
                int co = s * 64 + ch * 32 + f * 8 + cq;
                float2 rq = *(const float2*)&g_RQ[(b * 128 + rb) * NC + co];
                float2 qb = *(const float2*)&g_biasq[b * NC + co];
                float2 pa = *(const float2*)&g_PQ[(b * 128 + row) * NC + co];
                float2 pb = *(const float2*)&g_PQ[(b * 128 + row + 8) * NC + co];
                stg[row * 264 + co] = 2.f * (acc[s][f][0] + rq.x + qb.x + pa.x);
                stg[row * 264 + co + 1] = 2.f * (acc[s][f][1] + rq.y + qb.y + pa.y);
                stg[(row + 8) * 264 + co] = 2.f * (acc[s][f][2] + rq.x + qb.x + pb.x);
                stg[(row + 8) * 264 + co + 1] = 2.f * (acc[s][f][3] + rq.y + qb.y + pb.y);
            }
    }
    __syncthreads();

    {
        int token = tid >> 2, q = tid & 3;
        float s = 0.f, s2 = 0.f;
#pragma unroll
        for (int jj = 0; jj < 16; jj++) {
            float4 v = *(const float4*)&stg[token * 264 + q * 64 + jj * 4];
            s += v.x + v.y + v.z + v.w;
            s2 += v.x * v.x + v.y * v.y + v.z * v.z + v.w * v.w;
        }
#pragma unroll
        for (int off = 1; off < 4; off <<= 1) {
            s += __shfl_xor_sync(0xffffffffu, s, off);
            s2 += __shfl_xor_sync(0xffffffffu, s2, off);
        }
        if (q == 0) {
            float mu = s * (1.f / 256.f);
            mus[token] = mu;
            rss[token] = rsqrtf(s2 * (1.f / 256.f) - mu * mu + 1e-5f);
        }
    }
    __syncthreads();

    {
        int t = tid & 127, cg = tid >> 7;
        float mu = mus[t], rs = rss[t];
        size_t obase = ((size_t)b * NC) * NTOK + n0 + t;
#pragma unroll 4
        for (int p = 0; p < 64; p++) {
            int co = cg * 64 + p;
            out[obase + (size_t)co * NTOK] = (stg[t * 264 + co] - mu) * rs * g_ln[co] + b_ln[co];
        }
    }
}

// ---------------- launch ----------------
extern "C" void kernel_launch(void* const* d_in, const int* in_sizes, int n_in,
                              void* d_out, int out_size) {
    const float* x    = (const float*)d_in[0];
    const float* Wq   = (const float*)d_in[1];
    const float* bq   = (const float*)d_in[2];
    const float* Wk   = (const float*)d_in[3];
    const float* bk   = (const float*)d_in[4];
    const float* Wv   = (const float*)d_in[5];
    const float* bv   = (const float*)d_in[6];
    const float* gK   = (const float*)d_in[7];
    const float* bK   = (const float*)d_in[8];
    const float* gV   = (const float*)d_in[9];
    const float* bV   = (const float*)d_in[10];
    const float* g_ln = (const float*)d_in[11];
    const float* b_ln = (const float*)d_in[12];
    float* out = (float*)d_out;

    cudaFuncSetAttribute(t1_kernel, cudaFuncAttributeMaxDynamicSharedMemorySize, T1_TOT);
    cudaFuncSetAttribute(t3_kernel, cudaFuncAttributeMaxDynamicSharedMemorySize, T3_TOT);

    prep0_kernel<<<256, 256>>>(Wk, Wv);
    prep1_kernel<<<16, 256>>>();
    t1_kernel<<<dim3(128, 8), 512, T1_TOT>>>(x, bk, bv, gK, bK, gV, bV);
    k2_reduce<<<256, 256>>>();
    k2b_buildM<<<dim3(8, 8), 256>>>(Wq, bq);
    k2m_conv<<<dim3(32, 8), 256>>>();
    k2c_rqpq<<<dim3(128, 8), 256>>>();
    t3_kernel<<<dim3(128, 8), 512, T3_TOT>>>(x, g_ln, b_ln, out);
}